// round 4
// baseline (speedup 1.0000x reference)
#include <cuda_runtime.h>
#include <math.h>

// ---------------------------------------------------------------------------
// Problem constants
// ---------------------------------------------------------------------------
namespace {
constexpr int B_ = 8, C_ = 256, H_ = 132, W_ = 132, NH_ = 8, D_ = 16;
constexpr int HW_ = H_ * W_;          // 17424
constexpr int M_  = B_ * HW_;         // 139392  (== 1089 * 128 exactly)
constexpr int CH_ = 128;              // C/2
constexpr int C2_ = 512;              // 2C
constexpr int C3_ = 384;              // 3C/2
constexpr int SPLIT_  = 8;
constexpr int KPS_    = HW_ / SPLIT_; // 2178 keys per split
constexpr int CHUNK_  = 66;           // keys per smem chunk (2178 = 33*66)
constexpr int NCHUNK_ = KPS_ / CHUNK_;

constexpr size_t SZ_BIG  = (size_t)M_ * C_;
constexpr size_t SZ_CAT  = (size_t)M_ * C3_;
constexpr size_t SZ_HALF = (size_t)M_ * CH_;

constexpr size_t OFF_XC    = 0;
constexpr size_t OFF_XEC   = OFF_XC  + SZ_BIG;
constexpr size_t OFF_XG    = OFF_XEC + SZ_BIG;
constexpr size_t OFF_KV    = OFF_XG  + SZ_BIG;
constexpr size_t OFF_CAT   = OFF_KV  + SZ_BIG;
constexpr size_t OFF_T1    = OFF_CAT + SZ_CAT;
constexpr size_t OFF_T2    = OFF_T1  + SZ_HALF;
constexpr size_t OFF_T3    = OFF_T2  + SZ_HALF;
constexpr size_t OFF_POOL  = OFF_T3  + SZ_HALF;
constexpr size_t OFF_MM    = OFF_POOL  + (size_t)B_ * 36 * C2_;
constexpr size_t OFF_SMALL = OFF_MM    + (size_t)B_ * 36 * CH_;
constexpr size_t OFF_PMAX  = OFF_SMALL + (size_t)B_ * CH_ * 36;
constexpr size_t OFF_PSUM  = OFF_PMAX  + (size_t)B_ * NH_ * 36 * SPLIT_;
constexpr size_t OFF_PACC  = OFF_PSUM  + (size_t)B_ * NH_ * 36 * SPLIT_;
constexpr size_t SCRATCH_TOTAL = OFF_PACC + (size_t)B_ * NH_ * 36 * SPLIT_ * D_;
}  // namespace

// ~1.0 GB device-global scratch (sanctioned workaround for no-alloc rule).
__device__ float g_scratch[SCRATCH_TOTAL];

// ---------------------------------------------------------------------------
// 1) LayerNorm over channels with NCHW -> (B*HW, C) transpose
// ---------------------------------------------------------------------------
__global__ void ln_kernel(const float* __restrict__ x, const float* __restrict__ gw,
                          const float* __restrict__ gb, float* __restrict__ out)
{
    __shared__ float s[256][33];
    __shared__ float sw[256], sb[256];
    int tid  = threadIdx.x;
    int b    = blockIdx.y;
    int pos0 = blockIdx.x * 32;
    sw[tid] = gw[tid];
    sb[tid] = gb[tid];
    int px = tid & 31, cg = tid >> 5;
    int p  = pos0 + px;
    const float* xb = x + (size_t)b * C_ * HW_;
    bool valid = (p < HW_);
    for (int c = cg; c < 256; c += 8)
        s[c][px] = valid ? xb[(size_t)c * HW_ + p] : 0.f;
    __syncthreads();
    int warp = tid >> 5, lane = tid & 31;
    #pragma unroll
    for (int pi = 0; pi < 4; ++pi) {
        int pp = warp * 4 + pi;
        int gp = pos0 + pp;
        if (gp >= HW_) continue;   // warp-uniform
        float sum = 0.f, sum2 = 0.f;
        #pragma unroll
        for (int jj = 0; jj < 8; ++jj) {
            float v = s[lane + jj * 32][pp];
            sum += v; sum2 += v * v;
        }
        #pragma unroll
        for (int o = 16; o > 0; o >>= 1) {
            sum  += __shfl_xor_sync(0xffffffffu, sum,  o);
            sum2 += __shfl_xor_sync(0xffffffffu, sum2, o);
        }
        float mean = sum * (1.f / 256.f);
        float var  = fmaxf(sum2 * (1.f / 256.f) - mean * mean, 0.f);
        float rstd = rsqrtf(var + 1e-6f);
        float* orow = out + (size_t)(b * HW_ + gp) * 256;
        #pragma unroll
        for (int jj = 0; jj < 8; ++jj) {
            int c = lane + jj * 32;
            orow[c] = (s[c][pp] - mean) * rstd * sw[c] + sb[c];
        }
    }
}

// ---------------------------------------------------------------------------
// 2) SGEMM: C = epilogue(A[M,K] @ W[K,N] + bias)
//    BM=128 BN=64 BK=16, 256 threads, 8x4 microtile per thread
//    EPI 0: plain row-major write (ldc, coloff)
//    EPI 1: exact GELU
//    EPI 2: multiply by aux[row*128+col] then write (ldc, coloff)
//    EPI 3: NCHW transposed write into (B,256,HW) tensor
// ---------------------------------------------------------------------------
template <int EPI>
__global__ __launch_bounds__(256)
void sgemm_k(const float* __restrict__ A, const float* __restrict__ Wm,
             const float* __restrict__ bias, const float* __restrict__ aux,
             float* __restrict__ Cout, int M, int N, int K, int ldc, int coloff)
{
    __shared__ float As[16][132];
    __shared__ float Ws[16][64];
    int tid = threadIdx.x;
    int bm = blockIdx.y * 128;
    int bn = blockIdx.x * 64;
    int tx = tid & 15, ty = tid >> 4;
    float acc[8][4];
    #pragma unroll
    for (int i = 0; i < 8; ++i)
        #pragma unroll
        for (int j = 0; j < 4; ++j) acc[i][j] = 0.f;
    int aRow = tid >> 2;
    int aK   = (tid & 3) << 2;
    int wRow = tid >> 4;
    int wCol = (tid & 15) << 2;
    for (int k0 = 0; k0 < K; k0 += 16) {
        #pragma unroll
        for (int r = 0; r < 2; ++r) {
            int row = bm + aRow + r * 64;
            float4 v = make_float4(0.f, 0.f, 0.f, 0.f);
            if (row < M)
                v = *reinterpret_cast<const float4*>(A + (size_t)row * K + k0 + aK);
            As[aK + 0][aRow + r * 64] = v.x;
            As[aK + 1][aRow + r * 64] = v.y;
            As[aK + 2][aRow + r * 64] = v.z;
            As[aK + 3][aRow + r * 64] = v.w;
        }
        *reinterpret_cast<float4*>(&Ws[wRow][wCol]) =
            *reinterpret_cast<const float4*>(Wm + (size_t)(k0 + wRow) * N + bn + wCol);
        __syncthreads();
        #pragma unroll
        for (int kk = 0; kk < 16; ++kk) {
            float a[8], bf[4];
            #pragma unroll
            for (int i = 0; i < 8; ++i) a[i] = As[kk][ty * 8 + i];
            #pragma unroll
            for (int j = 0; j < 4; ++j) bf[j] = Ws[kk][tx * 4 + j];
            #pragma unroll
            for (int i = 0; i < 8; ++i)
                #pragma unroll
                for (int j = 0; j < 4; ++j)
                    acc[i][j] = fmaf(a[i], bf[j], acc[i][j]);
        }
        __syncthreads();
    }
    #pragma unroll
    for (int i = 0; i < 8; ++i) {
        int row = bm + ty * 8 + i;
        if (row >= M) continue;
        int bb = row / HW_;
        int pp = row - bb * HW_;
        #pragma unroll
        for (int j = 0; j < 4; ++j) {
            int col = bn + tx * 4 + j;
            float v = acc[i][j] + bias[col];
            if (EPI == 1) v = 0.5f * v * (1.f + erff(v * 0.70710678f));
            if (EPI == 2) v *= aux[(size_t)row * 128 + col];
            if (EPI == 3)
                Cout[(size_t)(bb * 256 + col) * HW_ + pp] = v;
            else
                Cout[(size_t)row * ldc + coloff + col] = v;
        }
    }
}

// ---------------------------------------------------------------------------
// 3) AdaptiveAvgPool2d((6,6)) on cat(xc, xec): blocked 22x22 mean
// ---------------------------------------------------------------------------
__global__ void pool_kernel(const float* __restrict__ xc, const float* __restrict__ xec,
                            float* __restrict__ pooled)
{
    int b = blockIdx.y, q = blockIdx.x;
    int qy = q / 6, qx = q - qy * 6;
    int c  = threadIdx.x;                    // 0..511
    const float* src = (c < 256) ? xc : xec;
    int cc = c & 255;
    size_t base = (size_t)b * HW_;
    float acc = 0.f;
    for (int i = 0; i < 22; ++i) {
        size_t rowp = base + (size_t)((qy * 22 + i) * 132 + qx * 22);
        for (int j = 0; j < 22; ++j)
            acc += src[(rowp + j) * 256 + cc];
    }
    pooled[(size_t)(b * 36 + q) * 512 + c] = acc * (1.f / 484.f);
}

// ---------------------------------------------------------------------------
// 4) Attention (36 queries x 17424 keys per (b,head)), online softmax,
//    split over key range; partials merged by attn_combine.
//    kv layout: row (b*HW+pos), k at channel head*16+d, v at 128+head*16+d.
// ---------------------------------------------------------------------------
__global__ __launch_bounds__(288)
void attn_partial(const float* __restrict__ kv, const float* __restrict__ mq_all,
                  float* __restrict__ pmax, float* __restrict__ psum,
                  float* __restrict__ pacc)
{
    __shared__ float ks[CHUNK_][17];
    __shared__ float vs[CHUNK_][17];
    int b = blockIdx.z, head = blockIdx.y, sp = blockIdx.x;
    int tid = threadIdx.x;
    int q = tid >> 3, j = tid & 7;   // 36 query groups x 8 lanes (aligned in warp)
    float mq[16];
    #pragma unroll
    for (int d = 0; d < 16; ++d)
        mq[d] = mq_all[(size_t)(b * 36 + q) * 128 + head * 16 + d] * 0.25f; // d^-0.5
    float mx = -INFINITY, sm = 0.f;
    float acc[16];
    #pragma unroll
    for (int d = 0; d < 16; ++d) acc[d] = 0.f;
    int kb = sp * KPS_;
    for (int c0 = 0; c0 < NCHUNK_; ++c0) {
        int pos0 = kb + c0 * CHUNK_;
        for (int idx = tid; idx < CHUNK_ * 16; idx += 288) {
            int key = idx >> 4, d = idx & 15;
            size_t base = ((size_t)b * HW_ + pos0 + key) * 256 + head * 16 + d;
            ks[key][d] = kv[base];
            vs[key][d] = kv[base + 128];
        }
        __syncthreads();
        for (int key = j; key < CHUNK_; key += 8) {
            float s = 0.f;
            #pragma unroll
            for (int d = 0; d < 16; ++d) s = fmaf(mq[d], ks[key][d], s);
            if (s <= mx) {
                float p = __expf(s - mx);
                sm += p;
                #pragma unroll
                for (int d = 0; d < 16; ++d) acc[d] = fmaf(p, vs[key][d], acc[d]);
            } else {
                float cr = __expf(mx - s);
                sm = fmaf(sm, cr, 1.f);
                #pragma unroll
                for (int d = 0; d < 16; ++d) acc[d] = fmaf(acc[d], cr, vs[key][d]);
                mx = s;
            }
        }
        __syncthreads();
    }
    // merge the 8 lanes of this query group (xor stays inside the group)
    #pragma unroll
    for (int o = 4; o > 0; o >>= 1) {
        float omx = __shfl_xor_sync(0xffffffffu, mx, o);
        float osm = __shfl_xor_sync(0xffffffffu, sm, o);
        float nm = fmaxf(mx, omx);
        float c1 = __expf(mx - nm), c2 = __expf(omx - nm);
        sm = sm * c1 + osm * c2;
        #pragma unroll
        for (int d = 0; d < 16; ++d) {
            float oa = __shfl_xor_sync(0xffffffffu, acc[d], o);
            acc[d] = acc[d] * c1 + oa * c2;
        }
        mx = nm;
    }
    int pi = (b * NH_ + head) * 36 + q;
    if (j == 0) {
        pmax[pi * SPLIT_ + sp] = mx;
        psum[pi * SPLIT_ + sp] = sm;
        #pragma unroll
        for (int d = 0; d < 16; ++d)
            pacc[((size_t)pi * SPLIT_ + sp) * 16 + d] = acc[d];
    }
}

__global__ void attn_combine(const float* __restrict__ pmax, const float* __restrict__ psum,
                             const float* __restrict__ pacc, float* __restrict__ sm_out)
{
    int idx = blockIdx.x * blockDim.x + threadIdx.x;
    if (idx >= B_ * NH_ * 36 * 16) return;
    int d  = idx & 15;
    int q  = (idx >> 4) % 36;
    int bh = idx / (16 * 36);
    int pi = bh * 36 + q;
    float gm = -INFINITY;
    #pragma unroll
    for (int s = 0; s < SPLIT_; ++s) gm = fmaxf(gm, pmax[pi * SPLIT_ + s]);
    float ts = 0.f, tv = 0.f;
    #pragma unroll
    for (int s = 0; s < SPLIT_; ++s) {
        float c = __expf(pmax[pi * SPLIT_ + s] - gm);
        ts += c * psum[pi * SPLIT_ + s];
        tv += c * pacc[((size_t)pi * SPLIT_ + s) * 16 + d];
    }
    int b = bh >> 3, head = bh & 7;
    // layout (B,128,36): channel = head*16+d, spatial q
    sm_out[(size_t)(b * 128 + head * 16 + d) * 36 + q] = tv / ts;
}

// ---------------------------------------------------------------------------
// 5) Bilinear upsample (B,128,6,6) -> (B,132,132,128), written into cat[:,0:128]
//    align_corners=False half-pixel centers, edge clamp (== jax renormalize)
// ---------------------------------------------------------------------------
__global__ void upsample_kernel(const float* __restrict__ sm_in, float* __restrict__ cat)
{
    __shared__ float s[36][128];
    int b = blockIdx.y;
    for (int idx = threadIdx.x; idx < 36 * 128; idx += 128) {
        int q = idx >> 7, ch = idx & 127;
        s[q][ch] = sm_in[(size_t)(b * 128 + ch) * 36 + q];
    }
    __syncthreads();
    int ch = threadIdx.x;
    int p0 = blockIdx.x * 64;
    for (int k = 0; k < 64; ++k) {
        int p = p0 + k;
        if (p >= HW_) return;   // uniform across block
        int h = p / 132, w = p - h * 132;
        float sy = (h + 0.5f) * (1.f / 22.f) - 0.5f;
        float sx = (w + 0.5f) * (1.f / 22.f) - 0.5f;
        float fy0 = floorf(sy), fx0 = floorf(sx);
        float fy = sy - fy0, fx = sx - fx0;
        int y0 = (int)fy0, x0 = (int)fx0;
        int y1 = min(y0 + 1, 5), x1 = min(x0 + 1, 5);
        y0 = max(y0, 0); x0 = max(x0, 0);
        float v00 = s[y0 * 6 + x0][ch], v01 = s[y0 * 6 + x1][ch];
        float v10 = s[y1 * 6 + x0][ch], v11 = s[y1 * 6 + x1][ch];
        float v = (1.f - fy) * ((1.f - fx) * v00 + fx * v01)
                + fy * ((1.f - fx) * v10 + fx * v11);
        cat[((size_t)b * HW_ + p) * 384 + ch] = v;
    }
}

// ---------------------------------------------------------------------------
// 6) Depthwise 7x7 conv, NHWC (channels inner), zero pad 3, + bias
//    tile: 4(h) x 16(w) positions x 32 channels per block
// ---------------------------------------------------------------------------
__global__ __launch_bounds__(256)
void dwconv_kernel(const float* __restrict__ in, const float* __restrict__ wgt,
                   const float* __restrict__ cbias, float* __restrict__ out)
{
    __shared__ float s[10][22][32];
    __shared__ float wsm[32][49];
    int wt = blockIdx.x, ht = blockIdx.y;
    int bz = blockIdx.z;
    int b = bz >> 2, cg = bz & 3;
    int h0 = ht * 4, w0 = wt * 16;
    int tid = threadIdx.x;
    for (int idx = tid; idx < 32 * 49; idx += 256) {
        int ch = idx / 49, t = idx - ch * 49;
        wsm[ch][t] = wgt[(cg * 32 + ch) * 49 + t];
    }
    const float* inb = in + (size_t)b * HW_ * 128;
    for (int idx = tid; idx < 10 * 22 * 32; idx += 256) {
        int ch = idx & 31;
        int r  = idx >> 5;
        int lw = r % 22, lh = r / 22;
        int gh = h0 - 3 + lh, gw = w0 - 3 + lw;
        float v = 0.f;
        if (gh >= 0 && gh < 132 && gw >= 0 && gw < 132)
            v = inb[(size_t)(gh * 132 + gw) * 128 + cg * 32 + ch];
        s[lh][lw][ch] = v;
    }
    __syncthreads();
    int ch = tid & 31;
    int pg = tid >> 5;   // 0..7
    float acc[8];
    #pragma unroll
    for (int i = 0; i < 8; ++i) acc[i] = 0.f;
    #pragma unroll
    for (int dy = 0; dy < 7; ++dy)
        #pragma unroll
        for (int dx = 0; dx < 7; ++dx) {
            float wv = wsm[ch][dy * 7 + dx];
            #pragma unroll
            for (int pi = 0; pi < 8; ++pi) {
                int posid = pg + pi * 8;
                int lh = posid >> 4, lw = posid & 15;
                acc[pi] = fmaf(wv, s[lh + dy][lw + dx][ch], acc[pi]);
            }
        }
    float bv = cbias[cg * 32 + ch];
    #pragma unroll
    for (int pi = 0; pi < 8; ++pi) {
        int posid = pg + pi * 8;
        int lh = posid >> 4, lw = posid & 15;
        int gw = w0 + lw;
        if (gw < 132)
            out[((size_t)b * HW_ + (h0 + lh) * 132 + gw) * 128 + cg * 32 + ch]
                = acc[pi] + bv;
    }
}

// ---------------------------------------------------------------------------
// Launcher
// ---------------------------------------------------------------------------
extern "C" void kernel_launch(void* const* d_in, const int* in_sizes, int n_in,
                              void* d_out, int out_size)
{
    (void)in_sizes; (void)n_in; (void)out_size;
    const float* x       = (const float*)d_in[0];
    const float* x_e     = (const float*)d_in[1];
    const float* norm_w  = (const float*)d_in[2];
    const float* norm_b  = (const float*)d_in[3];
    const float* norme_w = (const float*)d_in[4];
    const float* norme_b = (const float*)d_in[5];
    const float* l_w     = (const float*)d_in[6];
    const float* l_b     = (const float*)d_in[7];
    const float* kv_w    = (const float*)d_in[8];
    const float* kv_b    = (const float*)d_in[9];
    const float* xe_w    = (const float*)d_in[10];
    const float* xe_b    = (const float*)d_in[11];
    const float* q_w     = (const float*)d_in[12];
    const float* q_b     = (const float*)d_in[13];
    const float* ef_w    = (const float*)d_in[14];
    const float* ef_b    = (const float*)d_in[15];
    const float* ec_w    = (const float*)d_in[16];
    const float* ec_b    = (const float*)d_in[17];
    const float* eb_w    = (const float*)d_in[18];
    const float* eb_b    = (const float*)d_in[19];
    const float* proj_w  = (const float*)d_in[20];
    const float* proj_b  = (const float*)d_in[21];
    const float* proje_w = (const float*)d_in[22];
    const float* proje_b = (const float*)d_in[23];

    float* base = nullptr;
    cudaGetSymbolAddress((void**)&base, g_scratch);
    float* xc    = base + OFF_XC;
    float* xec   = base + OFF_XEC;
    float* xg    = base + OFF_XG;
    float* kvb   = base + OFF_KV;
    float* cat   = base + OFF_CAT;
    float* t1    = base + OFF_T1;
    float* t2    = base + OFF_T2;
    float* t3    = base + OFF_T3;
    float* pool  = base + OFF_POOL;
    float* mbuf  = base + OFF_MM;
    float* smalb = base + OFF_SMALL;
    float* pmax  = base + OFF_PMAX;
    float* psum  = base + OFF_PSUM;
    float* pacc  = base + OFF_PACC;

    float* outp = (float*)d_out;
    float* oute = outp + SZ_BIG;

    dim3 lnG((HW_ + 31) / 32, B_);
    ln_kernel<<<lnG, 256>>>(x,   norm_w,  norm_b,  xc);
    ln_kernel<<<lnG, 256>>>(x_e, norme_w, norme_b, xec);

    // GFA: xg = gelu(xc @ l_w + l_b); kv = xg @ kv_w + kv_b
    sgemm_k<1><<<dim3(4, 1089), 256>>>(xc, l_w,  l_b,  nullptr, xg,  M_, 256, 256, 256, 0);
    sgemm_k<0><<<dim3(4, 1089), 256>>>(xg, kv_w, kv_b, nullptr, kvb, M_, 256, 256, 256, 0);

    pool_kernel<<<dim3(36, B_), 512>>>(xc, xec, pool);
    sgemm_k<0><<<dim3(2, 3), 256>>>(pool, xe_w, xe_b, nullptr, mbuf, B_ * 36, 128, 512, 128, 0);

    attn_partial<<<dim3(SPLIT_, NH_, B_), 288>>>(kvb, mbuf, pmax, psum, pacc);
    attn_combine<<<(B_ * NH_ * 36 * 16 + 255) / 256, 256>>>(pmax, psum, pacc, smalb);
    upsample_kernel<<<dim3((HW_ + 63) / 64, B_), 128>>>(smalb, cat);  // cat[:,0:128]

    // LFA 1: q from xc, e from xec -> cat[:,128:256]
    sgemm_k<0><<<dim3(2, 1089), 256>>>(xc,  q_w,  q_b,  nullptr, t1, M_, 128, 256, 128, 0);
    sgemm_k<0><<<dim3(2, 1089), 256>>>(xec, ef_w, ef_b, nullptr, t2, M_, 128, 256, 128, 0);
    dwconv_kernel<<<dim3(9, 33, B_ * 4), 256>>>(t2, ec_w, ec_b, t3);
    sgemm_k<2><<<dim3(2, 1089), 256>>>(t3, eb_w, eb_b, t1, cat, M_, 128, 128, 384, 128);

    // LFA 2: q from xec, e from xc -> cat[:,256:384]
    sgemm_k<0><<<dim3(2, 1089), 256>>>(xec, q_w,  q_b,  nullptr, t1, M_, 128, 256, 128, 0);
    sgemm_k<0><<<dim3(2, 1089), 256>>>(xc,  ef_w, ef_b, nullptr, t2, M_, 128, 256, 128, 0);
    dwconv_kernel<<<dim3(9, 33, B_ * 4), 256>>>(t2, ec_w, ec_b, t3);
    sgemm_k<2><<<dim3(2, 1089), 256>>>(t3, eb_w, eb_b, t1, cat, M_, 128, 128, 384, 256);

    // Projections, NCHW outputs: out then out_e
    sgemm_k<3><<<dim3(4, 1089), 256>>>(cat, proj_w,  proj_b,  nullptr, outp, M_, 256, 384, 0, 0);
    sgemm_k<3><<<dim3(4, 1089), 256>>>(cat, proje_w, proje_b, nullptr, oute, M_, 256, 384, 0, 0);
}

// round 5
// speedup vs baseline: 1.9262x; 1.9262x over previous
#include <cuda_runtime.h>
#include <math.h>
#include <stdint.h>

// ---------------------------------------------------------------------------
// Problem constants
// ---------------------------------------------------------------------------
namespace {
constexpr int B_ = 8, C_ = 256, H_ = 132, W_ = 132, NH_ = 8, D_ = 16;
constexpr int HW_ = H_ * W_;          // 17424
constexpr int M_  = B_ * HW_;         // 139392  (== 1089 * 128 exactly)
constexpr int CH_ = 128;              // C/2
constexpr int C2_ = 512;              // 2C
constexpr int C3_ = 384;              // 3C/2
constexpr int SPLIT_  = 8;
constexpr int KPS_    = HW_ / SPLIT_; // 2178 keys per split
constexpr int CHUNK_  = 66;           // keys per smem chunk (2178 = 33*66)
constexpr int NCHUNK_ = KPS_ / CHUNK_;

constexpr size_t SZ_BIG  = (size_t)M_ * C_;
constexpr size_t SZ_CAT  = (size_t)M_ * C3_;
constexpr size_t SZ_HALF = (size_t)M_ * CH_;

constexpr size_t OFF_XC    = 0;
constexpr size_t OFF_XEC   = OFF_XC  + SZ_BIG;
constexpr size_t OFF_XG    = OFF_XEC + SZ_BIG;
constexpr size_t OFF_KV    = OFF_XG  + SZ_BIG;
constexpr size_t OFF_CAT   = OFF_KV  + SZ_BIG;
constexpr size_t OFF_T1    = OFF_CAT + SZ_CAT;
constexpr size_t OFF_T2    = OFF_T1  + SZ_HALF;
constexpr size_t OFF_T3    = OFF_T2  + SZ_HALF;
constexpr size_t OFF_POOL  = OFF_T3  + SZ_HALF;
constexpr size_t OFF_MM    = OFF_POOL  + (size_t)B_ * 36 * C2_;
constexpr size_t OFF_SMALL = OFF_MM    + (size_t)B_ * 36 * CH_;
constexpr size_t OFF_PMAX  = OFF_SMALL + (size_t)B_ * CH_ * 36;
constexpr size_t OFF_PSUM  = OFF_PMAX  + (size_t)B_ * NH_ * 36 * SPLIT_;
constexpr size_t OFF_PACC  = OFF_PSUM  + (size_t)B_ * NH_ * 36 * SPLIT_;
constexpr size_t SCRATCH_TOTAL = OFF_PACC + (size_t)B_ * NH_ * 36 * SPLIT_ * D_;
}  // namespace

__device__ float g_scratch[SCRATCH_TOTAL];

// ---------------------------------------------------------------------------
// helpers
// ---------------------------------------------------------------------------
__device__ __forceinline__ float to_tf32(float x) {
    float r;
    asm("cvt.rna.tf32.f32 %0, %1;" : "=f"(r) : "f"(x));
    return r;
}

// ---------------------------------------------------------------------------
// 1) LayerNorm over channels with NCHW -> (B*HW, C) transpose
// ---------------------------------------------------------------------------
__global__ void ln_kernel(const float* __restrict__ x, const float* __restrict__ gw,
                          const float* __restrict__ gb, float* __restrict__ out)
{
    __shared__ float s[256][33];
    __shared__ float sw[256], sb[256];
    int tid  = threadIdx.x;
    int b    = blockIdx.y;
    int pos0 = blockIdx.x * 32;
    sw[tid] = gw[tid];
    sb[tid] = gb[tid];
    int px = tid & 31, cg = tid >> 5;
    int p  = pos0 + px;
    const float* xb = x + (size_t)b * C_ * HW_;
    bool valid = (p < HW_);
    for (int c = cg; c < 256; c += 8)
        s[c][px] = valid ? xb[(size_t)c * HW_ + p] : 0.f;
    __syncthreads();
    int warp = tid >> 5, lane = tid & 31;
    #pragma unroll
    for (int pi = 0; pi < 4; ++pi) {
        int pp = warp * 4 + pi;
        int gp = pos0 + pp;
        if (gp >= HW_) continue;
        float sum = 0.f, sum2 = 0.f;
        #pragma unroll
        for (int jj = 0; jj < 8; ++jj) {
            float v = s[lane + jj * 32][pp];
            sum += v; sum2 += v * v;
        }
        #pragma unroll
        for (int o = 16; o > 0; o >>= 1) {
            sum  += __shfl_xor_sync(0xffffffffu, sum,  o);
            sum2 += __shfl_xor_sync(0xffffffffu, sum2, o);
        }
        float mean = sum * (1.f / 256.f);
        float var  = fmaxf(sum2 * (1.f / 256.f) - mean * mean, 0.f);
        float rstd = rsqrtf(var + 1e-6f);
        float* orow = out + (size_t)(b * HW_ + gp) * 256;
        #pragma unroll
        for (int jj = 0; jj < 8; ++jj) {
            int c = lane + jj * 32;
            orow[c] = (s[c][pp] - mean) * rstd * sw[c] + sb[c];
        }
    }
}

// ---------------------------------------------------------------------------
// 2a) TF32 tensor-core GEMM: C = epi(A[M,K] @ W[K,N] + bias)
//     BM=128 BN=128 BK=16, 256 threads (8 warps as 2M x 4N, warp tile 64x32)
//     Requires: M % 128 == 0, N % 128 == 0, K % 16 == 0.
//     EPI 0: plain write (ldc, coloff)    EPI 1: exact GELU
//     EPI 2: * aux[row*128+col]           EPI 3: NCHW transposed write
// ---------------------------------------------------------------------------
template <int EPI>
__global__ __launch_bounds__(256)
void tgemm(const float* __restrict__ A, const float* __restrict__ Wm,
           const float* __restrict__ bias, const float* __restrict__ aux,
           float* __restrict__ Cout, int M, int N, int K, int ldc, int coloff)
{
    __shared__ float As[2][16][136];
    __shared__ float Bs[2][16][136];
    int tid = threadIdx.x;
    int bm = blockIdx.y * 128;
    int bn = blockIdx.x * 128;
    int lane = tid & 31, wid = tid >> 5;
    int wm = (wid & 1) * 64;         // warp M offset
    int wn = (wid >> 1) * 32;        // warp N offset
    int g = lane >> 2, tig = lane & 3;

    float acc[4][4][4];
    #pragma unroll
    for (int mt = 0; mt < 4; ++mt)
        #pragma unroll
        for (int nt = 0; nt < 4; ++nt)
            #pragma unroll
            for (int r = 0; r < 4; ++r) acc[mt][nt][r] = 0.f;

    // global-load mapping
    int aRow = tid >> 2;             // 0..63
    int aK   = (tid & 3) << 2;       // 0,4,8,12
    int bK   = tid >> 4;             // 0..15
    int bN   = (tid & 15) << 2;      // 0..60

    const float* Ag0 = A + (size_t)(bm + aRow) * K + aK;
    const float* Ag1 = A + (size_t)(bm + aRow + 64) * K + aK;
    const float* Bg  = Wm + (size_t)bK * N + bn + bN;

    float4 pa0, pa1, pb0, pb1;
    // prologue: load k-step 0
    pa0 = *reinterpret_cast<const float4*>(Ag0);
    pa1 = *reinterpret_cast<const float4*>(Ag1);
    pb0 = *reinterpret_cast<const float4*>(Bg);
    pb1 = *reinterpret_cast<const float4*>(Bg + 64);
    {
        As[0][aK + 0][aRow] = to_tf32(pa0.x);
        As[0][aK + 1][aRow] = to_tf32(pa0.y);
        As[0][aK + 2][aRow] = to_tf32(pa0.z);
        As[0][aK + 3][aRow] = to_tf32(pa0.w);
        As[0][aK + 0][aRow + 64] = to_tf32(pa1.x);
        As[0][aK + 1][aRow + 64] = to_tf32(pa1.y);
        As[0][aK + 2][aRow + 64] = to_tf32(pa1.z);
        As[0][aK + 3][aRow + 64] = to_tf32(pa1.w);
        float4 q0 = make_float4(to_tf32(pb0.x), to_tf32(pb0.y), to_tf32(pb0.z), to_tf32(pb0.w));
        float4 q1 = make_float4(to_tf32(pb1.x), to_tf32(pb1.y), to_tf32(pb1.z), to_tf32(pb1.w));
        *reinterpret_cast<float4*>(&Bs[0][bK][bN])      = q0;
        *reinterpret_cast<float4*>(&Bs[0][bK][bN + 64]) = q1;
    }
    __syncthreads();

    int nsteps = K >> 4;
    for (int s = 0; s < nsteps; ++s) {
        int cur = s & 1;
        if (s + 1 < nsteps) {
            const float* a0 = Ag0 + (s + 1) * 16;
            const float* a1 = Ag1 + (s + 1) * 16;
            const float* bg = Bg + (size_t)(s + 1) * 16 * N;
            pa0 = *reinterpret_cast<const float4*>(a0);
            pa1 = *reinterpret_cast<const float4*>(a1);
            pb0 = *reinterpret_cast<const float4*>(bg);
            pb1 = *reinterpret_cast<const float4*>(bg + 64);
        }
        // compute on buffer `cur`
        #pragma unroll
        for (int k8 = 0; k8 < 2; ++k8) {
            int kb = k8 * 8;
            uint32_t af[4][4], bf[4][2];
            #pragma unroll
            for (int mt = 0; mt < 4; ++mt) {
                int mrow = wm + mt * 16 + g;
                af[mt][0] = __float_as_uint(As[cur][kb + tig][mrow]);
                af[mt][1] = __float_as_uint(As[cur][kb + tig][mrow + 8]);
                af[mt][2] = __float_as_uint(As[cur][kb + tig + 4][mrow]);
                af[mt][3] = __float_as_uint(As[cur][kb + tig + 4][mrow + 8]);
            }
            #pragma unroll
            for (int nt = 0; nt < 4; ++nt) {
                int ncol = wn + nt * 8 + g;
                bf[nt][0] = __float_as_uint(Bs[cur][kb + tig][ncol]);
                bf[nt][1] = __float_as_uint(Bs[cur][kb + tig + 4][ncol]);
            }
            #pragma unroll
            for (int mt = 0; mt < 4; ++mt)
                #pragma unroll
                for (int nt = 0; nt < 4; ++nt) {
                    asm volatile(
                        "mma.sync.aligned.m16n8k8.row.col.f32.tf32.tf32.f32 "
                        "{%0,%1,%2,%3}, {%4,%5,%6,%7}, {%8,%9}, {%0,%1,%2,%3};\n"
                        : "+f"(acc[mt][nt][0]), "+f"(acc[mt][nt][1]),
                          "+f"(acc[mt][nt][2]), "+f"(acc[mt][nt][3])
                        : "r"(af[mt][0]), "r"(af[mt][1]), "r"(af[mt][2]), "r"(af[mt][3]),
                          "r"(bf[nt][0]), "r"(bf[nt][1]));
                }
        }
        if (s + 1 < nsteps) {
            int nb = cur ^ 1;
            As[nb][aK + 0][aRow] = to_tf32(pa0.x);
            As[nb][aK + 1][aRow] = to_tf32(pa0.y);
            As[nb][aK + 2][aRow] = to_tf32(pa0.z);
            As[nb][aK + 3][aRow] = to_tf32(pa0.w);
            As[nb][aK + 0][aRow + 64] = to_tf32(pa1.x);
            As[nb][aK + 1][aRow + 64] = to_tf32(pa1.y);
            As[nb][aK + 2][aRow + 64] = to_tf32(pa1.z);
            As[nb][aK + 3][aRow + 64] = to_tf32(pa1.w);
            float4 q0 = make_float4(to_tf32(pb0.x), to_tf32(pb0.y), to_tf32(pb0.z), to_tf32(pb0.w));
            float4 q1 = make_float4(to_tf32(pb1.x), to_tf32(pb1.y), to_tf32(pb1.z), to_tf32(pb1.w));
            *reinterpret_cast<float4*>(&Bs[nb][bK][bN])      = q0;
            *reinterpret_cast<float4*>(&Bs[nb][bK][bN + 64]) = q1;
        }
        __syncthreads();
    }

    // epilogue
    #pragma unroll
    for (int mt = 0; mt < 4; ++mt) {
        int row0 = bm + wm + mt * 16 + g;
        #pragma unroll
        for (int rr = 0; rr < 2; ++rr) {
            int row = row0 + rr * 8;
            int bb = row / HW_;
            int pp = row - bb * HW_;
            #pragma unroll
            for (int nt = 0; nt < 4; ++nt) {
                #pragma unroll
                for (int cc = 0; cc < 2; ++cc) {
                    int col = bn + wn + nt * 8 + 2 * tig + cc;
                    float v = acc[mt][nt][rr * 2 + cc] + bias[col];
                    if (EPI == 1) v = 0.5f * v * (1.f + erff(v * 0.70710678f));
                    if (EPI == 2) v *= aux[(size_t)row * 128 + col];
                    if (EPI == 3)
                        Cout[(size_t)(bb * 256 + col) * HW_ + pp] = v;
                    else
                        Cout[(size_t)row * ldc + coloff + col] = v;
                }
            }
        }
    }
}

// ---------------------------------------------------------------------------
// 2b) Small FFMA SGEMM (kept for the 288-row pooled GEMM only)
// ---------------------------------------------------------------------------
__global__ __launch_bounds__(256)
void sgemm_small(const float* __restrict__ A, const float* __restrict__ Wm,
                 const float* __restrict__ bias, float* __restrict__ Cout,
                 int M, int N, int K)
{
    __shared__ float As[16][132];
    __shared__ float Ws[16][64];
    int tid = threadIdx.x;
    int bm = blockIdx.y * 128;
    int bn = blockIdx.x * 64;
    int tx = tid & 15, ty = tid >> 4;
    float acc[8][4];
    #pragma unroll
    for (int i = 0; i < 8; ++i)
        #pragma unroll
        for (int j = 0; j < 4; ++j) acc[i][j] = 0.f;
    int aRow = tid >> 2;
    int aK   = (tid & 3) << 2;
    int wRow = tid >> 4;
    int wCol = (tid & 15) << 2;
    for (int k0 = 0; k0 < K; k0 += 16) {
        #pragma unroll
        for (int r = 0; r < 2; ++r) {
            int row = bm + aRow + r * 64;
            float4 v = make_float4(0.f, 0.f, 0.f, 0.f);
            if (row < M)
                v = *reinterpret_cast<const float4*>(A + (size_t)row * K + k0 + aK);
            As[aK + 0][aRow + r * 64] = v.x;
            As[aK + 1][aRow + r * 64] = v.y;
            As[aK + 2][aRow + r * 64] = v.z;
            As[aK + 3][aRow + r * 64] = v.w;
        }
        *reinterpret_cast<float4*>(&Ws[wRow][wCol]) =
            *reinterpret_cast<const float4*>(Wm + (size_t)(k0 + wRow) * N + bn + wCol);
        __syncthreads();
        #pragma unroll
        for (int kk = 0; kk < 16; ++kk) {
            float a[8], bf[4];
            #pragma unroll
            for (int i = 0; i < 8; ++i) a[i] = As[kk][ty * 8 + i];
            #pragma unroll
            for (int j = 0; j < 4; ++j) bf[j] = Ws[kk][tx * 4 + j];
            #pragma unroll
            for (int i = 0; i < 8; ++i)
                #pragma unroll
                for (int j = 0; j < 4; ++j)
                    acc[i][j] = fmaf(a[i], bf[j], acc[i][j]);
        }
        __syncthreads();
    }
    #pragma unroll
    for (int i = 0; i < 8; ++i) {
        int row = bm + ty * 8 + i;
        if (row >= M) continue;
        #pragma unroll
        for (int j = 0; j < 4; ++j) {
            int col = bn + tx * 4 + j;
            Cout[(size_t)row * N + col] = acc[i][j] + bias[col];
        }
    }
}

// ---------------------------------------------------------------------------
// 3) AdaptiveAvgPool2d((6,6)) on cat(xc, xec)
// ---------------------------------------------------------------------------
__global__ void pool_kernel(const float* __restrict__ xc, const float* __restrict__ xec,
                            float* __restrict__ pooled)
{
    int b = blockIdx.y, q = blockIdx.x;
    int qy = q / 6, qx = q - qy * 6;
    int c  = threadIdx.x;
    const float* src = (c < 256) ? xc : xec;
    int cc = c & 255;
    size_t base = (size_t)b * HW_;
    float acc = 0.f;
    for (int i = 0; i < 22; ++i) {
        size_t rowp = base + (size_t)((qy * 22 + i) * 132 + qx * 22);
        for (int j = 0; j < 22; ++j)
            acc += src[(rowp + j) * 256 + cc];
    }
    pooled[(size_t)(b * 36 + q) * 512 + c] = acc * (1.f / 484.f);
}

// ---------------------------------------------------------------------------
// 4) Attention (online softmax, split over keys) + combine
// ---------------------------------------------------------------------------
__global__ __launch_bounds__(288)
void attn_partial(const float* __restrict__ kv, const float* __restrict__ mq_all,
                  float* __restrict__ pmax, float* __restrict__ psum,
                  float* __restrict__ pacc)
{
    __shared__ float ks[CHUNK_][17];
    __shared__ float vs[CHUNK_][17];
    int b = blockIdx.z, head = blockIdx.y, sp = blockIdx.x;
    int tid = threadIdx.x;
    int q = tid >> 3, j = tid & 7;
    float mq[16];
    #pragma unroll
    for (int d = 0; d < 16; ++d)
        mq[d] = mq_all[(size_t)(b * 36 + q) * 128 + head * 16 + d] * 0.25f;
    float mx = -INFINITY, sm = 0.f;
    float acc[16];
    #pragma unroll
    for (int d = 0; d < 16; ++d) acc[d] = 0.f;
    int kb = sp * KPS_;
    for (int c0 = 0; c0 < NCHUNK_; ++c0) {
        int pos0 = kb + c0 * CHUNK_;
        for (int idx = tid; idx < CHUNK_ * 16; idx += 288) {
            int key = idx >> 4, d = idx & 15;
            size_t base = ((size_t)b * HW_ + pos0 + key) * 256 + head * 16 + d;
            ks[key][d] = kv[base];
            vs[key][d] = kv[base + 128];
        }
        __syncthreads();
        for (int key = j; key < CHUNK_; key += 8) {
            float s = 0.f;
            #pragma unroll
            for (int d = 0; d < 16; ++d) s = fmaf(mq[d], ks[key][d], s);
            if (s <= mx) {
                float p = __expf(s - mx);
                sm += p;
                #pragma unroll
                for (int d = 0; d < 16; ++d) acc[d] = fmaf(p, vs[key][d], acc[d]);
            } else {
                float cr = __expf(mx - s);
                sm = fmaf(sm, cr, 1.f);
                #pragma unroll
                for (int d = 0; d < 16; ++d) acc[d] = fmaf(acc[d], cr, vs[key][d]);
                mx = s;
            }
        }
        __syncthreads();
    }
    #pragma unroll
    for (int o = 4; o > 0; o >>= 1) {
        float omx = __shfl_xor_sync(0xffffffffu, mx, o);
        float osm = __shfl_xor_sync(0xffffffffu, sm, o);
        float nm = fmaxf(mx, omx);
        float c1 = __expf(mx - nm), c2 = __expf(omx - nm);
        sm = sm * c1 + osm * c2;
        #pragma unroll
        for (int d = 0; d < 16; ++d) {
            float oa = __shfl_xor_sync(0xffffffffu, acc[d], o);
            acc[d] = acc[d] * c1 + oa * c2;
        }
        mx = nm;
    }
    int pi = (b * NH_ + head) * 36 + q;
    if (j == 0) {
        pmax[pi * SPLIT_ + sp] = mx;
        psum[pi * SPLIT_ + sp] = sm;
        #pragma unroll
        for (int d = 0; d < 16; ++d)
            pacc[((size_t)pi * SPLIT_ + sp) * 16 + d] = acc[d];
    }
}

__global__ void attn_combine(const float* __restrict__ pmax, const float* __restrict__ psum,
                             const float* __restrict__ pacc, float* __restrict__ sm_out)
{
    int idx = blockIdx.x * blockDim.x + threadIdx.x;
    if (idx >= B_ * NH_ * 36 * 16) return;
    int d  = idx & 15;
    int q  = (idx >> 4) % 36;
    int bh = idx / (16 * 36);
    int pi = bh * 36 + q;
    float gm = -INFINITY;
    #pragma unroll
    for (int s = 0; s < SPLIT_; ++s) gm = fmaxf(gm, pmax[pi * SPLIT_ + s]);
    float ts = 0.f, tv = 0.f;
    #pragma unroll
    for (int s = 0; s < SPLIT_; ++s) {
        float c = __expf(pmax[pi * SPLIT_ + s] - gm);
        ts += c * psum[pi * SPLIT_ + s];
        tv += c * pacc[((size_t)pi * SPLIT_ + s) * 16 + d];
    }
    int b = bh >> 3, head = bh & 7;
    sm_out[(size_t)(b * 128 + head * 16 + d) * 36 + q] = tv / ts;
}

// ---------------------------------------------------------------------------
// 5) Bilinear upsample (B,128,6,6) -> cat[:, 0:128]
// ---------------------------------------------------------------------------
__global__ void upsample_kernel(const float* __restrict__ sm_in, float* __restrict__ cat)
{
    __shared__ float s[36][128];
    int b = blockIdx.y;
    for (int idx = threadIdx.x; idx < 36 * 128; idx += 128) {
        int q = idx >> 7, ch = idx & 127;
        s[q][ch] = sm_in[(size_t)(b * 128 + ch) * 36 + q];
    }
    __syncthreads();
    int ch = threadIdx.x;
    int p0 = blockIdx.x * 64;
    for (int k = 0; k < 64; ++k) {
        int p = p0 + k;
        if (p >= HW_) return;
        int h = p / 132, w = p - h * 132;
        float sy = (h + 0.5f) * (1.f / 22.f) - 0.5f;
        float sx = (w + 0.5f) * (1.f / 22.f) - 0.5f;
        float fy0 = floorf(sy), fx0 = floorf(sx);
        float fy = sy - fy0, fx = sx - fx0;
        int y0 = (int)fy0, x0 = (int)fx0;
        int y1 = min(y0 + 1, 5), x1 = min(x0 + 1, 5);
        y0 = max(y0, 0); x0 = max(x0, 0);
        float v00 = s[y0 * 6 + x0][ch], v01 = s[y0 * 6 + x1][ch];
        float v10 = s[y1 * 6 + x0][ch], v11 = s[y1 * 6 + x1][ch];
        float v = (1.f - fy) * ((1.f - fx) * v00 + fx * v01)
                + fy * ((1.f - fx) * v10 + fx * v11);
        cat[((size_t)b * HW_ + p) * 384 + ch] = v;
    }
}

// ---------------------------------------------------------------------------
// 6) Depthwise 7x7 conv, NHWC channels-inner
// ---------------------------------------------------------------------------
__global__ __launch_bounds__(256)
void dwconv_kernel(const float* __restrict__ in, const float* __restrict__ wgt,
                   const float* __restrict__ cbias, float* __restrict__ out)
{
    __shared__ float s[10][22][32];
    __shared__ float wsm[32][49];
    int wt = blockIdx.x, ht = blockIdx.y;
    int bz = blockIdx.z;
    int b = bz >> 2, cg = bz & 3;
    int h0 = ht * 4, w0 = wt * 16;
    int tid = threadIdx.x;
    for (int idx = tid; idx < 32 * 49; idx += 256) {
        int ch = idx / 49, t = idx - ch * 49;
        wsm[ch][t] = wgt[(cg * 32 + ch) * 49 + t];
    }
    const float* inb = in + (size_t)b * HW_ * 128;
    for (int idx = tid; idx < 10 * 22 * 32; idx += 256) {
        int ch = idx & 31;
        int r  = idx >> 5;
        int lw = r % 22, lh = r / 22;
        int gh = h0 - 3 + lh, gw = w0 - 3 + lw;
        float v = 0.f;
        if (gh >= 0 && gh < 132 && gw >= 0 && gw < 132)
            v = inb[(size_t)(gh * 132 + gw) * 128 + cg * 32 + ch];
        s[lh][lw][ch] = v;
    }
    __syncthreads();
    int ch = tid & 31;
    int pg = tid >> 5;
    float acc[8];
    #pragma unroll
    for (int i = 0; i < 8; ++i) acc[i] = 0.f;
    #pragma unroll
    for (int dy = 0; dy < 7; ++dy)
        #pragma unroll
        for (int dx = 0; dx < 7; ++dx) {
            float wv = wsm[ch][dy * 7 + dx];
            #pragma unroll
            for (int pi = 0; pi < 8; ++pi) {
                int posid = pg + pi * 8;
                int lh = posid >> 4, lw = posid & 15;
                acc[pi] = fmaf(wv, s[lh + dy][lw + dx][ch], acc[pi]);
            }
        }
    float bv = cbias[cg * 32 + ch];
    #pragma unroll
    for (int pi = 0; pi < 8; ++pi) {
        int posid = pg + pi * 8;
        int lh = posid >> 4, lw = posid & 15;
        int gw = w0 + lw;
        if (gw < 132)
            out[((size_t)b * HW_ + (h0 + lh) * 132 + gw) * 128 + cg * 32 + ch]
                = acc[pi] + bv;
    }
}

// ---------------------------------------------------------------------------
// Launcher
// ---------------------------------------------------------------------------
extern "C" void kernel_launch(void* const* d_in, const int* in_sizes, int n_in,
                              void* d_out, int out_size)
{
    (void)in_sizes; (void)n_in; (void)out_size;
    const float* x       = (const float*)d_in[0];
    const float* x_e     = (const float*)d_in[1];
    const float* norm_w  = (const float*)d_in[2];
    const float* norm_b  = (const float*)d_in[3];
    const float* norme_w = (const float*)d_in[4];
    const float* norme_b = (const float*)d_in[5];
    const float* l_w     = (const float*)d_in[6];
    const float* l_b     = (const float*)d_in[7];
    const float* kv_w    = (const float*)d_in[8];
    const float* kv_b    = (const float*)d_in[9];
    const float* xe_w    = (const float*)d_in[10];
    const float* xe_b    = (const float*)d_in[11];
    const float* q_w     = (const float*)d_in[12];
    const float* q_b     = (const float*)d_in[13];
    const float* ef_w    = (const float*)d_in[14];
    const float* ef_b    = (const float*)d_in[15];
    const float* ec_w    = (const float*)d_in[16];
    const float* ec_b    = (const float*)d_in[17];
    const float* eb_w    = (const float*)d_in[18];
    const float* eb_b    = (const float*)d_in[19];
    const float* proj_w  = (const float*)d_in[20];
    const float* proj_b  = (const float*)d_in[21];
    const float* proje_w = (const float*)d_in[22];
    const float* proje_b = (const float*)d_in[23];

    float* base = nullptr;
    cudaGetSymbolAddress((void**)&base, g_scratch);
    float* xc    = base + OFF_XC;
    float* xec   = base + OFF_XEC;
    float* xg    = base + OFF_XG;
    float* kvb   = base + OFF_KV;
    float* cat   = base + OFF_CAT;
    float* t1    = base + OFF_T1;
    float* t2    = base + OFF_T2;
    float* t3    = base + OFF_T3;
    float* pool  = base + OFF_POOL;
    float* mbuf  = base + OFF_MM;
    float* smalb = base + OFF_SMALL;
    float* pmax  = base + OFF_PMAX;
    float* psum  = base + OFF_PSUM;
    float* pacc  = base + OFF_PACC;

    float* outp = (float*)d_out;
    float* oute = outp + SZ_BIG;

    dim3 lnG((HW_ + 31) / 32, B_);
    ln_kernel<<<lnG, 256>>>(x,   norm_w,  norm_b,  xc);
    ln_kernel<<<lnG, 256>>>(x_e, norme_w, norme_b, xec);

    // GFA: xg = gelu(xc @ l_w + l_b); kv = xg @ kv_w + kv_b
    tgemm<1><<<dim3(2, 1089), 256>>>(xc, l_w,  l_b,  nullptr, xg,  M_, 256, 256, 256, 0);
    tgemm<0><<<dim3(2, 1089), 256>>>(xg, kv_w, kv_b, nullptr, kvb, M_, 256, 256, 256, 0);

    pool_kernel<<<dim3(36, B_), 512>>>(xc, xec, pool);
    sgemm_small<<<dim3(2, 3), 256>>>(pool, xe_w, xe_b, mbuf, B_ * 36, 128, 512);

    attn_partial<<<dim3(SPLIT_, NH_, B_), 288>>>(kvb, mbuf, pmax, psum, pacc);
    attn_combine<<<(B_ * NH_ * 36 * 16 + 255) / 256, 256>>>(pmax, psum, pacc, smalb);
    upsample_kernel<<<dim3((HW_ + 63) / 64, B_), 128>>>(smalb, cat);  // cat[:,0:128]

    // LFA 1: q from xc, e from xec -> cat[:,128:256]
    tgemm<0><<<dim3(1, 1089), 256>>>(xc,  q_w,  q_b,  nullptr, t1, M_, 128, 256, 128, 0);
    tgemm<0><<<dim3(1, 1089), 256>>>(xec, ef_w, ef_b, nullptr, t2, M_, 128, 256, 128, 0);
    dwconv_kernel<<<dim3(9, 33, B_ * 4), 256>>>(t2, ec_w, ec_b, t3);
    tgemm<2><<<dim3(1, 1089), 256>>>(t3, eb_w, eb_b, t1, cat, M_, 128, 128, 384, 128);

    // LFA 2: q from xec, e from xc -> cat[:,256:384]
    tgemm<0><<<dim3(1, 1089), 256>>>(xec, q_w,  q_b,  nullptr, t1, M_, 128, 256, 128, 0);
    tgemm<0><<<dim3(1, 1089), 256>>>(xc,  ef_w, ef_b, nullptr, t2, M_, 128, 256, 128, 0);
    dwconv_kernel<<<dim3(9, 33, B_ * 4), 256>>>(t2, ec_w, ec_b, t3);
    tgemm<2><<<dim3(1, 1089), 256>>>(t3, eb_w, eb_b, t1, cat, M_, 128, 128, 384, 256);

    // Projections, NCHW outputs: out then out_e
    tgemm<3><<<dim3(2, 1089), 256>>>(cat, proj_w,  proj_b,  nullptr, outp, M_, 256, 384, 0, 0);
    tgemm<3><<<dim3(2, 1089), 256>>>(cat, proje_w, proje_b, nullptr, oute, M_, 256, 384, 0, 0);
}

// round 6
// speedup vs baseline: 2.0933x; 1.0868x over previous
#include <cuda_runtime.h>
#include <math.h>
#include <stdint.h>

// ---------------------------------------------------------------------------
// Problem constants
// ---------------------------------------------------------------------------
namespace {
constexpr int B_ = 8, C_ = 256, H_ = 132, W_ = 132, NH_ = 8, D_ = 16;
constexpr int HW_ = H_ * W_;          // 17424
constexpr int M_  = B_ * HW_;         // 139392  (== 1089 * 128 exactly)
constexpr int CH_ = 128;              // C/2
constexpr int C2_ = 512;              // 2C
constexpr int C3_ = 384;              // 3C/2
constexpr int SPLIT_  = 8;
constexpr int KPS_    = HW_ / SPLIT_; // 2178 keys per split
constexpr int CHUNK_  = 66;           // keys per smem chunk (2178 = 33*66)
constexpr int NCHUNK_ = KPS_ / CHUNK_;

constexpr size_t SZ_BIG  = (size_t)M_ * C_;
constexpr size_t SZ_CAT  = (size_t)M_ * C3_;
constexpr size_t SZ_HALF = (size_t)M_ * CH_;

constexpr size_t OFF_XC    = 0;
constexpr size_t OFF_XEC   = OFF_XC  + SZ_BIG;
constexpr size_t OFF_XG    = OFF_XEC + SZ_BIG;
constexpr size_t OFF_KV    = OFF_XG  + SZ_BIG;
constexpr size_t OFF_CAT   = OFF_KV  + SZ_BIG;
constexpr size_t OFF_T1    = OFF_CAT + SZ_CAT;
constexpr size_t OFF_T2    = OFF_T1  + SZ_HALF;
constexpr size_t OFF_T3    = OFF_T2  + SZ_HALF;
constexpr size_t OFF_T4    = OFF_T3  + SZ_HALF;
constexpr size_t OFF_T5    = OFF_T4  + SZ_HALF;
constexpr size_t OFF_POOL  = OFF_T5  + SZ_HALF;
constexpr size_t OFF_MM    = OFF_POOL  + (size_t)B_ * 36 * C2_;
constexpr size_t OFF_SMALL = OFF_MM    + (size_t)B_ * 36 * CH_;
constexpr size_t OFF_PMAX  = OFF_SMALL + (size_t)B_ * CH_ * 36;
constexpr size_t OFF_PSUM  = OFF_PMAX  + (size_t)B_ * NH_ * 36 * SPLIT_;
constexpr size_t OFF_PACC  = OFF_PSUM  + (size_t)B_ * NH_ * 36 * SPLIT_;
constexpr size_t OFF_WQEF  = OFF_PACC  + (size_t)B_ * NH_ * 36 * SPLIT_ * D_;
constexpr size_t OFF_BQEF  = OFF_WQEF  + 256 * 256;
constexpr size_t OFF_WPROJ = OFF_BQEF  + 256;
constexpr size_t OFF_BPROJ = OFF_WPROJ + 384 * 512;
constexpr size_t SCRATCH_TOTAL = OFF_BPROJ + 512;
}  // namespace

__device__ float g_scratch[SCRATCH_TOTAL];

// ---------------------------------------------------------------------------
// helpers
// ---------------------------------------------------------------------------
__device__ __forceinline__ float to_tf32(float x) {
    float r;
    asm("cvt.rna.tf32.f32 %0, %1;" : "=f"(r) : "f"(x));
    return r;
}

__device__ __forceinline__ void ldsm4(uint32_t& r0, uint32_t& r1, uint32_t& r2,
                                      uint32_t& r3, uint32_t addr) {
    asm volatile("ldmatrix.sync.aligned.m8n8.x4.shared.b16 {%0,%1,%2,%3}, [%4];"
                 : "=r"(r0), "=r"(r1), "=r"(r2), "=r"(r3) : "r"(addr));
}

// ---------------------------------------------------------------------------
// 0) pack q|ef and proj|proje weights into fused operands
// ---------------------------------------------------------------------------
__global__ void pack_weights(const float* __restrict__ qw, const float* __restrict__ qb,
                             const float* __restrict__ efw, const float* __restrict__ efb,
                             const float* __restrict__ pw, const float* __restrict__ pb,
                             const float* __restrict__ pew, const float* __restrict__ peb,
                             float* __restrict__ wqef, float* __restrict__ bqef,
                             float* __restrict__ wproj, float* __restrict__ bproj)
{
    int i = blockIdx.x * 256 + threadIdx.x;
    if (i < 256 * 256) {
        int k = i >> 8, j = i & 255;
        wqef[i] = (j < 128) ? qw[k * 128 + j] : efw[k * 128 + (j - 128)];
    }
    if (i < 384 * 512) {
        int k = i >> 9, j = i & 511;
        wproj[i] = (j < 256) ? pw[k * 256 + j] : pew[k * 256 + (j - 256)];
    }
    if (i < 256) bqef[i] = (i < 128) ? qb[i] : efb[i - 128];
    if (i < 512) bproj[i] = (i < 256) ? pb[i] : peb[i - 256];
}

// ---------------------------------------------------------------------------
// 1) LayerNorm over channels with NCHW -> (B*HW, C) transpose
// ---------------------------------------------------------------------------
__global__ void ln_kernel(const float* __restrict__ x, const float* __restrict__ gw,
                          const float* __restrict__ gb, float* __restrict__ out)
{
    __shared__ float s[256][33];
    __shared__ float sw[256], sb[256];
    int tid  = threadIdx.x;
    int b    = blockIdx.y;
    int pos0 = blockIdx.x * 32;
    sw[tid] = gw[tid];
    sb[tid] = gb[tid];
    int px = tid & 31, cg = tid >> 5;
    int p  = pos0 + px;
    const float* xb = x + (size_t)b * C_ * HW_;
    bool valid = (p < HW_);
    for (int c = cg; c < 256; c += 8)
        s[c][px] = valid ? xb[(size_t)c * HW_ + p] : 0.f;
    __syncthreads();
    int warp = tid >> 5, lane = tid & 31;
    #pragma unroll
    for (int pi = 0; pi < 4; ++pi) {
        int pp = warp * 4 + pi;
        int gp = pos0 + pp;
        if (gp >= HW_) continue;
        float sum = 0.f, sum2 = 0.f;
        #pragma unroll
        for (int jj = 0; jj < 8; ++jj) {
            float v = s[lane + jj * 32][pp];
            sum += v; sum2 += v * v;
        }
        #pragma unroll
        for (int o = 16; o > 0; o >>= 1) {
            sum  += __shfl_xor_sync(0xffffffffu, sum,  o);
            sum2 += __shfl_xor_sync(0xffffffffu, sum2, o);
        }
        float mean = sum * (1.f / 256.f);
        float var  = fmaxf(sum2 * (1.f / 256.f) - mean * mean, 0.f);
        float rstd = rsqrtf(var + 1e-6f);
        float* orow = out + (size_t)(b * HW_ + gp) * 256;
        #pragma unroll
        for (int jj = 0; jj < 8; ++jj) {
            int c = lane + jj * 32;
            orow[c] = (s[c][pp] - mean) * rstd * sw[c] + sb[c];
        }
    }
}

// ---------------------------------------------------------------------------
// 2a) TF32 tensor-core GEMM with ldmatrix fragment loads.
//     BM=128 BN=128 BK=16, 256 threads (8 warps 2Mx4N, warp tile 64x32).
//     Smem: [row][k0..15], 16B-chunk XOR swizzle (chunk ^= (row>>1)&3).
//     Requires M%128==0, N%128==0, K%16==0.
//     EPI 0: plain (ldc,coloff)           EPI 1: exact GELU (ldc,coloff)
//     EPI 2: *aux then (ldc,coloff)       EPI 4: dual NCHW split at col 256
//     EPI 5: dual plain split at col 128 (Cout / Cout2, ld 128)
// ---------------------------------------------------------------------------
template <int EPI>
__global__ __launch_bounds__(256, 2)
void tgemm(const float* __restrict__ A, const float* __restrict__ Wm,
           const float* __restrict__ bias, const float* __restrict__ aux,
           float* __restrict__ Cout, float* __restrict__ Cout2,
           int M, int N, int K, int ldc, int coloff)
{
    __shared__ float As[2][128 * 16];
    __shared__ float Bs[2][128 * 16];
    const int tid = threadIdx.x;
    const int bm = blockIdx.y * 128;
    const int bn = blockIdx.x * 128;
    const int lane = tid & 31, wid = tid >> 5;
    const int wm = (wid & 1) * 64, wn = (wid >> 1) * 32;
    const int g = lane >> 2, tig = lane & 3;

    float acc[4][4][4] = {};

    uint32_t sA = (uint32_t)__cvta_generic_to_shared(&As[0][0]);
    uint32_t sB = (uint32_t)__cvta_generic_to_shared(&Bs[0][0]);

    // fragment base addresses (buffer 0, k8-block 0); other k8-block = ^32 bytes
    uint32_t aAddr[4], bAddr[2];
    {
        int rsel = ((lane >> 3) & 1) * 8 + (lane & 7);
        int csel = lane >> 4;  // 0/1
        #pragma unroll
        for (int mt = 0; mt < 4; ++mt) {
            int row = wm + mt * 16 + rsel;
            int c = csel ^ ((row >> 1) & 3);
            aAddr[mt] = sA + (uint32_t)(row * 16 + 4 * c) * 4u;
        }
        int m = lane >> 3;
        int nrsel = (m >> 1) * 8 + (lane & 7);
        int ncsel = m & 1;
        #pragma unroll
        for (int np = 0; np < 2; ++np) {
            int row = wn + np * 16 + nrsel;
            int c = ncsel ^ ((row >> 1) & 3);
            bAddr[np] = sB + (uint32_t)(row * 16 + 4 * c) * 4u;
        }
    }

    // global->smem staging maps
    const int aRow = tid >> 2;           // 0..63
    const int aK   = (tid & 3) << 2;     // 0,4,8,12
    const int ar1  = aRow + 64;
    const int aSt0 = aRow * 16 + 4 * ((aK >> 2) ^ ((aRow >> 1) & 3));
    const int aSt1 = ar1 * 16 + 4 * ((aK >> 2) ^ ((ar1 >> 1) & 3));
    const float* Ag0 = A + (size_t)(bm + aRow) * K + aK;
    const float* Ag1 = A + (size_t)(bm + ar1) * K + aK;

    const int bNl = tid & 127;
    const int bKh = (tid >> 7) * 8;      // 0 or 8
    const int bSt0 = bNl * 16 + 4 * (((bKh >> 2) + 0) ^ ((bNl >> 1) & 3));
    const int bSt1 = bNl * 16 + 4 * (((bKh >> 2) + 1) ^ ((bNl >> 1) & 3));
    const float* Bg = Wm + bn + bNl;

    float ar0v[4], ar1v[4], brv[8];
    auto gload = [&](int s) {
        float4 v0 = *reinterpret_cast<const float4*>(Ag0 + s * 16);
        float4 v1 = *reinterpret_cast<const float4*>(Ag1 + s * 16);
        ar0v[0] = v0.x; ar0v[1] = v0.y; ar0v[2] = v0.z; ar0v[3] = v0.w;
        ar1v[0] = v1.x; ar1v[1] = v1.y; ar1v[2] = v1.z; ar1v[3] = v1.w;
        int kbase = s * 16 + bKh;
        #pragma unroll
        for (int i = 0; i < 8; ++i)
            brv[i] = Bg[(size_t)(kbase + i) * N];
    };
    auto sstore = [&](int buf) {
        float* a = As[buf];
        float* b = Bs[buf];
        *reinterpret_cast<float4*>(&a[aSt0]) =
            make_float4(to_tf32(ar0v[0]), to_tf32(ar0v[1]), to_tf32(ar0v[2]), to_tf32(ar0v[3]));
        *reinterpret_cast<float4*>(&a[aSt1]) =
            make_float4(to_tf32(ar1v[0]), to_tf32(ar1v[1]), to_tf32(ar1v[2]), to_tf32(ar1v[3]));
        *reinterpret_cast<float4*>(&b[bSt0]) =
            make_float4(to_tf32(brv[0]), to_tf32(brv[1]), to_tf32(brv[2]), to_tf32(brv[3]));
        *reinterpret_cast<float4*>(&b[bSt1]) =
            make_float4(to_tf32(brv[4]), to_tf32(brv[5]), to_tf32(brv[6]), to_tf32(brv[7]));
    };
    auto compute = [&](int buf) {
        uint32_t bo = (uint32_t)buf * 8192u;
        #pragma unroll
        for (int kb2 = 0; kb2 < 2; ++kb2) {
            uint32_t kx = kb2 ? 32u : 0u;
            uint32_t a_[4][4], b_[4][2];
            #pragma unroll
            for (int mt = 0; mt < 4; ++mt)
                ldsm4(a_[mt][0], a_[mt][1], a_[mt][2], a_[mt][3],
                      (aAddr[mt] + bo) ^ kx);
            ldsm4(b_[0][0], b_[0][1], b_[1][0], b_[1][1], (bAddr[0] + bo) ^ kx);
            ldsm4(b_[2][0], b_[2][1], b_[3][0], b_[3][1], (bAddr[1] + bo) ^ kx);
            #pragma unroll
            for (int mt = 0; mt < 4; ++mt)
                #pragma unroll
                for (int nt = 0; nt < 4; ++nt) {
                    asm volatile(
                        "mma.sync.aligned.m16n8k8.row.col.f32.tf32.tf32.f32 "
                        "{%0,%1,%2,%3}, {%4,%5,%6,%7}, {%8,%9}, {%0,%1,%2,%3};\n"
                        : "+f"(acc[mt][nt][0]), "+f"(acc[mt][nt][1]),
                          "+f"(acc[mt][nt][2]), "+f"(acc[mt][nt][3])
                        : "r"(a_[mt][0]), "r"(a_[mt][1]), "r"(a_[mt][2]), "r"(a_[mt][3]),
                          "r"(b_[nt][0]), "r"(b_[nt][1]));
                }
        }
    };

    int nsteps = K >> 4;
    gload(0);
    sstore(0);
    __syncthreads();
    for (int s = 0; s < nsteps; ++s) {
        if (s + 1 < nsteps) gload(s + 1);
        compute(s & 1);
        if (s + 1 < nsteps) sstore((s + 1) & 1);
        __syncthreads();
    }

    // epilogue
    #pragma unroll
    for (int mt = 0; mt < 4; ++mt) {
        int row0 = bm + wm + mt * 16 + g;
        #pragma unroll
        for (int rr = 0; rr < 2; ++rr) {
            int row = row0 + rr * 8;
            int bb = row / HW_;
            int pp = row - bb * HW_;
            #pragma unroll
            for (int nt = 0; nt < 4; ++nt) {
                #pragma unroll
                for (int cc = 0; cc < 2; ++cc) {
                    int col = bn + wn + nt * 8 + 2 * tig + cc;
                    float v = acc[mt][nt][rr * 2 + cc] + bias[col];
                    if (EPI == 1) v = 0.5f * v * (1.f + erff(v * 0.70710678f));
                    if (EPI == 2) v *= aux[(size_t)row * 128 + col];
                    if (EPI == 4) {
                        float* tgt = (col < 256) ? Cout : Cout2;
                        tgt[(size_t)(bb * 256 + (col & 255)) * HW_ + pp] = v;
                    } else if (EPI == 5) {
                        if (col < 128) Cout[(size_t)row * 128 + col] = v;
                        else           Cout2[(size_t)row * 128 + (col - 128)] = v;
                    } else {
                        Cout[(size_t)row * ldc + coloff + col] = v;
                    }
                }
            }
        }
    }
}

// ---------------------------------------------------------------------------
// 2b) Small FFMA SGEMM (288-row pooled GEMM only)
// ---------------------------------------------------------------------------
__global__ __launch_bounds__(256)
void sgemm_small(const float* __restrict__ A, const float* __restrict__ Wm,
                 const float* __restrict__ bias, float* __restrict__ Cout,
                 int M, int N, int K)
{
    __shared__ float As[16][132];
    __shared__ float Ws[16][64];
    int tid = threadIdx.x;
    int bm = blockIdx.y * 128;
    int bn = blockIdx.x * 64;
    int tx = tid & 15, ty = tid >> 4;
    float acc[8][4];
    #pragma unroll
    for (int i = 0; i < 8; ++i)
        #pragma unroll
        for (int j = 0; j < 4; ++j) acc[i][j] = 0.f;
    int aRow = tid >> 2;
    int aK   = (tid & 3) << 2;
    int wRow = tid >> 4;
    int wCol = (tid & 15) << 2;
    for (int k0 = 0; k0 < K; k0 += 16) {
        #pragma unroll
        for (int r = 0; r < 2; ++r) {
            int row = bm + aRow + r * 64;
            float4 v = make_float4(0.f, 0.f, 0.f, 0.f);
            if (row < M)
                v = *reinterpret_cast<const float4*>(A + (size_t)row * K + k0 + aK);
            As[aK + 0][aRow + r * 64] = v.x;
            As[aK + 1][aRow + r * 64] = v.y;
            As[aK + 2][aRow + r * 64] = v.z;
            As[aK + 3][aRow + r * 64] = v.w;
        }
        *reinterpret_cast<float4*>(&Ws[wRow][wCol]) =
            *reinterpret_cast<const float4*>(Wm + (size_t)(k0 + wRow) * N + bn + wCol);
        __syncthreads();
        #pragma unroll
        for (int kk = 0; kk < 16; ++kk) {
            float a[8], bf[4];
            #pragma unroll
            for (int i = 0; i < 8; ++i) a[i] = As[kk][ty * 8 + i];
            #pragma unroll
            for (int j = 0; j < 4; ++j) bf[j] = Ws[kk][tx * 4 + j];
            #pragma unroll
            for (int i = 0; i < 8; ++i)
                #pragma unroll
                for (int j = 0; j < 4; ++j)
                    acc[i][j] = fmaf(a[i], bf[j], acc[i][j]);
        }
        __syncthreads();
    }
    #pragma unroll
    for (int i = 0; i < 8; ++i) {
        int row = bm + ty * 8 + i;
        if (row >= M) continue;
        #pragma unroll
        for (int j = 0; j < 4; ++j) {
            int col = bn + tx * 4 + j;
            Cout[(size_t)row * N + col] = acc[i][j] + bias[col];
        }
    }
}

// ---------------------------------------------------------------------------
// 3) AdaptiveAvgPool2d((6,6)) on cat(xc, xec)
// ---------------------------------------------------------------------------
__global__ void pool_kernel(const float* __restrict__ xc, const float* __restrict__ xec,
                            float* __restrict__ pooled)
{
    int b = blockIdx.y, q = blockIdx.x;
    int qy = q / 6, qx = q - qy * 6;
    int c  = threadIdx.x;
    const float* src = (c < 256) ? xc : xec;
    int cc = c & 255;
    size_t base = (size_t)b * HW_;
    float acc = 0.f;
    for (int i = 0; i < 22; ++i) {
        size_t rowp = base + (size_t)((qy * 22 + i) * 132 + qx * 22);
        for (int j = 0; j < 22; ++j)
            acc += src[(rowp + j) * 256 + cc];
    }
    pooled[(size_t)(b * 36 + q) * 512 + c] = acc * (1.f / 484.f);
}

// ---------------------------------------------------------------------------
// 4) Attention (online softmax, split over keys) + combine
// ---------------------------------------------------------------------------
__global__ __launch_bounds__(288)
void attn_partial(const float* __restrict__ kv, const float* __restrict__ mq_all,
                  float* __restrict__ pmax, float* __restrict__ psum,
                  float* __restrict__ pacc)
{
    __shared__ float ks[CHUNK_][17];
    __shared__ float vs[CHUNK_][17];
    int b = blockIdx.z, head = blockIdx.y, sp = blockIdx.x;
    int tid = threadIdx.x;
    int q = tid >> 3, j = tid & 7;
    float mq[16];
    #pragma unroll
    for (int d = 0; d < 16; ++d)
        mq[d] = mq_all[(size_t)(b * 36 + q) * 128 + head * 16 + d] * 0.25f;
    float mx = -INFINITY, sm = 0.f;
    float acc[16];
    #pragma unroll
    for (int d = 0; d < 16; ++d) acc[d] = 0.f;
    int kb = sp * KPS_;
    for (int c0 = 0; c0 < NCHUNK_; ++c0) {
        int pos0 = kb + c0 * CHUNK_;
        for (int idx = tid; idx < CHUNK_ * 16; idx += 288) {
            int key = idx >> 4, d = idx & 15;
            size_t base = ((size_t)b * HW_ + pos0 + key) * 256 + head * 16 + d;
            ks[key][d] = kv[base];
            vs[key][d] = kv[base + 128];
        }
        __syncthreads();
        for (int key = j; key < CHUNK_; key += 8) {
            float s = 0.f;
            #pragma unroll
            for (int d = 0; d < 16; ++d) s = fmaf(mq[d], ks[key][d], s);
            if (s <= mx) {
                float p = __expf(s - mx);
                sm += p;
                #pragma unroll
                for (int d = 0; d < 16; ++d) acc[d] = fmaf(p, vs[key][d], acc[d]);
            } else {
                float cr = __expf(mx - s);
                sm = fmaf(sm, cr, 1.f);
                #pragma unroll
                for (int d = 0; d < 16; ++d) acc[d] = fmaf(acc[d], cr, vs[key][d]);
                mx = s;
            }
        }
        __syncthreads();
    }
    #pragma unroll
    for (int o = 4; o > 0; o >>= 1) {
        float omx = __shfl_xor_sync(0xffffffffu, mx, o);
        float osm = __shfl_xor_sync(0xffffffffu, sm, o);
        float nm = fmaxf(mx, omx);
        float c1 = __expf(mx - nm), c2 = __expf(omx - nm);
        sm = sm * c1 + osm * c2;
        #pragma unroll
        for (int d = 0; d < 16; ++d) {
            float oa = __shfl_xor_sync(0xffffffffu, acc[d], o);
            acc[d] = acc[d] * c1 + oa * c2;
        }
        mx = nm;
    }
    int pi = (b * NH_ + head) * 36 + q;
    if (j == 0) {
        pmax[pi * SPLIT_ + sp] = mx;
        psum[pi * SPLIT_ + sp] = sm;
        #pragma unroll
        for (int d = 0; d < 16; ++d)
            pacc[((size_t)pi * SPLIT_ + sp) * 16 + d] = acc[d];
    }
}

__global__ void attn_combine(const float* __restrict__ pmax, const float* __restrict__ psum,
                             const float* __restrict__ pacc, float* __restrict__ sm_out)
{
    int idx = blockIdx.x * blockDim.x + threadIdx.x;
    if (idx >= B_ * NH_ * 36 * 16) return;
    int d  = idx & 15;
    int q  = (idx >> 4) % 36;
    int bh = idx / (16 * 36);
    int pi = bh * 36 + q;
    float gm = -INFINITY;
    #pragma unroll
    for (int s = 0; s < SPLIT_; ++s) gm = fmaxf(gm, pmax[pi * SPLIT_ + s]);
    float ts = 0.f, tv = 0.f;
    #pragma unroll
    for (int s = 0; s < SPLIT_; ++s) {
        float c = __expf(pmax[pi * SPLIT_ + s] - gm);
        ts += c * psum[pi * SPLIT_ + s];
        tv += c * pacc[((size_t)pi * SPLIT_ + s) * 16 + d];
    }
    int b = bh >> 3, head = bh & 7;
    sm_out[(size_t)(b * 128 + head * 16 + d) * 36 + q] = tv / ts;
}

// ---------------------------------------------------------------------------
// 5) Bilinear upsample (B,128,6,6) -> cat[:, 0:128]
// ---------------------------------------------------------------------------
__global__ void upsample_kernel(const float* __restrict__ sm_in, float* __restrict__ cat)
{
    __shared__ float s[36][128];
    int b = blockIdx.y;
    for (int idx = threadIdx.x; idx < 36 * 128; idx += 128) {
        int q = idx >> 7, ch = idx & 127;
        s[q][ch] = sm_in[(size_t)(b * 128 + ch) * 36 + q];
    }
    __syncthreads();
    int ch = threadIdx.x;
    int p0 = blockIdx.x * 64;
    for (int k = 0; k < 64; ++k) {
        int p = p0 + k;
        if (p >= HW_) return;
        int h = p / 132, w = p - h * 132;
        float sy = (h + 0.5f) * (1.f / 22.f) - 0.5f;
        float sx = (w + 0.5f) * (1.f / 22.f) - 0.5f;
        float fy0 = floorf(sy), fx0 = floorf(sx);
        float fy = sy - fy0, fx = sx - fx0;
        int y0 = (int)fy0, x0 = (int)fx0;
        int y1 = min(y0 + 1, 5), x1 = min(x0 + 1, 5);
        y0 = max(y0, 0); x0 = max(x0, 0);
        float v00 = s[y0 * 6 + x0][ch], v01 = s[y0 * 6 + x1][ch];
        float v10 = s[y1 * 6 + x0][ch], v11 = s[y1 * 6 + x1][ch];
        float v = (1.f - fy) * ((1.f - fx) * v00 + fx * v01)
                + fy * ((1.f - fx) * v10 + fx * v11);
        cat[((size_t)b * HW_ + p) * 384 + ch] = v;
    }
}

// ---------------------------------------------------------------------------
// 6) Depthwise 7x7 conv, NHWC channels-inner
// ---------------------------------------------------------------------------
__global__ __launch_bounds__(256)
void dwconv_kernel(const float* __restrict__ in, const float* __restrict__ wgt,
                   const float* __restrict__ cbias, float* __restrict__ out)
{
    __shared__ float s[10][22][32];
    __shared__ float wsm[32][49];
    int wt = blockIdx.x, ht = blockIdx.y;
    int bz = blockIdx.z;
    int b = bz >> 2, cg = bz & 3;
    int h0 = ht * 4, w0 = wt * 16;
    int tid = threadIdx.x;
    for (int idx = tid; idx < 32 * 49; idx += 256) {
        int ch = idx / 49, t = idx - ch * 49;
        wsm[ch][t] = wgt[(cg * 32 + ch) * 49 + t];
    }
    const float* inb = in + (size_t)b * HW_ * 128;
    for (int idx = tid; idx < 10 * 22 * 32; idx += 256) {
        int ch = idx & 31;
        int r  = idx >> 5;
        int lw = r % 22, lh = r / 22;
        int gh = h0 - 3 + lh, gw = w0 - 3 + lw;
        float v = 0.f;
        if (gh >= 0 && gh < 132 && gw >= 0 && gw < 132)
            v = inb[(size_t)(gh * 132 + gw) * 128 + cg * 32 + ch];
        s[lh][lw][ch] = v;
    }
    __syncthreads();
    int ch = tid & 31;
    int pg = tid >> 5;
    float acc[8];
    #pragma unroll
    for (int i = 0; i < 8; ++i) acc[i] = 0.f;
    #pragma unroll
    for (int dy = 0; dy < 7; ++dy)
        #pragma unroll
        for (int dx = 0; dx < 7; ++dx) {
            float wv = wsm[ch][dy * 7 + dx];
            #pragma unroll
            for (int pi = 0; pi < 8; ++pi) {
                int posid = pg + pi * 8;
                int lh = posid >> 4, lw = posid & 15;
                acc[pi] = fmaf(wv, s[lh + dy][lw + dx][ch], acc[pi]);
            }
        }
    float bv = cbias[cg * 32 + ch];
    #pragma unroll
    for (int pi = 0; pi < 8; ++pi) {
        int posid = pg + pi * 8;
        int lh = posid >> 4, lw = posid & 15;
        int gw = w0 + lw;
        if (gw < 132)
            out[((size_t)b * HW_ + (h0 + lh) * 132 + gw) * 128 + cg * 32 + ch]
                = acc[pi] + bv;
    }
}

// ---------------------------------------------------------------------------
// Launcher
// ---------------------------------------------------------------------------
extern "C" void kernel_launch(void* const* d_in, const int* in_sizes, int n_in,
                              void* d_out, int out_size)
{
    (void)in_sizes; (void)n_in; (void)out_size;
    const float* x       = (const float*)d_in[0];
    const float* x_e     = (const float*)d_in[1];
    const float* norm_w  = (const float*)d_in[2];
    const float* norm_b  = (const float*)d_in[3];
    const float* norme_w = (const float*)d_in[4];
    const float* norme_b = (const float*)d_in[5];
    const float* l_w     = (const float*)d_in[6];
    const float* l_b     = (const float*)d_in[7];
    const float* kv_w    = (const float*)d_in[8];
    const float* kv_b    = (const float*)d_in[9];
    const float* xe_w    = (const float*)d_in[10];
    const float* xe_b    = (const float*)d_in[11];
    const float* q_w     = (const float*)d_in[12];
    const float* q_b     = (const float*)d_in[13];
    const float* ef_w    = (const float*)d_in[14];
    const float* ef_b    = (const float*)d_in[15];
    const float* ec_w    = (const float*)d_in[16];
    const float* ec_b    = (const float*)d_in[17];
    const float* eb_w    = (const float*)d_in[18];
    const float* eb_b    = (const float*)d_in[19];
    const float* proj_w  = (const float*)d_in[20];
    const float* proj_b  = (const float*)d_in[21];
    const float* proje_w = (const float*)d_in[22];
    const float* proje_b = (const float*)d_in[23];

    float* base = nullptr;
    cudaGetSymbolAddress((void**)&base, g_scratch);
    float* xc    = base + OFF_XC;
    float* xec   = base + OFF_XEC;
    float* xg    = base + OFF_XG;
    float* kvb   = base + OFF_KV;
    float* cat   = base + OFF_CAT;
    float* t1    = base + OFF_T1;   // q (LFA1, from xc)
    float* t2    = base + OFF_T2;   // ef (LFA1, from xec)
    float* t3    = base + OFF_T3;   // conv output (shared)
    float* t4    = base + OFF_T4;   // q (LFA2, from xec)
    float* t5    = base + OFF_T5;   // ef (LFA2, from xc)
    float* pool  = base + OFF_POOL;
    float* mbuf  = base + OFF_MM;
    float* smalb = base + OFF_SMALL;
    float* pmax  = base + OFF_PMAX;
    float* psum  = base + OFF_PSUM;
    float* pacc  = base + OFF_PACC;
    float* wqef  = base + OFF_WQEF;
    float* bqef  = base + OFF_BQEF;
    float* wproj = base + OFF_WPROJ;
    float* bproj = base + OFF_BPROJ;

    float* outp = (float*)d_out;
    float* oute = outp + SZ_BIG;

    pack_weights<<<768, 256>>>(q_w, q_b, ef_w, ef_b, proj_w, proj_b,
                               proje_w, proje_b, wqef, bqef, wproj, bproj);

    dim3 lnG((HW_ + 31) / 32, B_);
    ln_kernel<<<lnG, 256>>>(x,   norm_w,  norm_b,  xc);
    ln_kernel<<<lnG, 256>>>(x_e, norme_w, norme_b, xec);

    // GFA: xg = gelu(xc @ l_w + l_b); kv = xg @ kv_w + kv_b
    tgemm<1><<<dim3(2, 1089), 256>>>(xc, l_w,  l_b,  nullptr, xg,  nullptr, M_, 256, 256, 256, 0);
    tgemm<0><<<dim3(2, 1089), 256>>>(xg, kv_w, kv_b, nullptr, kvb, nullptr, M_, 256, 256, 256, 0);

    pool_kernel<<<dim3(36, B_), 512>>>(xc, xec, pool);
    sgemm_small<<<dim3(2, 3), 256>>>(pool, xe_w, xe_b, mbuf, B_ * 36, 128, 512);

    attn_partial<<<dim3(SPLIT_, NH_, B_), 288>>>(kvb, mbuf, pmax, psum, pacc);
    attn_combine<<<(B_ * NH_ * 36 * 16 + 255) / 256, 256>>>(pmax, psum, pacc, smalb);
    upsample_kernel<<<dim3((HW_ + 63) / 64, B_), 128>>>(smalb, cat);  // cat[:,0:128]

    // fused q|ef GEMMs (one per input)
    tgemm<5><<<dim3(2, 1089), 256>>>(xc,  wqef, bqef, nullptr, t1, t5, M_, 256, 256, 0, 0);
    tgemm<5><<<dim3(2, 1089), 256>>>(xec, wqef, bqef, nullptr, t4, t2, M_, 256, 256, 0, 0);

    // LFA 1: conv(ef from xec), eb GEMM * q(xc) -> cat[:,128:256]
    dwconv_kernel<<<dim3(9, 33, B_ * 4), 256>>>(t2, ec_w, ec_b, t3);
    tgemm<2><<<dim3(1, 1089), 256>>>(t3, eb_w, eb_b, t1, cat, nullptr, M_, 128, 128, 384, 128);

    // LFA 2: conv(ef from xc), eb GEMM * q(xec) -> cat[:,256:384]
    dwconv_kernel<<<dim3(9, 33, B_ * 4), 256>>>(t5, ec_w, ec_b, t3);
    tgemm<2><<<dim3(1, 1089), 256>>>(t3, eb_w, eb_b, t4, cat, nullptr, M_, 128, 128, 384, 256);

    // fused projections, NCHW outputs split at col 256
    tgemm<4><<<dim3(4, 1089), 256>>>(cat, wproj, bproj, nullptr, outp, oute, M_, 512, 384, 0, 0);
}

// round 8
// speedup vs baseline: 2.1574x; 1.0306x over previous
#include <cuda_runtime.h>
#include <math.h>
#include <stdint.h>

// ---------------------------------------------------------------------------
// Problem constants
// ---------------------------------------------------------------------------
namespace {
constexpr int B_ = 8, C_ = 256, H_ = 132, W_ = 132, NH_ = 8, D_ = 16;
constexpr int HW_ = H_ * W_;          // 17424
constexpr int M_  = B_ * HW_;         // 139392  (== 1089 * 128 exactly)
constexpr int CH_ = 128;              // C/2
constexpr int C2_ = 512;              // 2C
constexpr int C3_ = 384;              // 3C/2
constexpr int SPLIT_  = 8;
constexpr int KPS_    = HW_ / SPLIT_; // 2178 keys per split
constexpr int CHUNK_  = 66;           // keys per smem chunk (2178 = 33*66)
constexpr int NCHUNK_ = KPS_ / CHUNK_;

constexpr size_t SZ_BIG  = (size_t)M_ * C_;
constexpr size_t SZ_CAT  = (size_t)M_ * C3_;
constexpr size_t SZ_HALF = (size_t)M_ * CH_;

constexpr size_t OFF_XC    = 0;
constexpr size_t OFF_XEC   = OFF_XC  + SZ_BIG;
constexpr size_t OFF_XG    = OFF_XEC + SZ_BIG;
constexpr size_t OFF_KV    = OFF_XG  + SZ_BIG;
constexpr size_t OFF_CAT   = OFF_KV  + SZ_BIG;
constexpr size_t OFF_T1    = OFF_CAT + SZ_CAT;
constexpr size_t OFF_T2    = OFF_T1  + SZ_HALF;
constexpr size_t OFF_T3    = OFF_T2  + SZ_HALF;
constexpr size_t OFF_T4    = OFF_T3  + SZ_HALF;
constexpr size_t OFF_T5    = OFF_T4  + SZ_HALF;
constexpr size_t OFF_POOL  = OFF_T5  + SZ_HALF;
constexpr size_t OFF_MM    = OFF_POOL  + (size_t)B_ * 36 * C2_;
constexpr size_t OFF_SMALL = OFF_MM    + (size_t)B_ * 36 * CH_;
constexpr size_t OFF_PMAX  = OFF_SMALL + (size_t)B_ * CH_ * 36;
constexpr size_t OFF_PSUM  = OFF_PMAX  + (size_t)B_ * NH_ * 36 * SPLIT_;
constexpr size_t OFF_PACC  = OFF_PSUM  + (size_t)B_ * NH_ * 36 * SPLIT_;
// transposed+tf32-rounded weights, [N][K] layout
constexpr size_t OFF_WL    = OFF_PACC  + (size_t)B_ * NH_ * 36 * SPLIT_ * D_;
constexpr size_t OFF_WKV   = OFF_WL    + 256 * 256;
constexpr size_t OFF_WQEF  = OFF_WKV   + 256 * 256;
constexpr size_t OFF_WEB   = OFF_WQEF  + 256 * 256;
constexpr size_t OFF_WPROJ = OFF_WEB   + 128 * 128;
constexpr size_t OFF_BQEF  = OFF_WPROJ + 512 * 384;
constexpr size_t OFF_BPROJ = OFF_BQEF  + 256;
constexpr size_t SCRATCH_TOTAL = OFF_BPROJ + 512;
}  // namespace

__device__ float g_scratch[SCRATCH_TOTAL];

// ---------------------------------------------------------------------------
// helpers
// ---------------------------------------------------------------------------
__device__ __forceinline__ float to_tf32(float x) {
    float r;
    asm("cvt.rna.tf32.f32 %0, %1;" : "=f"(r) : "f"(x));
    return r;
}
__device__ __forceinline__ void ldsm4(uint32_t& r0, uint32_t& r1, uint32_t& r2,
                                      uint32_t& r3, uint32_t addr) {
    asm volatile("ldmatrix.sync.aligned.m8n8.x4.shared.b16 {%0,%1,%2,%3}, [%4];"
                 : "=r"(r0), "=r"(r1), "=r"(r2), "=r"(r3) : "r"(addr));
}
__device__ __forceinline__ void cp_async16(uint32_t dst, const void* src) {
    asm volatile("cp.async.ca.shared.global [%0], [%1], 16;" :: "r"(dst), "l"(src));
}
__device__ __forceinline__ void cp_commit() {
    asm volatile("cp.async.commit_group;");
}
template <int N>
__device__ __forceinline__ void cp_wait() {
    asm volatile("cp.async.wait_group %0;" :: "n"(N));
}

// ---------------------------------------------------------------------------
// 0) weight transpose + tf32 rounding (one-time per replay, tiny)
// ---------------------------------------------------------------------------
__global__ void tr_round(const float* __restrict__ W, float* __restrict__ Wt,
                         int K, int N)
{
    int i = blockIdx.x * 256 + threadIdx.x;
    if (i >= K * N) return;
    int k = i / N, n = i - k * N;
    Wt[(size_t)n * K + k] = to_tf32(W[i]);
}
// fuse two [K][Nh] weights into Wt[(2*Nh)][K]
__global__ void tr_round2(const float* __restrict__ W1, const float* __restrict__ W2,
                          float* __restrict__ Wt, int K, int Nh)
{
    int i = blockIdx.x * 256 + threadIdx.x;
    if (i >= K * 2 * Nh) return;
    int k = i / (2 * Nh), n = i - k * (2 * Nh);
    float v = (n < Nh) ? W1[k * Nh + n] : W2[k * Nh + (n - Nh)];
    Wt[(size_t)n * K + k] = to_tf32(v);
}
__global__ void pack_bias(const float* __restrict__ qb, const float* __restrict__ efb,
                          const float* __restrict__ pb, const float* __restrict__ peb,
                          float* __restrict__ bqef, float* __restrict__ bproj)
{
    int i = blockIdx.x * 256 + threadIdx.x;
    if (i < 256) bqef[i] = (i < 128) ? qb[i] : efb[i - 128];
    if (i < 512) bproj[i] = (i < 256) ? pb[i] : peb[i - 256];
}

// ---------------------------------------------------------------------------
// 1) LayerNorm over channels with NCHW -> (B*HW, C) transpose
// ---------------------------------------------------------------------------
__global__ void ln_kernel(const float* __restrict__ x, const float* __restrict__ gw,
                          const float* __restrict__ gb, float* __restrict__ out)
{
    __shared__ float s[256][33];
    __shared__ float sw[256], sb[256];
    int tid  = threadIdx.x;
    int b    = blockIdx.y;
    int pos0 = blockIdx.x * 32;
    sw[tid] = gw[tid];
    sb[tid] = gb[tid];
    int px = tid & 31, cg = tid >> 5;
    int p  = pos0 + px;
    const float* xb = x + (size_t)b * C_ * HW_;
    bool valid = (p < HW_);
    for (int c = cg; c < 256; c += 8)
        s[c][px] = valid ? xb[(size_t)c * HW_ + p] : 0.f;
    __syncthreads();
    int warp = tid >> 5, lane = tid & 31;
    #pragma unroll
    for (int pi = 0; pi < 4; ++pi) {
        int pp = warp * 4 + pi;
        int gp = pos0 + pp;
        if (gp >= HW_) continue;
        float sum = 0.f, sum2 = 0.f;
        #pragma unroll
        for (int jj = 0; jj < 8; ++jj) {
            float v = s[lane + jj * 32][pp];
            sum += v; sum2 += v * v;
        }
        #pragma unroll
        for (int o = 16; o > 0; o >>= 1) {
            sum  += __shfl_xor_sync(0xffffffffu, sum,  o);
            sum2 += __shfl_xor_sync(0xffffffffu, sum2, o);
        }
        float mean = sum * (1.f / 256.f);
        float var  = fmaxf(sum2 * (1.f / 256.f) - mean * mean, 0.f);
        float rstd = rsqrtf(var + 1e-6f);
        float* orow = out + (size_t)(b * HW_ + gp) * 256;
        #pragma unroll
        for (int jj = 0; jj < 8; ++jj) {
            int c = lane + jj * 32;
            orow[c] = (s[c][pp] - mean) * rstd * sw[c] + sb[c];
        }
    }
}

// ---------------------------------------------------------------------------
// 2a) TF32 tensor-core GEMM.
//     A[M][K] fp32, rna-rounded in register staging (2-stage ring).
//     Wt[N][K] pre-rounded tf32, staged via cp.async (3-stage ring).
//     BM=128 BN=128 BK=16, 256 threads (8 warps 2Mx4N, warp tile 64x32).
//     Smem [row][k0..15], 16B-chunk XOR swizzle (chunk ^= (row>>1)&3).
//     Requires M%128==0, N%128==0, K%16==0.
//     EPI 0: plain (ldc,coloff)       EPI 1: exact GELU
//     EPI 2: *aux then (ldc,coloff)   EPI 4: dual NCHW split at col 256
//     EPI 5: dual plain split at col 128
// ---------------------------------------------------------------------------
template <int EPI>
__global__ __launch_bounds__(256, 2)
void tgemm(const float* __restrict__ A, const float* __restrict__ Wt,
           const float* __restrict__ bias, const float* __restrict__ aux,
           float* __restrict__ Cout, float* __restrict__ Cout2,
           int M, int N, int K, int ldc, int coloff)
{
    __shared__ float As[2][128 * 16];
    __shared__ float Bs[3][128 * 16];
    const int tid = threadIdx.x;
    const int bm = blockIdx.y * 128;
    const int bn = blockIdx.x * 128;
    const int lane = tid & 31, wid = tid >> 5;
    const int wm = (wid & 1) * 64, wn = (wid >> 1) * 32;
    const int g = lane >> 2, tig = lane & 3;

    float acc[4][4][4] = {};

    uint32_t sA = (uint32_t)__cvta_generic_to_shared(&As[0][0]);
    uint32_t sB = (uint32_t)__cvta_generic_to_shared(&Bs[0][0]);

    // ldmatrix fragment base addresses (buffer 0, k8 block 0); k8=1 -> ^32B
    uint32_t aAddr[4], bAddr[2];
    {
        int rsel = ((lane >> 3) & 1) * 8 + (lane & 7);
        int csel = lane >> 4;
        #pragma unroll
        for (int mt = 0; mt < 4; ++mt) {
            int row = wm + mt * 16 + rsel;
            int c = csel ^ ((row >> 1) & 3);
            aAddr[mt] = sA + (uint32_t)(row * 16 + 4 * c) * 4u;
        }
        int m = lane >> 3;
        int nrsel = (m >> 1) * 8 + (lane & 7);
        int ncsel = m & 1;
        #pragma unroll
        for (int np = 0; np < 2; ++np) {
            int row = wn + np * 16 + nrsel;
            int c = ncsel ^ ((row >> 1) & 3);
            bAddr[np] = sB + (uint32_t)(row * 16 + 4 * c) * 4u;
        }
    }

    // staging maps: each thread handles 2 16B chunks for A and 2 for B
    const int aRow = tid >> 2;           // 0..63
    const int aK   = (tid & 3) << 2;     // 0,4,8,12
    const int ar1  = aRow + 64;
    const int st0  = aRow * 16 + 4 * ((aK >> 2) ^ ((aRow >> 1) & 3));
    const int st1  = ar1 * 16 + 4 * ((aK >> 2) ^ ((ar1 >> 1) & 3));
    const float* agp0 = A  + (size_t)(bm + aRow) * K + aK;
    const float* agp1 = agp0 + (size_t)64 * K;
    const float* bgp0 = Wt + (size_t)(bn + aRow) * K + aK;
    const float* bgp1 = bgp0 + (size_t)64 * K;
    const uint32_t dB0 = sB + (uint32_t)st0 * 4u;
    const uint32_t dB1 = sB + (uint32_t)st1 * 4u;

    float ar0v[4], ar1v[4];
    auto gloadA = [&](int s) {
        float4 v0 = *reinterpret_cast<const float4*>(agp0 + s * 16);
        float4 v1 = *reinterpret_cast<const float4*>(agp1 + s * 16);
        ar0v[0] = v0.x; ar0v[1] = v0.y; ar0v[2] = v0.z; ar0v[3] = v0.w;
        ar1v[0] = v1.x; ar1v[1] = v1.y; ar1v[2] = v1.z; ar1v[3] = v1.w;
    };
    auto storeA = [&](int buf) {
        float* a = As[buf];
        *reinterpret_cast<float4*>(&a[st0]) =
            make_float4(to_tf32(ar0v[0]), to_tf32(ar0v[1]), to_tf32(ar0v[2]), to_tf32(ar0v[3]));
        *reinterpret_cast<float4*>(&a[st1]) =
            make_float4(to_tf32(ar1v[0]), to_tf32(ar1v[1]), to_tf32(ar1v[2]), to_tf32(ar1v[3]));
    };
    auto issueB = [&](int s, int buf) {
        uint32_t off = (uint32_t)buf * 8192u;
        cp_async16(dB0 + off, bgp0 + s * 16);
        cp_async16(dB1 + off, bgp1 + s * 16);
    };
    auto compute = [&](int ab, int bb) {
        uint32_t ao = (uint32_t)ab * 8192u;
        uint32_t bo = (uint32_t)bb * 8192u;
        #pragma unroll
        for (int kb2 = 0; kb2 < 2; ++kb2) {
            uint32_t kx = kb2 ? 32u : 0u;
            uint32_t a_[4][4], b_[4][2];
            #pragma unroll
            for (int mt = 0; mt < 4; ++mt)
                ldsm4(a_[mt][0], a_[mt][1], a_[mt][2], a_[mt][3],
                      (aAddr[mt] + ao) ^ kx);
            ldsm4(b_[0][0], b_[0][1], b_[1][0], b_[1][1], (bAddr[0] + bo) ^ kx);
            ldsm4(b_[2][0], b_[2][1], b_[3][0], b_[3][1], (bAddr[1] + bo) ^ kx);
            #pragma unroll
            for (int mt = 0; mt < 4; ++mt)
                #pragma unroll
                for (int nt = 0; nt < 4; ++nt) {
                    asm volatile(
                        "mma.sync.aligned.m16n8k8.row.col.f32.tf32.tf32.f32 "
                        "{%0,%1,%2,%3}, {%4,%5,%6,%7}, {%8,%9}, {%0,%1,%2,%3};\n"
                        : "+f"(acc[mt][nt][0]), "+f"(acc[mt][nt][1]),
                          "+f"(acc[mt][nt][2]), "+f"(acc[mt][nt][3])
                        : "r"(a_[mt][0]), "r"(a_[mt][1]), "r"(a_[mt][2]), "r"(a_[mt][3]),
                          "r"(b_[nt][0]), "r"(b_[nt][1]));
                }
        }
    };

    const int nsteps = K >> 4;   // >= 8 for all our shapes
    issueB(0, 0); cp_commit();
    issueB(1, 1); cp_commit();
    gloadA(0); storeA(0);
    cp_wait<1>();
    __syncthreads();
    for (int s = 0; s < nsteps; ++s) {
        if (s + 1 < nsteps) gloadA(s + 1);
        compute(s & 1, s % 3);
        if (s + 1 < nsteps) storeA((s + 1) & 1);
        if (s + 2 < nsteps) issueB(s + 2, (s + 2) % 3);
        cp_commit();
        cp_wait<1>();
        __syncthreads();
    }

    // epilogue
    #pragma unroll
    for (int mt = 0; mt < 4; ++mt) {
        int row0 = bm + wm + mt * 16 + g;
        #pragma unroll
        for (int rr = 0; rr < 2; ++rr) {
            int row = row0 + rr * 8;
            int bb = row / HW_;
            int pp = row - bb * HW_;
            #pragma unroll
            for (int nt = 0; nt < 4; ++nt) {
                #pragma unroll
                for (int cc = 0; cc < 2; ++cc) {
                    int col = bn + wn + nt * 8 + 2 * tig + cc;
                    float v = acc[mt][nt][rr * 2 + cc] + bias[col];
                    if (EPI == 1) v = 0.5f * v * (1.f + erff(v * 0.70710678f));
                    if (EPI == 2) v *= aux[(size_t)row * 128 + col];
                    if (EPI == 4) {
                        float* tgt = (col < 256) ? Cout : Cout2;
                        tgt[(size_t)(bb * 256 + (col & 255)) * HW_ + pp] = v;
                    } else if (EPI == 5) {
                        if (col < 128) Cout[(size_t)row * 128 + col] = v;
                        else           Cout2[(size_t)row * 128 + (col - 128)] = v;
                    } else {
                        Cout[(size_t)row * ldc + coloff + col] = v;
                    }
                }
            }
        }
    }
}

// ---------------------------------------------------------------------------
// 2b) Small FFMA SGEMM (288-row pooled GEMM only; W is [K][N] original)
// ---------------------------------------------------------------------------
__global__ __launch_bounds__(256)
void sgemm_small(const float* __restrict__ A, const float* __restrict__ Wm,
                 const float* __restrict__ bias, float* __restrict__ Cout,
                 int M, int N, int K)
{
    __shared__ float As[16][132];
    __shared__ float Ws[16][64];
    int tid = threadIdx.x;
    int bm = blockIdx.y * 128;
    int bn = blockIdx.x * 64;
    int tx = tid & 15, ty = tid >> 4;
    float acc[8][4];
    #pragma unroll
    for (int i = 0; i < 8; ++i)
        #pragma unroll
        for (int j = 0; j < 4; ++j) acc[i][j] = 0.f;
    int aRow = tid >> 2;
    int aK   = (tid & 3) << 2;
    int wRow = tid >> 4;
    int wCol = (tid & 15) << 2;
    for (int k0 = 0; k0 < K; k0 += 16) {
        #pragma unroll
        for (int r = 0; r < 2; ++r) {
            int row = bm + aRow + r * 64;
            float4 v = make_float4(0.f, 0.f, 0.f, 0.f);
            if (row < M)
                v = *reinterpret_cast<const float4*>(A + (size_t)row * K + k0 + aK);
            As[aK + 0][aRow + r * 64] = v.x;
            As[aK + 1][aRow + r * 64] = v.y;
            As[aK + 2][aRow + r * 64] = v.z;
            As[aK + 3][aRow + r * 64] = v.w;
        }
        *reinterpret_cast<float4*>(&Ws[wRow][wCol]) =
            *reinterpret_cast<const float4*>(Wm + (size_t)(k0 + wRow) * N + bn + wCol);
        __syncthreads();
        #pragma unroll
        for (int kk = 0; kk < 16; ++kk) {
            float a[8], bf[4];
            #pragma unroll
            for (int i = 0; i < 8; ++i) a[i] = As[kk][ty * 8 + i];
            #pragma unroll
            for (int j = 0; j < 4; ++j) bf[j] = Ws[kk][tx * 4 + j];
            #pragma unroll
            for (int i = 0; i < 8; ++i)
                #pragma unroll
                for (int j = 0; j < 4; ++j)
                    acc[i][j] = fmaf(a[i], bf[j], acc[i][j]);
        }
        __syncthreads();
    }
    #pragma unroll
    for (int i = 0; i < 8; ++i) {
        int row = bm + ty * 8 + i;
        if (row >= M) continue;
        #pragma unroll
        for (int j = 0; j < 4; ++j) {
            int col = bn + tx * 4 + j;
            Cout[(size_t)row * N + col] = acc[i][j] + bias[col];
        }
    }
}

// ---------------------------------------------------------------------------
// 3) AdaptiveAvgPool2d((6,6)) on cat(xc, xec)
// ---------------------------------------------------------------------------
__global__ void pool_kernel(const float* __restrict__ xc, const float* __restrict__ xec,
                            float* __restrict__ pooled)
{
    int b = blockIdx.y, q = blockIdx.x;
    int qy = q / 6, qx = q - qy * 6;
    int c  = threadIdx.x;
    const float* src = (c < 256) ? xc : xec;
    int cc = c & 255;
    size_t base = (size_t)b * HW_;
    float acc = 0.f;
    for (int i = 0; i < 22; ++i) {
        size_t rowp = base + (size_t)((qy * 22 + i) * 132 + qx * 22);
        for (int j = 0; j < 22; ++j)
            acc += src[(rowp + j) * 256 + cc];
    }
    pooled[(size_t)(b * 36 + q) * 512 + c] = acc * (1.f / 484.f);
}

// ---------------------------------------------------------------------------
// 4) Attention (online softmax, split over keys) + combine
// ---------------------------------------------------------------------------
__global__ __launch_bounds__(288)
void attn_partial(const float* __restrict__ kv, const float* __restrict__ mq_all,
                  float* __restrict__ pmax, float* __restrict__ psum,
                  float* __restrict__ pacc)
{
    __shared__ float ks[CHUNK_][17];
    __shared__ float vs[CHUNK_][17];
    int b = blockIdx.z, head = blockIdx.y, sp = blockIdx.x;
    int tid = threadIdx.x;
    int q = tid >> 3, j = tid & 7;
    float mq[16];
    #pragma unroll
    for (int d = 0; d < 16; ++d)
        mq[d] = mq_all[(size_t)(b * 36 + q) * 128 + head * 16 + d] * 0.25f;
    float mx = -INFINITY, sm = 0.f;
    float acc[16];
    #pragma unroll
    for (int d = 0; d < 16; ++d) acc[d] = 0.f;
    int kb = sp * KPS_;
    for (int c0 = 0; c0 < NCHUNK_; ++c0) {
        int pos0 = kb + c0 * CHUNK_;
        for (int idx = tid; idx < CHUNK_ * 16; idx += 288) {
            int key = idx >> 4, d = idx & 15;
            size_t base = ((size_t)b * HW_ + pos0 + key) * 256 + head * 16 + d;
            ks[key][d] = kv[base];
            vs[key][d] = kv[base + 128];
        }
        __syncthreads();
        for (int key = j; key < CHUNK_; key += 8) {
            float s = 0.f;
            #pragma unroll
            for (int d = 0; d < 16; ++d) s = fmaf(mq[d], ks[key][d], s);
            if (s <= mx) {
                float p = __expf(s - mx);
                sm += p;
                #pragma unroll
                for (int d = 0; d < 16; ++d) acc[d] = fmaf(p, vs[key][d], acc[d]);
            } else {
                float cr = __expf(mx - s);
                sm = fmaf(sm, cr, 1.f);
                #pragma unroll
                for (int d = 0; d < 16; ++d) acc[d] = fmaf(acc[d], cr, vs[key][d]);
                mx = s;
            }
        }
        __syncthreads();
    }
    #pragma unroll
    for (int o = 4; o > 0; o >>= 1) {
        float omx = __shfl_xor_sync(0xffffffffu, mx, o);
        float osm = __shfl_xor_sync(0xffffffffu, sm, o);
        float nm = fmaxf(mx, omx);
        float c1 = __expf(mx - nm), c2 = __expf(omx - nm);
        sm = sm * c1 + osm * c2;
        #pragma unroll
        for (int d = 0; d < 16; ++d) {
            float oa = __shfl_xor_sync(0xffffffffu, acc[d], o);
            acc[d] = acc[d] * c1 + oa * c2;
        }
        mx = nm;
    }
    int pi = (b * NH_ + head) * 36 + q;
    if (j == 0) {
        pmax[pi * SPLIT_ + sp] = mx;
        psum[pi * SPLIT_ + sp] = sm;
        #pragma unroll
        for (int d = 0; d < 16; ++d)
            pacc[((size_t)pi * SPLIT_ + sp) * 16 + d] = acc[d];
    }
}

__global__ void attn_combine(const float* __restrict__ pmax, const float* __restrict__ psum,
                             const float* __restrict__ pacc, float* __restrict__ sm_out)
{
    int idx = blockIdx.x * blockDim.x + threadIdx.x;
    if (idx >= B_ * NH_ * 36 * 16) return;
    int d  = idx & 15;
    int q  = (idx >> 4) % 36;
    int bh = idx / (16 * 36);
    int pi = bh * 36 + q;
    float gm = -INFINITY;
    #pragma unroll
    for (int s = 0; s < SPLIT_; ++s) gm = fmaxf(gm, pmax[pi * SPLIT_ + s]);
    float ts = 0.f, tv = 0.f;
    #pragma unroll
    for (int s = 0; s < SPLIT_; ++s) {
        float c = __expf(pmax[pi * SPLIT_ + s] - gm);
        ts += c * psum[pi * SPLIT_ + s];
        tv += c * pacc[((size_t)pi * SPLIT_ + s) * 16 + d];
    }
    int b = bh >> 3, head = bh & 7;
    sm_out[(size_t)(b * 128 + head * 16 + d) * 36 + q] = tv / ts;
}

// ---------------------------------------------------------------------------
// 5) Bilinear upsample (B,128,6,6) -> cat[:, 0:128]
// ---------------------------------------------------------------------------
__global__ void upsample_kernel(const float* __restrict__ sm_in, float* __restrict__ cat)
{
    __shared__ float s[36][128];
    int b = blockIdx.y;
    for (int idx = threadIdx.x; idx < 36 * 128; idx += 128) {
        int q = idx >> 7, ch = idx & 127;
        s[q][ch] = sm_in[(size_t)(b * 128 + ch) * 36 + q];
    }
    __syncthreads();
    int ch = threadIdx.x;
    int p0 = blockIdx.x * 64;
    for (int k = 0; k < 64; ++k) {
        int p = p0 + k;
        if (p >= HW_) return;
        int h = p / 132, w = p - h * 132;
        float sy = (h + 0.5f) * (1.f / 22.f) - 0.5f;
        float sx = (w + 0.5f) * (1.f / 22.f) - 0.5f;
        float fy0 = floorf(sy), fx0 = floorf(sx);
        float fy = sy - fy0, fx = sx - fx0;
        int y0 = (int)fy0, x0 = (int)fx0;
        int y1 = min(y0 + 1, 5), x1 = min(x0 + 1, 5);
        y0 = max(y0, 0); x0 = max(x0, 0);
        float v00 = s[y0 * 6 + x0][ch], v01 = s[y0 * 6 + x1][ch];
        float v10 = s[y1 * 6 + x0][ch], v11 = s[y1 * 6 + x1][ch];
        float v = (1.f - fy) * ((1.f - fx) * v00 + fx * v01)
                + fy * ((1.f - fx) * v10 + fx * v11);
        cat[((size_t)b * HW_ + p) * 384 + ch] = v;
    }
}

// ---------------------------------------------------------------------------
// 6) Depthwise 7x7 conv, NHWC channels-inner
// ---------------------------------------------------------------------------
__global__ __launch_bounds__(256)
void dwconv_kernel(const float* __restrict__ in, const float* __restrict__ wgt,
                   const float* __restrict__ cbias, float* __restrict__ out)
{
    __shared__ float s[10][22][32];
    __shared__ float wsm[32][49];
    int wt = blockIdx.x, ht = blockIdx.y;
    int bz = blockIdx.z;
    int b = bz >> 2, cg = bz & 3;
    int h0 = ht * 4, w0 = wt * 16;
    int tid = threadIdx.x;
    for (int idx = tid; idx < 32 * 49; idx += 256) {
        int ch = idx / 49, t = idx - ch * 49;
        wsm[ch][t] = wgt[(cg * 32 + ch) * 49 + t];
    }
    const float* inb = in + (size_t)b * HW_ * 128;
    for (int idx = tid; idx < 10 * 22 * 32; idx += 256) {
        int ch = idx & 31;
        int r  = idx >> 5;
        int lw = r % 22, lh = r / 22;
        int gh = h0 - 3 + lh, gw = w0 - 3 + lw;
        float v = 0.f;
        if (gh >= 0 && gh < 132 && gw >= 0 && gw < 132)
            v = inb[(size_t)(gh * 132 + gw) * 128 + cg * 32 + ch];
        s[lh][lw][ch] = v;
    }
    __syncthreads();
    int ch = tid & 31;
    int pg = tid >> 5;
    float acc[8];
    #pragma unroll
    for (int i = 0; i < 8; ++i) acc[i] = 0.f;
    #pragma unroll
    for (int dy = 0; dy < 7; ++dy)
        #pragma unroll
        for (int dx = 0; dx < 7; ++dx) {
            float wv = wsm[ch][dy * 7 + dx];
            #pragma unroll
            for (int pi = 0; pi < 8; ++pi) {
                int posid = pg + pi * 8;
                int lh = posid >> 4, lw = posid & 15;
                acc[pi] = fmaf(wv, s[lh + dy][lw + dx][ch], acc[pi]);
            }
        }
    float bv = cbias[cg * 32 + ch];
    #pragma unroll
    for (int pi = 0; pi < 8; ++pi) {
        int posid = pg + pi * 8;
        int lh = posid >> 4, lw = posid & 15;
        int gw = w0 + lw;
        if (gw < 132)
            out[((size_t)b * HW_ + (h0 + lh) * 132 + gw) * 128 + cg * 32 + ch]
                = acc[pi] + bv;
    }
}

// ---------------------------------------------------------------------------
// Launcher
// ---------------------------------------------------------------------------
extern "C" void kernel_launch(void* const* d_in, const int* in_sizes, int n_in,
                              void* d_out, int out_size)
{
    (void)in_sizes; (void)n_in; (void)out_size;
    const float* x       = (const float*)d_in[0];
    const float* x_e     = (const float*)d_in[1];
    const float* norm_w  = (const float*)d_in[2];
    const float* norm_b  = (const float*)d_in[3];
    const float* norme_w = (const float*)d_in[4];
    const float* norme_b = (const float*)d_in[5];
    const float* l_w     = (const float*)d_in[6];
    const float* l_b     = (const float*)d_in[7];
    const float* kv_w    = (const float*)d_in[8];
    const float* kv_b    = (const float*)d_in[9];
    const float* xe_w    = (const float*)d_in[10];
    const float* xe_b    = (const float*)d_in[11];
    const float* q_w     = (const float*)d_in[12];
    const float* q_b     = (const float*)d_in[13];
    const float* ef_w    = (const float*)d_in[14];
    const float* ef_b    = (const float*)d_in[15];
    const float* ec_w    = (const float*)d_in[16];
    const float* ec_b    = (const float*)d_in[17];
    const float* eb_w    = (const float*)d_in[18];
    const float* eb_b    = (const float*)d_in[19];
    const float* proj_w  = (const float*)d_in[20];
    const float* proj_b  = (const float*)d_in[21];
    const float* proje_w = (const float*)d_in[22];
    const float* proje_b = (const float*)d_in[23];

    float* base = nullptr;
    cudaGetSymbolAddress((void**)&base, g_scratch);
    float* xc    = base + OFF_XC;
    float* xec   = base + OFF_XEC;
    float* xg    = base + OFF_XG;
    float* kvb   = base + OFF_KV;
    float* cat   = base + OFF_CAT;
    float* t1    = base + OFF_T1;   // q (LFA1, from xc)
    float* t2    = base + OFF_T2;   // ef (LFA1, from xec)
    float* t3    = base + OFF_T3;   // conv output (shared)
    float* t4    = base + OFF_T4;   // q (LFA2, from xec)
    float* t5    = base + OFF_T5;   // ef (LFA2, from xc)
    float* pool  = base + OFF_POOL;
    float* mbuf  = base + OFF_MM;
    float* smalb = base + OFF_SMALL;
    float* pmax  = base + OFF_PMAX;
    float* psum  = base + OFF_PSUM;
    float* pacc  = base + OFF_PACC;
    float* wl_t   = base + OFF_WL;
    float* wkv_t  = base + OFF_WKV;
    float* wqef_t = base + OFF_WQEF;
    float* web_t  = base + OFF_WEB;
    float* wproj_t= base + OFF_WPROJ;
    float* bqef  = base + OFF_BQEF;
    float* bproj = base + OFF_BPROJ;

    float* outp = (float*)d_out;
    float* oute = outp + SZ_BIG;

    // one-time weight transforms (cheap; part of the graph)
    tr_round <<<(256 * 256 + 255) / 256, 256>>>(l_w,  wl_t,  256, 256);
    tr_round <<<(256 * 256 + 255) / 256, 256>>>(kv_w, wkv_t, 256, 256);
    tr_round <<<(128 * 128 + 255) / 256, 256>>>(eb_w, web_t, 128, 128);
    tr_round2<<<(256 * 256 + 255) / 256, 256>>>(q_w, ef_w, wqef_t, 256, 128);
    tr_round2<<<(384 * 512 + 255) / 256, 256>>>(proj_w, proje_w, wproj_t, 384, 256);
    pack_bias<<<2, 256>>>(q_b, ef_b, proj_b, proje_b, bqef, bproj);

    dim3 lnG((HW_ + 31) / 32, B_);
    ln_kernel<<<lnG, 256>>>(x,   norm_w,  norm_b,  xc);
    ln_kernel<<<lnG, 256>>>(x_e, norme_w, norme_b, xec);

    // GFA: xg = gelu(xc @ l_w + l_b); kv = xg @ kv_w + kv_b
    tgemm<1><<<dim3(2, 1089), 256>>>(xc, wl_t,  l_b,  nullptr, xg,  nullptr, M_, 256, 256, 256, 0);
    tgemm<0><<<dim3(2, 1089), 256>>>(xg, wkv_t, kv_b, nullptr, kvb, nullptr, M_, 256, 256, 256, 0);

    pool_kernel<<<dim3(36, B_), 512>>>(xc, xec, pool);
    sgemm_small<<<dim3(2, 3), 256>>>(pool, xe_w, xe_b, mbuf, B_ * 36, 128, 512);

    attn_partial<<<dim3(SPLIT_, NH_, B_), 288>>>(kvb, mbuf, pmax, psum, pacc);
    attn_combine<<<(B_ * NH_ * 36 * 16 + 255) / 256, 256>>>(pmax, psum, pacc, smalb);
    upsample_kernel<<<dim3((HW_ + 63) / 64, B_), 128>>>(smalb, cat);  // cat[:,0:128]

    // fused q|ef GEMMs (one per input)
    tgemm<5><<<dim3(2, 1089), 256>>>(xc,  wqef_t, bqef, nullptr, t1, t5, M_, 256, 256, 0, 0);
    tgemm<5><<<dim3(2, 1089), 256>>>(xec, wqef_t, bqef, nullptr, t4, t2, M_, 256, 256, 0, 0);

    // LFA 1: conv(ef from xec), eb GEMM * q(xc) -> cat[:,128:256]
    dwconv_kernel<<<dim3(9, 33, B_ * 4), 256>>>(t2, ec_w, ec_b, t3);
    tgemm<2><<<dim3(1, 1089), 256>>>(t3, web_t, eb_b, t1, cat, nullptr, M_, 128, 128, 384, 128);

    // LFA 2: conv(ef from xc), eb GEMM * q(xec) -> cat[:,256:384]
    dwconv_kernel<<<dim3(9, 33, B_ * 4), 256>>>(t5, ec_w, ec_b, t3);
    tgemm<2><<<dim3(1, 1089), 256>>>(t3, web_t, eb_b, t4, cat, nullptr, M_, 128, 128, 384, 256);

    // fused projections, NCHW outputs split at col 256
    tgemm<4><<<dim3(4, 1089), 256>>>(cat, wproj_t, bproj, nullptr, outp, oute, M_, 512, 384, 0, 0);
}

// round 9
// speedup vs baseline: 2.2301x; 1.0337x over previous
#include <cuda_runtime.h>
#include <math.h>
#include <stdint.h>

// ---------------------------------------------------------------------------
// Problem constants
// ---------------------------------------------------------------------------
namespace {
constexpr int B_ = 8, C_ = 256, H_ = 132, W_ = 132, NH_ = 8, D_ = 16;
constexpr int HW_ = H_ * W_;          // 17424
constexpr int M_  = B_ * HW_;         // 139392  (== 1089 * 128 exactly)
constexpr int CH_ = 128;              // C/2
constexpr int C2_ = 512;              // 2C
constexpr int C3_ = 384;              // 3C/2
constexpr int SPLIT_  = 8;
constexpr int KPS_    = HW_ / SPLIT_; // 2178 keys per split
constexpr int CHUNK_  = 66;           // keys per smem chunk (2178 = 33*66)
constexpr int NCHUNK_ = KPS_ / CHUNK_;

constexpr size_t SZ_BIG  = (size_t)M_ * C_;
constexpr size_t SZ_CAT  = (size_t)M_ * C3_;
constexpr size_t SZ_HALF = (size_t)M_ * CH_;

constexpr size_t OFF_XC    = 0;
constexpr size_t OFF_XEC   = OFF_XC  + SZ_BIG;
constexpr size_t OFF_XG    = OFF_XEC + SZ_BIG;
constexpr size_t OFF_KV    = OFF_XG  + SZ_BIG;
constexpr size_t OFF_CAT   = OFF_KV  + SZ_BIG;
constexpr size_t OFF_T1    = OFF_CAT + SZ_CAT;
constexpr size_t OFF_T2    = OFF_T1  + SZ_HALF;
constexpr size_t OFF_T3    = OFF_T2  + SZ_HALF;
constexpr size_t OFF_T4    = OFF_T3  + SZ_HALF;
constexpr size_t OFF_T5    = OFF_T4  + SZ_HALF;
constexpr size_t OFF_POOL  = OFF_T5  + SZ_HALF;
constexpr size_t OFF_MM    = OFF_POOL  + (size_t)B_ * 36 * C2_;
constexpr size_t OFF_SMALL = OFF_MM    + (size_t)B_ * 36 * CH_;
constexpr size_t OFF_PMAX  = OFF_SMALL + (size_t)B_ * CH_ * 36;
constexpr size_t OFF_PSUM  = OFF_PMAX  + (size_t)B_ * NH_ * 36 * SPLIT_;
constexpr size_t OFF_PACC  = OFF_PSUM  + (size_t)B_ * NH_ * 36 * SPLIT_;
// transposed+tf32-rounded weights, [N][K] layout
constexpr size_t OFF_WL    = OFF_PACC  + (size_t)B_ * NH_ * 36 * SPLIT_ * D_;
constexpr size_t OFF_WKV   = OFF_WL    + 256 * 256;
constexpr size_t OFF_WQEF  = OFF_WKV   + 256 * 256;
constexpr size_t OFF_WEB   = OFF_WQEF  + 256 * 256;
constexpr size_t OFF_WPROJ = OFF_WEB   + 128 * 128;
constexpr size_t OFF_BQEF  = OFF_WPROJ + 512 * 384;
constexpr size_t OFF_BPROJ = OFF_BQEF  + 256;
constexpr size_t SCRATCH_TOTAL = OFF_BPROJ + 512;
}  // namespace

__device__ float g_scratch[SCRATCH_TOTAL];

// ---------------------------------------------------------------------------
// helpers
// ---------------------------------------------------------------------------
__device__ __forceinline__ float to_tf32(float x) {
    float r;
    asm("cvt.rna.tf32.f32 %0, %1;" : "=f"(r) : "f"(x));
    return r;
}
__device__ __forceinline__ void ldsm4(uint32_t& r0, uint32_t& r1, uint32_t& r2,
                                      uint32_t& r3, uint32_t addr) {
    asm volatile("ldmatrix.sync.aligned.m8n8.x4.shared.b16 {%0,%1,%2,%3}, [%4];"
                 : "=r"(r0), "=r"(r1), "=r"(r2), "=r"(r3) : "r"(addr));
}
__device__ __forceinline__ void cp_async16(uint32_t dst, const void* src) {
    asm volatile("cp.async.ca.shared.global [%0], [%1], 16;" :: "r"(dst), "l"(src));
}
__device__ __forceinline__ void cp_commit() {
    asm volatile("cp.async.commit_group;");
}
template <int N>
__device__ __forceinline__ void cp_wait() {
    asm volatile("cp.async.wait_group %0;" :: "n"(N));
}

// ---------------------------------------------------------------------------
// 0) weight transpose + tf32 rounding (one-time per replay, tiny)
// ---------------------------------------------------------------------------
__global__ void tr_round(const float* __restrict__ W, float* __restrict__ Wt,
                         int K, int N)
{
    int i = blockIdx.x * 256 + threadIdx.x;
    if (i >= K * N) return;
    int k = i / N, n = i - k * N;
    Wt[(size_t)n * K + k] = to_tf32(W[i]);
}
// fuse two [K][Nh] weights into Wt[(2*Nh)][K]
__global__ void tr_round2(const float* __restrict__ W1, const float* __restrict__ W2,
                          float* __restrict__ Wt, int K, int Nh)
{
    int i = blockIdx.x * 256 + threadIdx.x;
    if (i >= K * 2 * Nh) return;
    int k = i / (2 * Nh), n = i - k * (2 * Nh);
    float v = (n < Nh) ? W1[k * Nh + n] : W2[k * Nh + (n - Nh)];
    Wt[(size_t)n * K + k] = to_tf32(v);
}
__global__ void pack_bias(const float* __restrict__ qb, const float* __restrict__ efb,
                          const float* __restrict__ pb, const float* __restrict__ peb,
                          float* __restrict__ bqef, float* __restrict__ bproj)
{
    int i = blockIdx.x * 256 + threadIdx.x;
    if (i < 256) bqef[i] = (i < 128) ? qb[i] : efb[i - 128];
    if (i < 512) bproj[i] = (i < 256) ? pb[i] : peb[i - 256];
}

// ---------------------------------------------------------------------------
// 1) LayerNorm over channels, NCHW -> (B*HW, C); output tf32-rounded
//    (xc/xec are consumed as tf32 MMA operands; the pooled path averages
//     484 values so the per-element rounding washes out)
// ---------------------------------------------------------------------------
__global__ void ln_kernel(const float* __restrict__ x, const float* __restrict__ gw,
                          const float* __restrict__ gb, float* __restrict__ out)
{
    __shared__ float s[256][33];
    __shared__ float sw[256], sb[256];
    int tid  = threadIdx.x;
    int b    = blockIdx.y;
    int pos0 = blockIdx.x * 32;
    sw[tid] = gw[tid];
    sb[tid] = gb[tid];
    int px = tid & 31, cg = tid >> 5;
    int p  = pos0 + px;
    const float* xb = x + (size_t)b * C_ * HW_;
    bool valid = (p < HW_);
    for (int c = cg; c < 256; c += 8)
        s[c][px] = valid ? xb[(size_t)c * HW_ + p] : 0.f;
    __syncthreads();
    int warp = tid >> 5, lane = tid & 31;
    #pragma unroll
    for (int pi = 0; pi < 4; ++pi) {
        int pp = warp * 4 + pi;
        int gp = pos0 + pp;
        if (gp >= HW_) continue;
        float sum = 0.f, sum2 = 0.f;
        #pragma unroll
        for (int jj = 0; jj < 8; ++jj) {
            float v = s[lane + jj * 32][pp];
            sum += v; sum2 += v * v;
        }
        #pragma unroll
        for (int o = 16; o > 0; o >>= 1) {
            sum  += __shfl_xor_sync(0xffffffffu, sum,  o);
            sum2 += __shfl_xor_sync(0xffffffffu, sum2, o);
        }
        float mean = sum * (1.f / 256.f);
        float var  = fmaxf(sum2 * (1.f / 256.f) - mean * mean, 0.f);
        float rstd = rsqrtf(var + 1e-6f);
        float* orow = out + (size_t)(b * HW_ + gp) * 256;
        #pragma unroll
        for (int jj = 0; jj < 8; ++jj) {
            int c = lane + jj * 32;
            orow[c] = to_tf32((s[c][pp] - mean) * rstd * sw[c] + sb[c]);
        }
    }
}

// ---------------------------------------------------------------------------
// 2a) TF32 tensor-core GEMM, pure cp.async 3-stage pipeline + ldmatrix.
//     A[M][K]: values already tf32 (rna pre-rounded by producers) so the
//     hardware RZ conversion is exact. Wt[N][K] pre-rounded tf32.
//     BM=128 BN=128 BK=16, 256 threads (8 warps 2Mx4N, warp tile 64x32).
//     Smem [row][k0..15], 16B-chunk XOR swizzle (chunk ^= (row>>1)&3).
//     Requires M%128==0, N%128==0, K%16==0.
//     EPI 0: plain (ldc,coloff)              EPI 1: GELU, tf32-rounded out
//     EPI 2: *aux, tf32-rounded (ldc,coloff) EPI 4: dual NCHW split at 256
//     EPI 5: dual plain split at col 128
// ---------------------------------------------------------------------------
template <int EPI>
__global__ __launch_bounds__(256, 2)
void tgemm(const float* __restrict__ A, const float* __restrict__ Wt,
           const float* __restrict__ bias, const float* __restrict__ aux,
           float* __restrict__ Cout, float* __restrict__ Cout2,
           int M, int N, int K, int ldc, int coloff)
{
    __shared__ float As[3][128 * 16];
    __shared__ float Bs[3][128 * 16];
    const int tid = threadIdx.x;
    const int bm = blockIdx.y * 128;
    const int bn = blockIdx.x * 128;
    const int lane = tid & 31, wid = tid >> 5;
    const int wm = (wid & 1) * 64, wn = (wid >> 1) * 32;
    const int g = lane >> 2, tig = lane & 3;

    float acc[4][4][4] = {};

    uint32_t sA = (uint32_t)__cvta_generic_to_shared(&As[0][0]);
    uint32_t sB = (uint32_t)__cvta_generic_to_shared(&Bs[0][0]);

    // ldmatrix fragment base addresses (buffer 0, k8 block 0); k8=1 -> ^32B
    uint32_t aAddr[4], bAddr[2];
    {
        int rsel = ((lane >> 3) & 1) * 8 + (lane & 7);
        int csel = lane >> 4;
        #pragma unroll
        for (int mt = 0; mt < 4; ++mt) {
            int row = wm + mt * 16 + rsel;
            int c = csel ^ ((row >> 1) & 3);
            aAddr[mt] = sA + (uint32_t)(row * 16 + 4 * c) * 4u;
        }
        int m = lane >> 3;
        int nrsel = (m >> 1) * 8 + (lane & 7);
        int ncsel = m & 1;
        #pragma unroll
        for (int np = 0; np < 2; ++np) {
            int row = wn + np * 16 + nrsel;
            int c = ncsel ^ ((row >> 1) & 3);
            bAddr[np] = sB + (uint32_t)(row * 16 + 4 * c) * 4u;
        }
    }

    // cp.async staging map: each thread moves 2 A-chunks + 2 B-chunks per stage
    const int aRow = tid >> 2;           // 0..63
    const int aK   = (tid & 3) << 2;     // 0,4,8,12
    const int ar1  = aRow + 64;
    const int st0  = aRow * 16 + 4 * ((aK >> 2) ^ ((aRow >> 1) & 3));
    const int st1  = ar1 * 16 + 4 * ((aK >> 2) ^ ((ar1 >> 1) & 3));
    const float* agp0 = A  + (size_t)(bm + aRow) * K + aK;
    const float* agp1 = agp0 + (size_t)64 * K;
    const float* bgp0 = Wt + (size_t)(bn + aRow) * K + aK;
    const float* bgp1 = bgp0 + (size_t)64 * K;
    const uint32_t dA0 = sA + (uint32_t)st0 * 4u;
    const uint32_t dA1 = sA + (uint32_t)st1 * 4u;
    const uint32_t dB0 = sB + (uint32_t)st0 * 4u;
    const uint32_t dB1 = sB + (uint32_t)st1 * 4u;

    auto issue = [&](int s, int buf) {
        uint32_t off = (uint32_t)buf * 8192u;
        cp_async16(dA0 + off, agp0 + s * 16);
        cp_async16(dA1 + off, agp1 + s * 16);
        cp_async16(dB0 + off, bgp0 + s * 16);
        cp_async16(dB1 + off, bgp1 + s * 16);
    };
    auto compute = [&](int buf) {
        uint32_t bo = (uint32_t)buf * 8192u;
        #pragma unroll
        for (int kb2 = 0; kb2 < 2; ++kb2) {
            uint32_t kx = kb2 ? 32u : 0u;
            uint32_t a_[4][4], b_[4][2];
            #pragma unroll
            for (int mt = 0; mt < 4; ++mt)
                ldsm4(a_[mt][0], a_[mt][1], a_[mt][2], a_[mt][3],
                      (aAddr[mt] + bo) ^ kx);
            ldsm4(b_[0][0], b_[0][1], b_[1][0], b_[1][1], (bAddr[0] + bo) ^ kx);
            ldsm4(b_[2][0], b_[2][1], b_[3][0], b_[3][1], (bAddr[1] + bo) ^ kx);
            #pragma unroll
            for (int mt = 0; mt < 4; ++mt)
                #pragma unroll
                for (int nt = 0; nt < 4; ++nt) {
                    asm volatile(
                        "mma.sync.aligned.m16n8k8.row.col.f32.tf32.tf32.f32 "
                        "{%0,%1,%2,%3}, {%4,%5,%6,%7}, {%8,%9}, {%0,%1,%2,%3};\n"
                        : "+f"(acc[mt][nt][0]), "+f"(acc[mt][nt][1]),
                          "+f"(acc[mt][nt][2]), "+f"(acc[mt][nt][3])
                        : "r"(a_[mt][0]), "r"(a_[mt][1]), "r"(a_[mt][2]), "r"(a_[mt][3]),
                          "r"(b_[nt][0]), "r"(b_[nt][1]));
                }
        }
    };

    const int nsteps = K >> 4;   // >= 8 for all our shapes
    issue(0, 0); cp_commit();
    issue(1, 1); cp_commit();
    cp_wait<1>();
    __syncthreads();
    for (int s = 0; s < nsteps; ++s) {
        compute(s % 3);
        if (s + 2 < nsteps) issue(s + 2, (s + 2) % 3);
        cp_commit();
        cp_wait<1>();
        __syncthreads();
    }

    // epilogue
    #pragma unroll
    for (int mt = 0; mt < 4; ++mt) {
        int row0 = bm + wm + mt * 16 + g;
        #pragma unroll
        for (int rr = 0; rr < 2; ++rr) {
            int row = row0 + rr * 8;
            int bb = row / HW_;
            int pp = row - bb * HW_;
            #pragma unroll
            for (int nt = 0; nt < 4; ++nt) {
                #pragma unroll
                for (int cc = 0; cc < 2; ++cc) {
                    int col = bn + wn + nt * 8 + 2 * tig + cc;
                    float v = acc[mt][nt][rr * 2 + cc] + bias[col];
                    if (EPI == 1) v = to_tf32(0.5f * v * (1.f + erff(v * 0.70710678f)));
                    if (EPI == 2) v = to_tf32(v * aux[(size_t)row * 128 + col]);
                    if (EPI == 4) {
                        float* tgt = (col < 256) ? Cout : Cout2;
                        tgt[(size_t)(bb * 256 + (col & 255)) * HW_ + pp] = v;
                    } else if (EPI == 5) {
                        if (col < 128) Cout[(size_t)row * 128 + col] = v;
                        else           Cout2[(size_t)row * 128 + (col - 128)] = v;
                    } else {
                        Cout[(size_t)row * ldc + coloff + col] = v;
                    }
                }
            }
        }
    }
}

// ---------------------------------------------------------------------------
// 2b) Small FFMA SGEMM (288-row pooled GEMM only; W is [K][N] original)
// ---------------------------------------------------------------------------
__global__ __launch_bounds__(256)
void sgemm_small(const float* __restrict__ A, const float* __restrict__ Wm,
                 const float* __restrict__ bias, float* __restrict__ Cout,
                 int M, int N, int K)
{
    __shared__ float As[16][132];
    __shared__ float Ws[16][64];
    int tid = threadIdx.x;
    int bm = blockIdx.y * 128;
    int bn = blockIdx.x * 64;
    int tx = tid & 15, ty = tid >> 4;
    float acc[8][4];
    #pragma unroll
    for (int i = 0; i < 8; ++i)
        #pragma unroll
        for (int j = 0; j < 4; ++j) acc[i][j] = 0.f;
    int aRow = tid >> 2;
    int aK   = (tid & 3) << 2;
    int wRow = tid >> 4;
    int wCol = (tid & 15) << 2;
    for (int k0 = 0; k0 < K; k0 += 16) {
        #pragma unroll
        for (int r = 0; r < 2; ++r) {
            int row = bm + aRow + r * 64;
            float4 v = make_float4(0.f, 0.f, 0.f, 0.f);
            if (row < M)
                v = *reinterpret_cast<const float4*>(A + (size_t)row * K + k0 + aK);
            As[aK + 0][aRow + r * 64] = v.x;
            As[aK + 1][aRow + r * 64] = v.y;
            As[aK + 2][aRow + r * 64] = v.z;
            As[aK + 3][aRow + r * 64] = v.w;
        }
        *reinterpret_cast<float4*>(&Ws[wRow][wCol]) =
            *reinterpret_cast<const float4*>(Wm + (size_t)(k0 + wRow) * N + bn + wCol);
        __syncthreads();
        #pragma unroll
        for (int kk = 0; kk < 16; ++kk) {
            float a[8], bf[4];
            #pragma unroll
            for (int i = 0; i < 8; ++i) a[i] = As[kk][ty * 8 + i];
            #pragma unroll
            for (int j = 0; j < 4; ++j) bf[j] = Ws[kk][tx * 4 + j];
            #pragma unroll
            for (int i = 0; i < 8; ++i)
                #pragma unroll
                for (int j = 0; j < 4; ++j)
                    acc[i][j] = fmaf(a[i], bf[j], acc[i][j]);
        }
        __syncthreads();
    }
    #pragma unroll
    for (int i = 0; i < 8; ++i) {
        int row = bm + ty * 8 + i;
        if (row >= M) continue;
        #pragma unroll
        for (int j = 0; j < 4; ++j) {
            int col = bn + tx * 4 + j;
            Cout[(size_t)row * N + col] = acc[i][j] + bias[col];
        }
    }
}

// ---------------------------------------------------------------------------
// 3) AdaptiveAvgPool2d((6,6)) on cat(xc, xec)
// ---------------------------------------------------------------------------
__global__ void pool_kernel(const float* __restrict__ xc, const float* __restrict__ xec,
                            float* __restrict__ pooled)
{
    int b = blockIdx.y, q = blockIdx.x;
    int qy = q / 6, qx = q - qy * 6;
    int c  = threadIdx.x;
    const float* src = (c < 256) ? xc : xec;
    int cc = c & 255;
    size_t base = (size_t)b * HW_;
    float acc = 0.f;
    for (int i = 0; i < 22; ++i) {
        size_t rowp = base + (size_t)((qy * 22 + i) * 132 + qx * 22);
        for (int j = 0; j < 22; ++j)
            acc += src[(rowp + j) * 256 + cc];
    }
    pooled[(size_t)(b * 36 + q) * 512 + c] = acc * (1.f / 484.f);
}

// ---------------------------------------------------------------------------
// 4) Attention (online softmax, split over keys) + combine
// ---------------------------------------------------------------------------
__global__ __launch_bounds__(288)
void attn_partial(const float* __restrict__ kv, const float* __restrict__ mq_all,
                  float* __restrict__ pmax, float* __restrict__ psum,
                  float* __restrict__ pacc)
{
    __shared__ float ks[CHUNK_][17];
    __shared__ float vs[CHUNK_][17];
    int b = blockIdx.z, head = blockIdx.y, sp = blockIdx.x;
    int tid = threadIdx.x;
    int q = tid >> 3, j = tid & 7;
    float mq[16];
    #pragma unroll
    for (int d = 0; d < 16; ++d)
        mq[d] = mq_all[(size_t)(b * 36 + q) * 128 + head * 16 + d] * 0.25f;
    float mx = -INFINITY, sm = 0.f;
    float acc[16];
    #pragma unroll
    for (int d = 0; d < 16; ++d) acc[d] = 0.f;
    int kb = sp * KPS_;
    for (int c0 = 0; c0 < NCHUNK_; ++c0) {
        int pos0 = kb + c0 * CHUNK_;
        for (int idx = tid; idx < CHUNK_ * 16; idx += 288) {
            int key = idx >> 4, d = idx & 15;
            size_t base = ((size_t)b * HW_ + pos0 + key) * 256 + head * 16 + d;
            ks[key][d] = kv[base];
            vs[key][d] = kv[base + 128];
        }
        __syncthreads();
        for (int key = j; key < CHUNK_; key += 8) {
            float s = 0.f;
            #pragma unroll
            for (int d = 0; d < 16; ++d) s = fmaf(mq[d], ks[key][d], s);
            if (s <= mx) {
                float p = __expf(s - mx);
                sm += p;
                #pragma unroll
                for (int d = 0; d < 16; ++d) acc[d] = fmaf(p, vs[key][d], acc[d]);
            } else {
                float cr = __expf(mx - s);
                sm = fmaf(sm, cr, 1.f);
                #pragma unroll
                for (int d = 0; d < 16; ++d) acc[d] = fmaf(acc[d], cr, vs[key][d]);
                mx = s;
            }
        }
        __syncthreads();
    }
    #pragma unroll
    for (int o = 4; o > 0; o >>= 1) {
        float omx = __shfl_xor_sync(0xffffffffu, mx, o);
        float osm = __shfl_xor_sync(0xffffffffu, sm, o);
        float nm = fmaxf(mx, omx);
        float c1 = __expf(mx - nm), c2 = __expf(omx - nm);
        sm = sm * c1 + osm * c2;
        #pragma unroll
        for (int d = 0; d < 16; ++d) {
            float oa = __shfl_xor_sync(0xffffffffu, acc[d], o);
            acc[d] = acc[d] * c1 + oa * c2;
        }
        mx = nm;
    }
    int pi = (b * NH_ + head) * 36 + q;
    if (j == 0) {
        pmax[pi * SPLIT_ + sp] = mx;
        psum[pi * SPLIT_ + sp] = sm;
        #pragma unroll
        for (int d = 0; d < 16; ++d)
            pacc[((size_t)pi * SPLIT_ + sp) * 16 + d] = acc[d];
    }
}

__global__ void attn_combine(const float* __restrict__ pmax, const float* __restrict__ psum,
                             const float* __restrict__ pacc, float* __restrict__ sm_out)
{
    int idx = blockIdx.x * blockDim.x + threadIdx.x;
    if (idx >= B_ * NH_ * 36 * 16) return;
    int d  = idx & 15;
    int q  = (idx >> 4) % 36;
    int bh = idx / (16 * 36);
    int pi = bh * 36 + q;
    float gm = -INFINITY;
    #pragma unroll
    for (int s = 0; s < SPLIT_; ++s) gm = fmaxf(gm, pmax[pi * SPLIT_ + s]);
    float ts = 0.f, tv = 0.f;
    #pragma unroll
    for (int s = 0; s < SPLIT_; ++s) {
        float c = __expf(pmax[pi * SPLIT_ + s] - gm);
        ts += c * psum[pi * SPLIT_ + s];
        tv += c * pacc[((size_t)pi * SPLIT_ + s) * 16 + d];
    }
    int b = bh >> 3, head = bh & 7;
    sm_out[(size_t)(b * 128 + head * 16 + d) * 36 + q] = tv / ts;
}

// ---------------------------------------------------------------------------
// 5) Bilinear upsample (B,128,6,6) -> cat[:, 0:128], tf32-rounded
// ---------------------------------------------------------------------------
__global__ void upsample_kernel(const float* __restrict__ sm_in, float* __restrict__ cat)
{
    __shared__ float s[36][128];
    int b = blockIdx.y;
    for (int idx = threadIdx.x; idx < 36 * 128; idx += 128) {
        int q = idx >> 7, ch = idx & 127;
        s[q][ch] = sm_in[(size_t)(b * 128 + ch) * 36 + q];
    }
    __syncthreads();
    int ch = threadIdx.x;
    int p0 = blockIdx.x * 64;
    for (int k = 0; k < 64; ++k) {
        int p = p0 + k;
        if (p >= HW_) return;
        int h = p / 132, w = p - h * 132;
        float sy = (h + 0.5f) * (1.f / 22.f) - 0.5f;
        float sx = (w + 0.5f) * (1.f / 22.f) - 0.5f;
        float fy0 = floorf(sy), fx0 = floorf(sx);
        float fy = sy - fy0, fx = sx - fx0;
        int y0 = (int)fy0, x0 = (int)fx0;
        int y1 = min(y0 + 1, 5), x1 = min(x0 + 1, 5);
        y0 = max(y0, 0); x0 = max(x0, 0);
        float v00 = s[y0 * 6 + x0][ch], v01 = s[y0 * 6 + x1][ch];
        float v10 = s[y1 * 6 + x0][ch], v11 = s[y1 * 6 + x1][ch];
        float v = (1.f - fy) * ((1.f - fx) * v00 + fx * v01)
                + fy * ((1.f - fx) * v10 + fx * v11);
        cat[((size_t)b * HW_ + p) * 384 + ch] = to_tf32(v);
    }
}

// ---------------------------------------------------------------------------
// 6) Depthwise 7x7 conv, NHWC channels-inner; output tf32-rounded
// ---------------------------------------------------------------------------
__global__ __launch_bounds__(256)
void dwconv_kernel(const float* __restrict__ in, const float* __restrict__ wgt,
                   const float* __restrict__ cbias, float* __restrict__ out)
{
    __shared__ float s[10][22][32];
    __shared__ float wsm[32][49];
    int wt = blockIdx.x, ht = blockIdx.y;
    int bz = blockIdx.z;
    int b = bz >> 2, cg = bz & 3;
    int h0 = ht * 4, w0 = wt * 16;
    int tid = threadIdx.x;
    for (int idx = tid; idx < 32 * 49; idx += 256) {
        int ch = idx / 49, t = idx - ch * 49;
        wsm[ch][t] = wgt[(cg * 32 + ch) * 49 + t];
    }
    const float* inb = in + (size_t)b * HW_ * 128;
    for (int idx = tid; idx < 10 * 22 * 32; idx += 256) {
        int ch = idx & 31;
        int r  = idx >> 5;
        int lw = r % 22, lh = r / 22;
        int gh = h0 - 3 + lh, gw = w0 - 3 + lw;
        float v = 0.f;
        if (gh >= 0 && gh < 132 && gw >= 0 && gw < 132)
            v = inb[(size_t)(gh * 132 + gw) * 128 + cg * 32 + ch];
        s[lh][lw][ch] = v;
    }
    __syncthreads();
    int ch = tid & 31;
    int pg = tid >> 5;
    float acc[8];
    #pragma unroll
    for (int i = 0; i < 8; ++i) acc[i] = 0.f;
    #pragma unroll
    for (int dy = 0; dy < 7; ++dy)
        #pragma unroll
        for (int dx = 0; dx < 7; ++dx) {
            float wv = wsm[ch][dy * 7 + dx];
            #pragma unroll
            for (int pi = 0; pi < 8; ++pi) {
                int posid = pg + pi * 8;
                int lh = posid >> 4, lw = posid & 15;
                acc[pi] = fmaf(wv, s[lh + dy][lw + dx][ch], acc[pi]);
            }
        }
    float bv = cbias[cg * 32 + ch];
    #pragma unroll
    for (int pi = 0; pi < 8; ++pi) {
        int posid = pg + pi * 8;
        int lh = posid >> 4, lw = posid & 15;
        int gw = w0 + lw;
        if (gw < 132)
            out[((size_t)b * HW_ + (h0 + lh) * 132 + gw) * 128 + cg * 32 + ch]
                = to_tf32(acc[pi] + bv);
    }
}

// ---------------------------------------------------------------------------
// Launcher
// ---------------------------------------------------------------------------
extern "C" void kernel_launch(void* const* d_in, const int* in_sizes, int n_in,
                              void* d_out, int out_size)
{
    (void)in_sizes; (void)n_in; (void)out_size;
    const float* x       = (const float*)d_in[0];
    const float* x_e     = (const float*)d_in[1];
    const float* norm_w  = (const float*)d_in[2];
    const float* norm_b  = (const float*)d_in[3];
    const float* norme_w = (const float*)d_in[4];
    const float* norme_b = (const float*)d_in[5];
    const float* l_w     = (const float*)d_in[6];
    const float* l_b     = (const float*)d_in[7];
    const float* kv_w    = (const float*)d_in[8];
    const float* kv_b    = (const float*)d_in[9];
    const float* xe_w    = (const float*)d_in[10];
    const float* xe_b    = (const float*)d_in[11];
    const float* q_w     = (const float*)d_in[12];
    const float* q_b     = (const float*)d_in[13];
    const float* ef_w    = (const float*)d_in[14];
    const float* ef_b    = (const float*)d_in[15];
    const float* ec_w    = (const float*)d_in[16];
    const float* ec_b    = (const float*)d_in[17];
    const float* eb_w    = (const float*)d_in[18];
    const float* eb_b    = (const float*)d_in[19];
    const float* proj_w  = (const float*)d_in[20];
    const float* proj_b  = (const float*)d_in[21];
    const float* proje_w = (const float*)d_in[22];
    const float* proje_b = (const float*)d_in[23];

    float* base = nullptr;
    cudaGetSymbolAddress((void**)&base, g_scratch);
    float* xc    = base + OFF_XC;
    float* xec   = base + OFF_XEC;
    float* xg    = base + OFF_XG;
    float* kvb   = base + OFF_KV;
    float* cat   = base + OFF_CAT;
    float* t1    = base + OFF_T1;   // q (LFA1, from xc)
    float* t2    = base + OFF_T2;   // ef (LFA1, from xec)
    float* t3    = base + OFF_T3;   // conv output (shared)
    float* t4    = base + OFF_T4;   // q (LFA2, from xec)
    float* t5    = base + OFF_T5;   // ef (LFA2, from xc)
    float* pool  = base + OFF_POOL;
    float* mbuf  = base + OFF_MM;
    float* smalb = base + OFF_SMALL;
    float* pmax  = base + OFF_PMAX;
    float* psum  = base + OFF_PSUM;
    float* pacc  = base + OFF_PACC;
    float* wl_t   = base + OFF_WL;
    float* wkv_t  = base + OFF_WKV;
    float* wqef_t = base + OFF_WQEF;
    float* web_t  = base + OFF_WEB;
    float* wproj_t= base + OFF_WPROJ;
    float* bqef  = base + OFF_BQEF;
    float* bproj = base + OFF_BPROJ;

    float* outp = (float*)d_out;
    float* oute = outp + SZ_BIG;

    // one-time weight transforms (cheap; part of the graph)
    tr_round <<<(256 * 256 + 255) / 256, 256>>>(l_w,  wl_t,  256, 256);
    tr_round <<<(256 * 256 + 255) / 256, 256>>>(kv_w, wkv_t, 256, 256);
    tr_round <<<(128 * 128 + 255) / 256, 256>>>(eb_w, web_t, 128, 128);
    tr_round2<<<(256 * 256 + 255) / 256, 256>>>(q_w, ef_w, wqef_t, 256, 128);
    tr_round2<<<(384 * 512 + 255) / 256, 256>>>(proj_w, proje_w, wproj_t, 384, 256);
    pack_bias<<<2, 256>>>(q_b, ef_b, proj_b, proje_b, bqef, bproj);

    dim3 lnG((HW_ + 31) / 32, B_);
    ln_kernel<<<lnG, 256>>>(x,   norm_w,  norm_b,  xc);
    ln_kernel<<<lnG, 256>>>(x_e, norme_w, norme_b, xec);

    // GFA: xg = gelu(xc @ l_w + l_b); kv = xg @ kv_w + kv_b
    tgemm<1><<<dim3(2, 1089), 256>>>(xc, wl_t,  l_b,  nullptr, xg,  nullptr, M_, 256, 256, 256, 0);
    tgemm<0><<<dim3(2, 1089), 256>>>(xg, wkv_t, kv_b, nullptr, kvb, nullptr, M_, 256, 256, 256, 0);

    pool_kernel<<<dim3(36, B_), 512>>>(xc, xec, pool);
    sgemm_small<<<dim3(2, 3), 256>>>(pool, xe_w, xe_b, mbuf, B_ * 36, 128, 512);

    attn_partial<<<dim3(SPLIT_, NH_, B_), 288>>>(kvb, mbuf, pmax, psum, pacc);
    attn_combine<<<(B_ * NH_ * 36 * 16 + 255) / 256, 256>>>(pmax, psum, pacc, smalb);
    upsample_kernel<<<dim3((HW_ + 63) / 64, B_), 128>>>(smalb, cat);  // cat[:,0:128]

    // fused q|ef GEMMs (one per input)
    tgemm<5><<<dim3(2, 1089), 256>>>(xc,  wqef_t, bqef, nullptr, t1, t5, M_, 256, 256, 0, 0);
    tgemm<5><<<dim3(2, 1089), 256>>>(xec, wqef_t, bqef, nullptr, t4, t2, M_, 256, 256, 0, 0);

    // LFA 1: conv(ef from xec), eb GEMM * q(xc) -> cat[:,128:256]
    dwconv_kernel<<<dim3(9, 33, B_ * 4), 256>>>(t2, ec_w, ec_b, t3);
    tgemm<2><<<dim3(1, 1089), 256>>>(t3, web_t, eb_b, t1, cat, nullptr, M_, 128, 128, 384, 128);

    // LFA 2: conv(ef from xc), eb GEMM * q(xec) -> cat[:,256:384]
    dwconv_kernel<<<dim3(9, 33, B_ * 4), 256>>>(t5, ec_w, ec_b, t3);
    tgemm<2><<<dim3(1, 1089), 256>>>(t3, web_t, eb_b, t4, cat, nullptr, M_, 128, 128, 384, 256);

    // fused projections, NCHW outputs split at col 256
    tgemm<4><<<dim3(4, 1089), 256>>>(cat, wproj_t, bproj, nullptr, outp, oute, M_, 512, 384, 0, 0);
}

// round 10
// speedup vs baseline: 2.2600x; 1.0134x over previous
#include <cuda_runtime.h>
#include <math.h>
#include <stdint.h>

// ---------------------------------------------------------------------------
// Problem constants
// ---------------------------------------------------------------------------
namespace {
constexpr int B_ = 8, C_ = 256, H_ = 132, W_ = 132, NH_ = 8, D_ = 16;
constexpr int HW_ = H_ * W_;          // 17424
constexpr int M_  = B_ * HW_;         // 139392  (== 1089 * 128 exactly)
constexpr int CH_ = 128;              // C/2
constexpr int C2_ = 512;              // 2C
constexpr int C3_ = 384;              // 3C/2
constexpr int SPLIT_  = 8;
constexpr int KPS_    = HW_ / SPLIT_; // 2178 keys per split
constexpr int CHUNK_  = 66;           // keys per smem chunk (2178 = 33*66)
constexpr int NCHUNK_ = KPS_ / CHUNK_;

constexpr size_t SZ_BIG  = (size_t)M_ * C_;
constexpr size_t SZ_CAT  = (size_t)M_ * C3_;
constexpr size_t SZ_HALF = (size_t)M_ * CH_;

constexpr size_t OFF_XC    = 0;
constexpr size_t OFF_XEC   = OFF_XC  + SZ_BIG;
constexpr size_t OFF_XG    = OFF_XEC + SZ_BIG;
constexpr size_t OFF_KV    = OFF_XG  + SZ_BIG;
constexpr size_t OFF_CAT   = OFF_KV  + SZ_BIG;
constexpr size_t OFF_TQ    = OFF_CAT + SZ_CAT;      // [q_xc ; q_xec]   2M x 128
constexpr size_t OFF_TEF   = OFF_TQ  + 2 * SZ_HALF; // [ef_xec ; ef_xc] 2M x 128
constexpr size_t OFF_TCV   = OFF_TEF + 2 * SZ_HALF; // conv out         2M x 128
constexpr size_t OFF_POOL  = OFF_TCV + 2 * SZ_HALF;
constexpr size_t OFF_MM    = OFF_POOL  + (size_t)B_ * 36 * C2_;
constexpr size_t OFF_SMALL = OFF_MM    + (size_t)B_ * 36 * CH_;
constexpr size_t OFF_PMAX  = OFF_SMALL + (size_t)B_ * CH_ * 36;
constexpr size_t OFF_PSUM  = OFF_PMAX  + (size_t)B_ * NH_ * 36 * SPLIT_;
constexpr size_t OFF_PACC  = OFF_PSUM  + (size_t)B_ * NH_ * 36 * SPLIT_;
// transposed+tf32-rounded weights, [N][K] layout
constexpr size_t OFF_WBIG  = OFF_PACC  + (size_t)B_ * NH_ * 36 * SPLIT_ * D_;
constexpr size_t OFF_WKV   = OFF_WBIG  + 512 * 256;
constexpr size_t OFF_WQEF  = OFF_WKV   + 256 * 256;
constexpr size_t OFF_WEB   = OFF_WQEF  + 256 * 256;
constexpr size_t OFF_WPROJ = OFF_WEB   + 128 * 128;
constexpr size_t OFF_BBIG  = OFF_WPROJ + 512 * 384;
constexpr size_t OFF_BQEF  = OFF_BBIG  + 512;
constexpr size_t OFF_BPROJ = OFF_BQEF  + 256;
constexpr size_t SCRATCH_TOTAL = OFF_BPROJ + 512;
}  // namespace

__device__ float g_scratch[SCRATCH_TOTAL];

// ---------------------------------------------------------------------------
// helpers
// ---------------------------------------------------------------------------
__device__ __forceinline__ float to_tf32(float x) {
    float r;
    asm("cvt.rna.tf32.f32 %0, %1;" : "=f"(r) : "f"(x));
    return r;
}
__device__ __forceinline__ void ldsm4(uint32_t& r0, uint32_t& r1, uint32_t& r2,
                                      uint32_t& r3, uint32_t addr) {
    asm volatile("ldmatrix.sync.aligned.m8n8.x4.shared.b16 {%0,%1,%2,%3}, [%4];"
                 : "=r"(r0), "=r"(r1), "=r"(r2), "=r"(r3) : "r"(addr));
}
__device__ __forceinline__ void cp_async16(uint32_t dst, const void* src) {
    asm volatile("cp.async.ca.shared.global [%0], [%1], 16;" :: "r"(dst), "l"(src));
}
__device__ __forceinline__ void cp_commit() {
    asm volatile("cp.async.commit_group;");
}
template <int N>
__device__ __forceinline__ void cp_wait() {
    asm volatile("cp.async.wait_group %0;" :: "n"(N));
}

// ---------------------------------------------------------------------------
// 0) weight prep (one-time per replay, tiny)
// ---------------------------------------------------------------------------
// wbig[N=512][K=256]: n<256 -> l_w, n<384 -> q_w, else ef_w
__global__ void tr_round3(const float* __restrict__ lw, const float* __restrict__ qw,
                          const float* __restrict__ efw, float* __restrict__ Wt)
{
    int i = blockIdx.x * 256 + threadIdx.x;
    if (i >= 256 * 512) return;
    int k = i >> 9, n = i & 511;
    float v;
    if (n < 256)      v = lw[k * 256 + n];
    else if (n < 384) v = qw[k * 128 + (n - 256)];
    else              v = efw[k * 128 + (n - 384)];
    Wt[(size_t)n * 256 + k] = to_tf32(v);
}
__global__ void tr_round(const float* __restrict__ W, float* __restrict__ Wt,
                         int K, int N)
{
    int i = blockIdx.x * 256 + threadIdx.x;
    if (i >= K * N) return;
    int k = i / N, n = i - k * N;
    Wt[(size_t)n * K + k] = to_tf32(W[i]);
}
// fuse two [K][Nh] weights into Wt[(2*Nh)][K]
__global__ void tr_round2(const float* __restrict__ W1, const float* __restrict__ W2,
                          float* __restrict__ Wt, int K, int Nh)
{
    int i = blockIdx.x * 256 + threadIdx.x;
    if (i >= K * 2 * Nh) return;
    int k = i / (2 * Nh), n = i - k * (2 * Nh);
    float v = (n < Nh) ? W1[k * Nh + n] : W2[k * Nh + (n - Nh)];
    Wt[(size_t)n * K + k] = to_tf32(v);
}
__global__ void prep_bias(const float* __restrict__ lb, const float* __restrict__ qb,
                          const float* __restrict__ efb,
                          const float* __restrict__ pb, const float* __restrict__ peb,
                          float* __restrict__ bbig, float* __restrict__ bqef,
                          float* __restrict__ bproj)
{
    int i = blockIdx.x * 256 + threadIdx.x;
    if (i < 512) {
        float v;
        if (i < 256)      v = lb[i];
        else if (i < 384) v = qb[i - 256];
        else              v = efb[i - 384];
        bbig[i] = v;
        bproj[i] = (i < 256) ? pb[i] : peb[i - 256];
    }
    if (i < 256) bqef[i] = (i < 128) ? qb[i] : efb[i - 128];
}

// ---------------------------------------------------------------------------
// 1) LayerNorm over channels, NCHW -> (B*HW, C); output tf32-rounded
// ---------------------------------------------------------------------------
__global__ void ln_kernel(const float* __restrict__ x, const float* __restrict__ gw,
                          const float* __restrict__ gb, float* __restrict__ out)
{
    __shared__ float s[256][33];
    __shared__ float sw[256], sb[256];
    int tid  = threadIdx.x;
    int b    = blockIdx.y;
    int pos0 = blockIdx.x * 32;
    sw[tid] = gw[tid];
    sb[tid] = gb[tid];
    int px = tid & 31, cg = tid >> 5;
    int p  = pos0 + px;
    const float* xb = x + (size_t)b * C_ * HW_;
    bool valid = (p < HW_);
    for (int c = cg; c < 256; c += 8)
        s[c][px] = valid ? xb[(size_t)c * HW_ + p] : 0.f;
    __syncthreads();
    int warp = tid >> 5, lane = tid & 31;
    #pragma unroll
    for (int pi = 0; pi < 4; ++pi) {
        int pp = warp * 4 + pi;
        int gp = pos0 + pp;
        if (gp >= HW_) continue;
        float sum = 0.f, sum2 = 0.f;
        #pragma unroll
        for (int jj = 0; jj < 8; ++jj) {
            float v = s[lane + jj * 32][pp];
            sum += v; sum2 += v * v;
        }
        #pragma unroll
        for (int o = 16; o > 0; o >>= 1) {
            sum  += __shfl_xor_sync(0xffffffffu, sum,  o);
            sum2 += __shfl_xor_sync(0xffffffffu, sum2, o);
        }
        float mean = sum * (1.f / 256.f);
        float var  = fmaxf(sum2 * (1.f / 256.f) - mean * mean, 0.f);
        float rstd = rsqrtf(var + 1e-6f);
        float* orow = out + (size_t)(b * HW_ + gp) * 256;
        #pragma unroll
        for (int jj = 0; jj < 8; ++jj) {
            int c = lane + jj * 32;
            orow[c] = to_tf32((s[c][pp] - mean) * rstd * sw[c] + sb[c]);
        }
    }
}

// ---------------------------------------------------------------------------
// 2a) TF32 tensor-core GEMM, pure cp.async 4-stage pipeline + ldmatrix.
//     A[M][K]: values already tf32 (rna pre-rounded by producers).
//     Wt[N][K] pre-rounded tf32.
//     BM=128 BN=128 BK=16, 256 threads (8 warps 2Mx4N, warp tile 64x32).
//     EPI 0: plain row-major (ld 256)
//     EPI 4: dual NCHW split at col 256 (proj)
//     EPI 5: dual plain split at col 128 (Cout/Cout2, ld 128)
//     EPI 6: *aux, row-split (row<M_ -> cat col 128, else cat col 256)
//     EPI 7: triple: col<256 GELU->Cout(ld256); <384 ->Cout2; else ->Cout3
// ---------------------------------------------------------------------------
template <int EPI>
__global__ __launch_bounds__(256, 2)
void tgemm(const float* __restrict__ A, const float* __restrict__ Wt,
           const float* __restrict__ bias, const float* __restrict__ aux,
           float* __restrict__ Cout, float* __restrict__ Cout2,
           float* __restrict__ Cout3, int M, int N, int K)
{
    __shared__ float As[4][128 * 16];
    __shared__ float Bs[4][128 * 16];
    const int tid = threadIdx.x;
    const int bm = blockIdx.y * 128;
    const int bn = blockIdx.x * 128;
    const int lane = tid & 31, wid = tid >> 5;
    const int wm = (wid & 1) * 64, wn = (wid >> 1) * 32;
    const int g = lane >> 2, tig = lane & 3;

    float acc[4][4][4] = {};

    uint32_t sA = (uint32_t)__cvta_generic_to_shared(&As[0][0]);
    uint32_t sB = (uint32_t)__cvta_generic_to_shared(&Bs[0][0]);

    // ldmatrix fragment base addresses (buffer 0, k8 block 0); k8=1 -> ^32B
    uint32_t aAddr[4], bAddr[2];
    {
        int rsel = ((lane >> 3) & 1) * 8 + (lane & 7);
        int csel = lane >> 4;
        #pragma unroll
        for (int mt = 0; mt < 4; ++mt) {
            int row = wm + mt * 16 + rsel;
            int c = csel ^ ((row >> 1) & 3);
            aAddr[mt] = sA + (uint32_t)(row * 16 + 4 * c) * 4u;
        }
        int m = lane >> 3;
        int nrsel = (m >> 1) * 8 + (lane & 7);
        int ncsel = m & 1;
        #pragma unroll
        for (int np = 0; np < 2; ++np) {
            int row = wn + np * 16 + nrsel;
            int c = ncsel ^ ((row >> 1) & 3);
            bAddr[np] = sB + (uint32_t)(row * 16 + 4 * c) * 4u;
        }
    }

    // cp.async staging map: each thread moves 2 A-chunks + 2 B-chunks per stage
    const int aRow = tid >> 2;           // 0..63
    const int aK   = (tid & 3) << 2;     // 0,4,8,12
    const int ar1  = aRow + 64;
    const int st0  = aRow * 16 + 4 * ((aK >> 2) ^ ((aRow >> 1) & 3));
    const int st1  = ar1 * 16 + 4 * ((aK >> 2) ^ ((ar1 >> 1) & 3));
    const float* agp0 = A  + (size_t)(bm + aRow) * K + aK;
    const float* agp1 = agp0 + (size_t)64 * K;
    const float* bgp0 = Wt + (size_t)(bn + aRow) * K + aK;
    const float* bgp1 = bgp0 + (size_t)64 * K;
    const uint32_t dA0 = sA + (uint32_t)st0 * 4u;
    const uint32_t dA1 = sA + (uint32_t)st1 * 4u;
    const uint32_t dB0 = sB + (uint32_t)st0 * 4u;
    const uint32_t dB1 = sB + (uint32_t)st1 * 4u;

    auto issue = [&](int s, int buf) {
        uint32_t off = (uint32_t)buf * 8192u;
        cp_async16(dA0 + off, agp0 + s * 16);
        cp_async16(dA1 + off, agp1 + s * 16);
        cp_async16(dB0 + off, bgp0 + s * 16);
        cp_async16(dB1 + off, bgp1 + s * 16);
    };
    auto compute = [&](int buf) {
        uint32_t bo = (uint32_t)buf * 8192u;
        #pragma unroll
        for (int kb2 = 0; kb2 < 2; ++kb2) {
            uint32_t kx = kb2 ? 32u : 0u;
            uint32_t a_[4][4], b_[4][2];
            #pragma unroll
            for (int mt = 0; mt < 4; ++mt)
                ldsm4(a_[mt][0], a_[mt][1], a_[mt][2], a_[mt][3],
                      (aAddr[mt] + bo) ^ kx);
            ldsm4(b_[0][0], b_[0][1], b_[1][0], b_[1][1], (bAddr[0] + bo) ^ kx);
            ldsm4(b_[2][0], b_[2][1], b_[3][0], b_[3][1], (bAddr[1] + bo) ^ kx);
            #pragma unroll
            for (int mt = 0; mt < 4; ++mt)
                #pragma unroll
                for (int nt = 0; nt < 4; ++nt) {
                    asm volatile(
                        "mma.sync.aligned.m16n8k8.row.col.f32.tf32.tf32.f32 "
                        "{%0,%1,%2,%3}, {%4,%5,%6,%7}, {%8,%9}, {%0,%1,%2,%3};\n"
                        : "+f"(acc[mt][nt][0]), "+f"(acc[mt][nt][1]),
                          "+f"(acc[mt][nt][2]), "+f"(acc[mt][nt][3])
                        : "r"(a_[mt][0]), "r"(a_[mt][1]), "r"(a_[mt][2]), "r"(a_[mt][3]),
                          "r"(b_[nt][0]), "r"(b_[nt][1]));
                }
        }
    };

    const int nsteps = K >> 4;   // >= 8 for all our shapes
    issue(0, 0); cp_commit();
    issue(1, 1); cp_commit();
    issue(2, 2); cp_commit();
    cp_wait<2>();
    __syncthreads();
    for (int s = 0; s < nsteps; ++s) {
        compute(s & 3);
        if (s + 3 < nsteps) issue(s + 3, (s + 3) & 3);
        cp_commit();
        cp_wait<2>();
        __syncthreads();
    }

    // epilogue
    #pragma unroll
    for (int mt = 0; mt < 4; ++mt) {
        int row0 = bm + wm + mt * 16 + g;
        #pragma unroll
        for (int rr = 0; rr < 2; ++rr) {
            int row = row0 + rr * 8;
            #pragma unroll
            for (int nt = 0; nt < 4; ++nt) {
                #pragma unroll
                for (int cc = 0; cc < 2; ++cc) {
                    int col = bn + wn + nt * 8 + 2 * tig + cc;
                    float v = acc[mt][nt][rr * 2 + cc] + bias[col];
                    if (EPI == 0) {
                        Cout[(size_t)row * 256 + col] = v;
                    } else if (EPI == 4) {
                        int bb = row / HW_;
                        int pp = row - bb * HW_;
                        float* tgt = (col < 256) ? Cout : Cout2;
                        tgt[(size_t)(bb * 256 + (col & 255)) * HW_ + pp] = v;
                    } else if (EPI == 5) {
                        if (col < 128) Cout[(size_t)row * 128 + col] = v;
                        else           Cout2[(size_t)row * 128 + (col - 128)] = v;
                    } else if (EPI == 6) {
                        float vv = to_tf32(v * aux[(size_t)row * 128 + col]);
                        int r2 = row, co = 128;
                        if (r2 >= M_) { r2 -= M_; co = 256; }
                        Cout[(size_t)r2 * 384 + co + col] = vv;
                    } else if (EPI == 7) {
                        if (col < 256) {
                            float gl = 0.5f * v * (1.f + erff(v * 0.70710678f));
                            Cout[(size_t)row * 256 + col] = to_tf32(gl);
                        } else if (col < 384) {
                            Cout2[(size_t)row * 128 + (col - 256)] = v;
                        } else {
                            Cout3[(size_t)row * 128 + (col - 384)] = v;
                        }
                    }
                }
            }
        }
    }
}

// ---------------------------------------------------------------------------
// 2b) Small FFMA SGEMM (288-row pooled GEMM only; W is [K][N] original)
// ---------------------------------------------------------------------------
__global__ __launch_bounds__(256)
void sgemm_small(const float* __restrict__ A, const float* __restrict__ Wm,
                 const float* __restrict__ bias, float* __restrict__ Cout,
                 int M, int N, int K)
{
    __shared__ float As[16][132];
    __shared__ float Ws[16][64];
    int tid = threadIdx.x;
    int bm = blockIdx.y * 128;
    int bn = blockIdx.x * 64;
    int tx = tid & 15, ty = tid >> 4;
    float acc[8][4];
    #pragma unroll
    for (int i = 0; i < 8; ++i)
        #pragma unroll
        for (int j = 0; j < 4; ++j) acc[i][j] = 0.f;
    int aRow = tid >> 2;
    int aK   = (tid & 3) << 2;
    int wRow = tid >> 4;
    int wCol = (tid & 15) << 2;
    for (int k0 = 0; k0 < K; k0 += 16) {
        #pragma unroll
        for (int r = 0; r < 2; ++r) {
            int row = bm + aRow + r * 64;
            float4 v = make_float4(0.f, 0.f, 0.f, 0.f);
            if (row < M)
                v = *reinterpret_cast<const float4*>(A + (size_t)row * K + k0 + aK);
            As[aK + 0][aRow + r * 64] = v.x;
            As[aK + 1][aRow + r * 64] = v.y;
            As[aK + 2][aRow + r * 64] = v.z;
            As[aK + 3][aRow + r * 64] = v.w;
        }
        *reinterpret_cast<float4*>(&Ws[wRow][wCol]) =
            *reinterpret_cast<const float4*>(Wm + (size_t)(k0 + wRow) * N + bn + wCol);
        __syncthreads();
        #pragma unroll
        for (int kk = 0; kk < 16; ++kk) {
            float a[8], bf[4];
            #pragma unroll
            for (int i = 0; i < 8; ++i) a[i] = As[kk][ty * 8 + i];
            #pragma unroll
            for (int j = 0; j < 4; ++j) bf[j] = Ws[kk][tx * 4 + j];
            #pragma unroll
            for (int i = 0; i < 8; ++i)
                #pragma unroll
                for (int j = 0; j < 4; ++j)
                    acc[i][j] = fmaf(a[i], bf[j], acc[i][j]);
        }
        __syncthreads();
    }
    #pragma unroll
    for (int i = 0; i < 8; ++i) {
        int row = bm + ty * 8 + i;
        if (row >= M) continue;
        #pragma unroll
        for (int j = 0; j < 4; ++j) {
            int col = bn + tx * 4 + j;
            Cout[(size_t)row * N + col] = acc[i][j] + bias[col];
        }
    }
}

// ---------------------------------------------------------------------------
// 3) AdaptiveAvgPool2d((6,6)) on cat(xc, xec)
// ---------------------------------------------------------------------------
__global__ void pool_kernel(const float* __restrict__ xc, const float* __restrict__ xec,
                            float* __restrict__ pooled)
{
    int b = blockIdx.y, q = blockIdx.x;
    int qy = q / 6, qx = q - qy * 6;
    int c  = threadIdx.x;
    const float* src = (c < 256) ? xc : xec;
    int cc = c & 255;
    size_t base = (size_t)b * HW_;
    float acc = 0.f;
    for (int i = 0; i < 22; ++i) {
        size_t rowp = base + (size_t)((qy * 22 + i) * 132 + qx * 22);
        for (int j = 0; j < 22; ++j)
            acc += src[(rowp + j) * 256 + cc];
    }
    pooled[(size_t)(b * 36 + q) * 512 + c] = acc * (1.f / 484.f);
}

// ---------------------------------------------------------------------------
// 4) Attention (online softmax, split over keys) + combine
// ---------------------------------------------------------------------------
__global__ __launch_bounds__(288)
void attn_partial(const float* __restrict__ kv, const float* __restrict__ mq_all,
                  float* __restrict__ pmax, float* __restrict__ psum,
                  float* __restrict__ pacc)
{
    __shared__ float ks[CHUNK_][17];
    __shared__ float vs[CHUNK_][17];
    int b = blockIdx.z, head = blockIdx.y, sp = blockIdx.x;
    int tid = threadIdx.x;
    int q = tid >> 3, j = tid & 7;
    float mq[16];
    #pragma unroll
    for (int d = 0; d < 16; ++d)
        mq[d] = mq_all[(size_t)(b * 36 + q) * 128 + head * 16 + d] * 0.25f;
    float mx = -INFINITY, sm = 0.f;
    float acc[16];
    #pragma unroll
    for (int d = 0; d < 16; ++d) acc[d] = 0.f;
    int kb = sp * KPS_;
    for (int c0 = 0; c0 < NCHUNK_; ++c0) {
        int pos0 = kb + c0 * CHUNK_;
        for (int idx = tid; idx < CHUNK_ * 16; idx += 288) {
            int key = idx >> 4, d = idx & 15;
            size_t base = ((size_t)b * HW_ + pos0 + key) * 256 + head * 16 + d;
            ks[key][d] = kv[base];
            vs[key][d] = kv[base + 128];
        }
        __syncthreads();
        for (int key = j; key < CHUNK_; key += 8) {
            float s = 0.f;
            #pragma unroll
            for (int d = 0; d < 16; ++d) s = fmaf(mq[d], ks[key][d], s);
            if (s <= mx) {
                float p = __expf(s - mx);
                sm += p;
                #pragma unroll
                for (int d = 0; d < 16; ++d) acc[d] = fmaf(p, vs[key][d], acc[d]);
            } else {
                float cr = __expf(mx - s);
                sm = fmaf(sm, cr, 1.f);
                #pragma unroll
                for (int d = 0; d < 16; ++d) acc[d] = fmaf(acc[d], cr, vs[key][d]);
                mx = s;
            }
        }
        __syncthreads();
    }
    #pragma unroll
    for (int o = 4; o > 0; o >>= 1) {
        float omx = __shfl_xor_sync(0xffffffffu, mx, o);
        float osm = __shfl_xor_sync(0xffffffffu, sm, o);
        float nm = fmaxf(mx, omx);
        float c1 = __expf(mx - nm), c2 = __expf(omx - nm);
        sm = sm * c1 + osm * c2;
        #pragma unroll
        for (int d = 0; d < 16; ++d) {
            float oa = __shfl_xor_sync(0xffffffffu, acc[d], o);
            acc[d] = acc[d] * c1 + oa * c2;
        }
        mx = nm;
    }
    int pi = (b * NH_ + head) * 36 + q;
    if (j == 0) {
        pmax[pi * SPLIT_ + sp] = mx;
        psum[pi * SPLIT_ + sp] = sm;
        #pragma unroll
        for (int d = 0; d < 16; ++d)
            pacc[((size_t)pi * SPLIT_ + sp) * 16 + d] = acc[d];
    }
}

__global__ void attn_combine(const float* __restrict__ pmax, const float* __restrict__ psum,
                             const float* __restrict__ pacc, float* __restrict__ sm_out)
{
    int idx = blockIdx.x * blockDim.x + threadIdx.x;
    if (idx >= B_ * NH_ * 36 * 16) return;
    int d  = idx & 15;
    int q  = (idx >> 4) % 36;
    int bh = idx / (16 * 36);
    int pi = bh * 36 + q;
    float gm = -INFINITY;
    #pragma unroll
    for (int s = 0; s < SPLIT_; ++s) gm = fmaxf(gm, pmax[pi * SPLIT_ + s]);
    float ts = 0.f, tv = 0.f;
    #pragma unroll
    for (int s = 0; s < SPLIT_; ++s) {
        float c = __expf(pmax[pi * SPLIT_ + s] - gm);
        ts += c * psum[pi * SPLIT_ + s];
        tv += c * pacc[((size_t)pi * SPLIT_ + s) * 16 + d];
    }
    int b = bh >> 3, head = bh & 7;
    sm_out[(size_t)(b * 128 + head * 16 + d) * 36 + q] = tv / ts;
}

// ---------------------------------------------------------------------------
// 5) Bilinear upsample (B,128,6,6) -> cat[:, 0:128], tf32-rounded
// ---------------------------------------------------------------------------
__global__ void upsample_kernel(const float* __restrict__ sm_in, float* __restrict__ cat)
{
    __shared__ float s[36][128];
    int b = blockIdx.y;
    for (int idx = threadIdx.x; idx < 36 * 128; idx += 128) {
        int q = idx >> 7, ch = idx & 127;
        s[q][ch] = sm_in[(size_t)(b * 128 + ch) * 36 + q];
    }
    __syncthreads();
    int ch = threadIdx.x;
    int p0 = blockIdx.x * 64;
    for (int k = 0; k < 64; ++k) {
        int p = p0 + k;
        if (p >= HW_) return;
        int h = p / 132, w = p - h * 132;
        float sy = (h + 0.5f) * (1.f / 22.f) - 0.5f;
        float sx = (w + 0.5f) * (1.f / 22.f) - 0.5f;
        float fy0 = floorf(sy), fx0 = floorf(sx);
        float fy = sy - fy0, fx = sx - fx0;
        int y0 = (int)fy0, x0 = (int)fx0;
        int y1 = min(y0 + 1, 5), x1 = min(x0 + 1, 5);
        y0 = max(y0, 0); x0 = max(x0, 0);
        float v00 = s[y0 * 6 + x0][ch], v01 = s[y0 * 6 + x1][ch];
        float v10 = s[y1 * 6 + x0][ch], v11 = s[y1 * 6 + x1][ch];
        float v = (1.f - fy) * ((1.f - fx) * v00 + fx * v01)
                + fy * ((1.f - fx) * v10 + fx * v11);
        cat[((size_t)b * HW_ + p) * 384 + ch] = to_tf32(v);
    }
}

// ---------------------------------------------------------------------------
// 6) Depthwise 7x7 conv, NHWC channels-inner, batched over 2B images;
//    output tf32-rounded
// ---------------------------------------------------------------------------
__global__ __launch_bounds__(256)
void dwconv_kernel(const float* __restrict__ in, const float* __restrict__ wgt,
                   const float* __restrict__ cbias, float* __restrict__ out)
{
    __shared__ float s[10][22][32];
    __shared__ float wsm[32][49];
    int wt = blockIdx.x, ht = blockIdx.y;
    int bz = blockIdx.z;
    int b = bz >> 2, cg = bz & 3;    // b in [0, 2*B_)
    int h0 = ht * 4, w0 = wt * 16;
    int tid = threadIdx.x;
    for (int idx = tid; idx < 32 * 49; idx += 256) {
        int ch = idx / 49, t = idx - ch * 49;
        wsm[ch][t] = wgt[(cg * 32 + ch) * 49 + t];
    }
    const float* inb = in + (size_t)b * HW_ * 128;
    for (int idx = tid; idx < 10 * 22 * 32; idx += 256) {
        int ch = idx & 31;
        int r  = idx >> 5;
        int lw = r % 22, lh = r / 22;
        int gh = h0 - 3 + lh, gw = w0 - 3 + lw;
        float v = 0.f;
        if (gh >= 0 && gh < 132 && gw >= 0 && gw < 132)
            v = inb[(size_t)(gh * 132 + gw) * 128 + cg * 32 + ch];
        s[lh][lw][ch] = v;
    }
    __syncthreads();
    int ch = tid & 31;
    int pg = tid >> 5;
    float acc[8];
    #pragma unroll
    for (int i = 0; i < 8; ++i) acc[i] = 0.f;
    #pragma unroll
    for (int dy = 0; dy < 7; ++dy)
        #pragma unroll
        for (int dx = 0; dx < 7; ++dx) {
            float wv = wsm[ch][dy * 7 + dx];
            #pragma unroll
            for (int pi = 0; pi < 8; ++pi) {
                int posid = pg + pi * 8;
                int lh = posid >> 4, lw = posid & 15;
                acc[pi] = fmaf(wv, s[lh + dy][lw + dx][ch], acc[pi]);
            }
        }
    float bv = cbias[cg * 32 + ch];
    #pragma unroll
    for (int pi = 0; pi < 8; ++pi) {
        int posid = pg + pi * 8;
        int lh = posid >> 4, lw = posid & 15;
        int gw = w0 + lw;
        if (gw < 132)
            out[((size_t)b * HW_ + (h0 + lh) * 132 + gw) * 128 + cg * 32 + ch]
                = to_tf32(acc[pi] + bv);
    }
}

// ---------------------------------------------------------------------------
// Launcher
// ---------------------------------------------------------------------------
extern "C" void kernel_launch(void* const* d_in, const int* in_sizes, int n_in,
                              void* d_out, int out_size)
{
    (void)in_sizes; (void)n_in; (void)out_size;
    const float* x       = (const float*)d_in[0];
    const float* x_e     = (const float*)d_in[1];
    const float* norm_w  = (const float*)d_in[2];
    const float* norm_b  = (const float*)d_in[3];
    const float* norme_w = (const float*)d_in[4];
    const float* norme_b = (const float*)d_in[5];
    const float* l_w     = (const float*)d_in[6];
    const float* l_b     = (const float*)d_in[7];
    const float* kv_w    = (const float*)d_in[8];
    const float* kv_b    = (const float*)d_in[9];
    const float* xe_w    = (const float*)d_in[10];
    const float* xe_b    = (const float*)d_in[11];
    const float* q_w     = (const float*)d_in[12];
    const float* q_b     = (const float*)d_in[13];
    const float* ef_w    = (const float*)d_in[14];
    const float* ef_b    = (const float*)d_in[15];
    const float* ec_w    = (const float*)d_in[16];
    const float* ec_b    = (const float*)d_in[17];
    const float* eb_w    = (const float*)d_in[18];
    const float* eb_b    = (const float*)d_in[19];
    const float* proj_w  = (const float*)d_in[20];
    const float* proj_b  = (const float*)d_in[21];
    const float* proje_w = (const float*)d_in[22];
    const float* proje_b = (const float*)d_in[23];

    float* base = nullptr;
    cudaGetSymbolAddress((void**)&base, g_scratch);
    float* xc    = base + OFF_XC;
    float* xec   = base + OFF_XEC;
    float* xg    = base + OFF_XG;
    float* kvb   = base + OFF_KV;
    float* cat   = base + OFF_CAT;
    float* tq    = base + OFF_TQ;    // [q_xc ; q_xec]
    float* tef   = base + OFF_TEF;   // [ef_xec ; ef_xc]
    float* tcv   = base + OFF_TCV;   // conv outputs, same row order as tef
    float* pool  = base + OFF_POOL;
    float* mbuf  = base + OFF_MM;
    float* smalb = base + OFF_SMALL;
    float* pmax  = base + OFF_PMAX;
    float* psum  = base + OFF_PSUM;
    float* pacc  = base + OFF_PACC;
    float* wbig  = base + OFF_WBIG;
    float* wkv_t = base + OFF_WKV;
    float* wqef_t= base + OFF_WQEF;
    float* web_t = base + OFF_WEB;
    float* wproj_t = base + OFF_WPROJ;
    float* bbig  = base + OFF_BBIG;
    float* bqef  = base + OFF_BQEF;
    float* bproj = base + OFF_BPROJ;

    float* outp = (float*)d_out;
    float* oute = outp + SZ_BIG;

    dim3 lnG((HW_ + 31) / 32, B_);

    // 0-2: weight/bias prep needed by launches 5-6
    tr_round3<<<(256 * 512 + 255) / 256, 256>>>(l_w, q_w, ef_w, wbig);
    tr_round <<<(256 * 256 + 255) / 256, 256>>>(kv_w, wkv_t, 256, 256);
    prep_bias<<<2, 256>>>(l_b, q_b, ef_b, proj_b, proje_b, bbig, bqef, bproj);
    // 3-4: LayerNorms
    ln_kernel<<<lnG, 256>>>(x,   norm_w,  norm_b,  xc);
    ln_kernel<<<lnG, 256>>>(x_e, norme_w, norme_b, xec);
    // 5: fused xc GEMM (N=512): gelu->xg | q_xc->tq[0:M] | ef_xc->tef[M:2M]
    //    (launch index 5 == ncu capture slot)
    tgemm<7><<<dim3(4, 1089), 256>>>(xc, wbig, bbig, nullptr,
                                     xg, tq, tef + SZ_HALF, M_, 512, 256);
    // 6: kv GEMM
    tgemm<0><<<dim3(2, 1089), 256>>>(xg, wkv_t, kv_b, nullptr,
                                     kvb, nullptr, nullptr, M_, 256, 256);
    // 7-8: xec q|ef GEMM: q_xec->tq[M:2M] | ef_xec->tef[0:M]
    tr_round2<<<(256 * 256 + 255) / 256, 256>>>(q_w, ef_w, wqef_t, 256, 128);
    tgemm<5><<<dim3(2, 1089), 256>>>(xec, wqef_t, bqef, nullptr,
                                     tq + SZ_HALF, tef, nullptr, M_, 256, 256);
    // 9-10: remaining weight preps
    tr_round <<<(128 * 128 + 255) / 256, 256>>>(eb_w, web_t, 128, 128);
    tr_round2<<<(384 * 512 + 255) / 256, 256>>>(proj_w, proje_w, wproj_t, 384, 256);
    // 11-15: GFA small path
    pool_kernel<<<dim3(36, B_), 512>>>(xc, xec, pool);
    sgemm_small<<<dim3(2, 3), 256>>>(pool, xe_w, xe_b, mbuf, B_ * 36, 128, 512);
    attn_partial<<<dim3(SPLIT_, NH_, B_), 288>>>(kvb, mbuf, pmax, psum, pacc);
    attn_combine<<<(B_ * NH_ * 36 * 16 + 255) / 256, 256>>>(pmax, psum, pacc, smalb);
    upsample_kernel<<<dim3((HW_ + 63) / 64, B_), 128>>>(smalb, cat);  // cat[:,0:128]
    // 16: batched depthwise conv over both LFA inputs
    dwconv_kernel<<<dim3(9, 33, 2 * B_ * 4), 256>>>(tef, ec_w, ec_b, tcv);
    // 17: merged eb GEMM (M=2M_), *q epilogue, row-split into cat cols 128/256
    tgemm<6><<<dim3(1, 2178), 256>>>(tcv, web_t, eb_b, tq,
                                     cat, nullptr, nullptr, 2 * M_, 128, 128);
    // 18: fused projections, NCHW outputs split at col 256
    tgemm<4><<<dim3(4, 1089), 256>>>(cat, wproj_t, bproj, nullptr,
                                     outp, oute, nullptr, M_, 512, 384);
}

// round 11
// speedup vs baseline: 2.3416x; 1.0361x over previous
#include <cuda_runtime.h>
#include <math.h>
#include <stdint.h>

// ---------------------------------------------------------------------------
// Problem constants
// ---------------------------------------------------------------------------
namespace {
constexpr int B_ = 8, C_ = 256, H_ = 132, W_ = 132, NH_ = 8, D_ = 16;
constexpr int HW_ = H_ * W_;          // 17424
constexpr int M_  = B_ * HW_;         // 139392  (== 1089 * 128 exactly)
constexpr int CH_ = 128;              // C/2
constexpr int C2_ = 512;              // 2C
constexpr int C3_ = 384;              // 3C/2
constexpr int SPLIT_  = 8;
constexpr int KPS_    = HW_ / SPLIT_; // 2178 keys per split
constexpr int CHUNK_  = 66;           // keys per smem chunk (2178 = 33*66)
constexpr int NCHUNK_ = KPS_ / CHUNK_;
constexpr int KSTR_   = 20;           // smem row stride (floats), 16B-aligned

constexpr size_t SZ_BIG  = (size_t)M_ * C_;
constexpr size_t SZ_CAT  = (size_t)M_ * C3_;
constexpr size_t SZ_HALF = (size_t)M_ * CH_;

constexpr size_t OFF_XC    = 0;
constexpr size_t OFF_XEC   = OFF_XC  + SZ_BIG;
constexpr size_t OFF_XG    = OFF_XEC + SZ_BIG;
constexpr size_t OFF_KV    = OFF_XG  + SZ_BIG;
constexpr size_t OFF_CAT   = OFF_KV  + SZ_BIG;
constexpr size_t OFF_TQ    = OFF_CAT + SZ_CAT;      // [q_xc ; q_xec]   2M x 128
constexpr size_t OFF_TEF   = OFF_TQ  + 2 * SZ_HALF; // [ef_xec ; ef_xc] 2M x 128
constexpr size_t OFF_TCV   = OFF_TEF + 2 * SZ_HALF; // conv out         2M x 128
constexpr size_t OFF_POOL  = OFF_TCV + 2 * SZ_HALF;
constexpr size_t OFF_MM    = OFF_POOL  + (size_t)B_ * 36 * C2_;
constexpr size_t OFF_SMALL = OFF_MM    + (size_t)B_ * 36 * CH_;
constexpr size_t OFF_PMAX  = OFF_SMALL + (size_t)B_ * CH_ * 36;
constexpr size_t OFF_PSUM  = OFF_PMAX  + (size_t)B_ * NH_ * 36 * SPLIT_;
constexpr size_t OFF_PACC  = OFF_PSUM  + (size_t)B_ * NH_ * 36 * SPLIT_;
// transposed+tf32-rounded weights, [N][K] layout
constexpr size_t OFF_WBIG  = OFF_PACC  + (size_t)B_ * NH_ * 36 * SPLIT_ * D_;
constexpr size_t OFF_WKV   = OFF_WBIG  + 512 * 256;
constexpr size_t OFF_WEB   = OFF_WKV   + 256 * 256;
constexpr size_t OFF_WPROJ = OFF_WEB   + 128 * 128;
constexpr size_t OFF_BBIG  = OFF_WPROJ + 512 * 384;
constexpr size_t OFF_BQEF  = OFF_BBIG  + 512;
constexpr size_t OFF_BPROJ = OFF_BQEF  + 256;
constexpr size_t SCRATCH_TOTAL = OFF_BPROJ + 512;
}  // namespace

__device__ float g_scratch[SCRATCH_TOTAL];

// ---------------------------------------------------------------------------
// helpers
// ---------------------------------------------------------------------------
__device__ __forceinline__ float to_tf32(float x) {
    float r;
    asm("cvt.rna.tf32.f32 %0, %1;" : "=f"(r) : "f"(x));
    return r;
}
__device__ __forceinline__ void ldsm4(uint32_t& r0, uint32_t& r1, uint32_t& r2,
                                      uint32_t& r3, uint32_t addr) {
    asm volatile("ldmatrix.sync.aligned.m8n8.x4.shared.b16 {%0,%1,%2,%3}, [%4];"
                 : "=r"(r0), "=r"(r1), "=r"(r2), "=r"(r3) : "r"(addr));
}
__device__ __forceinline__ void cp_async16(uint32_t dst, const void* src) {
    asm volatile("cp.async.ca.shared.global [%0], [%1], 16;" :: "r"(dst), "l"(src));
}
__device__ __forceinline__ void cp_commit() {
    asm volatile("cp.async.commit_group;");
}
template <int N>
__device__ __forceinline__ void cp_wait() {
    asm volatile("cp.async.wait_group %0;" :: "n"(N));
}

// ---------------------------------------------------------------------------
// 0) weight prep (one-time per replay, tiny)
// ---------------------------------------------------------------------------
// wbig[N=512][K=256]: n<256 -> l_w, n<384 -> q_w, else ef_w
// NOTE: rows 256..511 double as the q|ef fused weight for the xec GEMM.
__global__ void tr_round3(const float* __restrict__ lw, const float* __restrict__ qw,
                          const float* __restrict__ efw, float* __restrict__ Wt)
{
    int i = blockIdx.x * 256 + threadIdx.x;
    if (i >= 256 * 512) return;
    int k = i >> 9, n = i & 511;
    float v;
    if (n < 256)      v = lw[k * 256 + n];
    else if (n < 384) v = qw[k * 128 + (n - 256)];
    else              v = efw[k * 128 + (n - 384)];
    Wt[(size_t)n * 256 + k] = to_tf32(v);
}
__global__ void tr_round(const float* __restrict__ W, float* __restrict__ Wt,
                         int K, int N)
{
    int i = blockIdx.x * 256 + threadIdx.x;
    if (i >= K * N) return;
    int k = i / N, n = i - k * N;
    Wt[(size_t)n * K + k] = to_tf32(W[i]);
}
// fuse two [K][Nh] weights into Wt[(2*Nh)][K]
__global__ void tr_round2(const float* __restrict__ W1, const float* __restrict__ W2,
                          float* __restrict__ Wt, int K, int Nh)
{
    int i = blockIdx.x * 256 + threadIdx.x;
    if (i >= K * 2 * Nh) return;
    int k = i / (2 * Nh), n = i - k * (2 * Nh);
    float v = (n < Nh) ? W1[k * Nh + n] : W2[k * Nh + (n - Nh)];
    Wt[(size_t)n * K + k] = to_tf32(v);
}
__global__ void prep_bias(const float* __restrict__ lb, const float* __restrict__ qb,
                          const float* __restrict__ efb,
                          const float* __restrict__ pb, const float* __restrict__ peb,
                          float* __restrict__ bbig, float* __restrict__ bqef,
                          float* __restrict__ bproj)
{
    int i = blockIdx.x * 256 + threadIdx.x;
    if (i < 512) {
        float v;
        if (i < 256)      v = lb[i];
        else if (i < 384) v = qb[i - 256];
        else              v = efb[i - 384];
        bbig[i] = v;
        bproj[i] = (i < 256) ? pb[i] : peb[i - 256];
    }
    if (i < 256) bqef[i] = (i < 128) ? qb[i] : efb[i - 128];
}

// ---------------------------------------------------------------------------
// 1) LayerNorm over channels, NCHW -> (B*HW, C); output tf32-rounded.
//    FUSED adaptive-pool accumulation: per-warp register partials per 22x22
//    bin, flushed via atomicAdd (pre-scaled by 1/484) into pooled
//    (B,36,512) at channel offset poolOff (0 for xc, 256 for xec).
// ---------------------------------------------------------------------------
__global__ void ln_kernel(const float* __restrict__ x, const float* __restrict__ gw,
                          const float* __restrict__ gb, float* __restrict__ out,
                          float* __restrict__ pooled, int poolOff)
{
    __shared__ float s[256][33];
    __shared__ float sw[256], sb[256];
    int tid  = threadIdx.x;
    int b    = blockIdx.y;
    int pos0 = blockIdx.x * 32;
    sw[tid] = gw[tid];
    sb[tid] = gb[tid];
    int px = tid & 31, cg = tid >> 5;
    int p  = pos0 + px;
    const float* xb = x + (size_t)b * C_ * HW_;
    bool valid = (p < HW_);
    for (int c = cg; c < 256; c += 8)
        s[c][px] = valid ? xb[(size_t)c * HW_ + p] : 0.f;
    __syncthreads();
    int warp = tid >> 5, lane = tid & 31;
    float pr[8];
    int curbin = -1;
    #pragma unroll
    for (int jj = 0; jj < 8; ++jj) pr[jj] = 0.f;
    #pragma unroll
    for (int pi = 0; pi < 4; ++pi) {
        int pp = warp * 4 + pi;
        int gp = pos0 + pp;
        if (gp >= HW_) continue;
        float sum = 0.f, sum2 = 0.f;
        #pragma unroll
        for (int jj = 0; jj < 8; ++jj) {
            float v = s[lane + jj * 32][pp];
            sum += v; sum2 += v * v;
        }
        #pragma unroll
        for (int o = 16; o > 0; o >>= 1) {
            sum  += __shfl_xor_sync(0xffffffffu, sum,  o);
            sum2 += __shfl_xor_sync(0xffffffffu, sum2, o);
        }
        float mean = sum * (1.f / 256.f);
        float var  = fmaxf(sum2 * (1.f / 256.f) - mean * mean, 0.f);
        float rstd = rsqrtf(var + 1e-6f);
        float* orow = out + (size_t)(b * HW_ + gp) * 256;
        int h = gp / 132, w = gp - h * 132;
        int bin = (h / 22) * 6 + (w / 22);
        if (bin != curbin) {
            if (curbin >= 0) {
                float* pb = pooled + (size_t)(b * 36 + curbin) * 512 + poolOff + lane;
                #pragma unroll
                for (int jj = 0; jj < 8; ++jj)
                    atomicAdd(pb + jj * 32, pr[jj] * (1.f / 484.f));
            }
            curbin = bin;
            #pragma unroll
            for (int jj = 0; jj < 8; ++jj) pr[jj] = 0.f;
        }
        #pragma unroll
        for (int jj = 0; jj < 8; ++jj) {
            int c = lane + jj * 32;
            float v = to_tf32((s[c][pp] - mean) * rstd * sw[c] + sb[c]);
            orow[c] = v;
            pr[jj] += v;
        }
    }
    if (curbin >= 0) {
        float* pb = pooled + (size_t)(b * 36 + curbin) * 512 + poolOff + lane;
        #pragma unroll
        for (int jj = 0; jj < 8; ++jj)
            atomicAdd(pb + jj * 32, pr[jj] * (1.f / 484.f));
    }
}

// ---------------------------------------------------------------------------
// 2a) TF32 tensor-core GEMM, pure cp.async 4-stage pipeline + ldmatrix.
//     A[M][K]: values already tf32 (rna pre-rounded by producers).
//     Wt[N][K] pre-rounded tf32.
//     BM=128 BN=128 BK=16, 256 threads (8 warps 2Mx4N, warp tile 64x32).
//     EPI 0: plain row-major (ld 256)
//     EPI 4: dual NCHW split at col 256 (proj)
//     EPI 5: dual plain split at col 128 (Cout/Cout2, ld 128)
//     EPI 6: *aux, row-split (row<M_ -> cat col 128, else cat col 256)
//     EPI 7: triple: col<256 GELU->Cout(ld256); <384 ->Cout2; else ->Cout3
// ---------------------------------------------------------------------------
template <int EPI>
__global__ __launch_bounds__(256, 2)
void tgemm(const float* __restrict__ A, const float* __restrict__ Wt,
           const float* __restrict__ bias, const float* __restrict__ aux,
           float* __restrict__ Cout, float* __restrict__ Cout2,
           float* __restrict__ Cout3, int M, int N, int K)
{
    __shared__ float As[4][128 * 16];
    __shared__ float Bs[4][128 * 16];
    const int tid = threadIdx.x;
    const int bm = blockIdx.y * 128;
    const int bn = blockIdx.x * 128;
    const int lane = tid & 31, wid = tid >> 5;
    const int wm = (wid & 1) * 64, wn = (wid >> 1) * 32;
    const int g = lane >> 2, tig = lane & 3;

    float acc[4][4][4] = {};

    uint32_t sA = (uint32_t)__cvta_generic_to_shared(&As[0][0]);
    uint32_t sB = (uint32_t)__cvta_generic_to_shared(&Bs[0][0]);

    // ldmatrix fragment base addresses (buffer 0, k8 block 0); k8=1 -> ^32B
    uint32_t aAddr[4], bAddr[2];
    {
        int rsel = ((lane >> 3) & 1) * 8 + (lane & 7);
        int csel = lane >> 4;
        #pragma unroll
        for (int mt = 0; mt < 4; ++mt) {
            int row = wm + mt * 16 + rsel;
            int c = csel ^ ((row >> 1) & 3);
            aAddr[mt] = sA + (uint32_t)(row * 16 + 4 * c) * 4u;
        }
        int m = lane >> 3;
        int nrsel = (m >> 1) * 8 + (lane & 7);
        int ncsel = m & 1;
        #pragma unroll
        for (int np = 0; np < 2; ++np) {
            int row = wn + np * 16 + nrsel;
            int c = ncsel ^ ((row >> 1) & 3);
            bAddr[np] = sB + (uint32_t)(row * 16 + 4 * c) * 4u;
        }
    }

    // cp.async staging map: each thread moves 2 A-chunks + 2 B-chunks per stage
    const int aRow = tid >> 2;           // 0..63
    const int aK   = (tid & 3) << 2;     // 0,4,8,12
    const int ar1  = aRow + 64;
    const int st0  = aRow * 16 + 4 * ((aK >> 2) ^ ((aRow >> 1) & 3));
    const int st1  = ar1 * 16 + 4 * ((aK >> 2) ^ ((ar1 >> 1) & 3));
    const float* agp0 = A  + (size_t)(bm + aRow) * K + aK;
    const float* agp1 = agp0 + (size_t)64 * K;
    const float* bgp0 = Wt + (size_t)(bn + aRow) * K + aK;
    const float* bgp1 = bgp0 + (size_t)64 * K;
    const uint32_t dA0 = sA + (uint32_t)st0 * 4u;
    const uint32_t dA1 = sA + (uint32_t)st1 * 4u;
    const uint32_t dB0 = sB + (uint32_t)st0 * 4u;
    const uint32_t dB1 = sB + (uint32_t)st1 * 4u;

    auto issue = [&](int s, int buf) {
        uint32_t off = (uint32_t)buf * 8192u;
        cp_async16(dA0 + off, agp0 + s * 16);
        cp_async16(dA1 + off, agp1 + s * 16);
        cp_async16(dB0 + off, bgp0 + s * 16);
        cp_async16(dB1 + off, bgp1 + s * 16);
    };
    auto compute = [&](int buf) {
        uint32_t bo = (uint32_t)buf * 8192u;
        #pragma unroll
        for (int kb2 = 0; kb2 < 2; ++kb2) {
            uint32_t kx = kb2 ? 32u : 0u;
            uint32_t a_[4][4], b_[4][2];
            #pragma unroll
            for (int mt = 0; mt < 4; ++mt)
                ldsm4(a_[mt][0], a_[mt][1], a_[mt][2], a_[mt][3],
                      (aAddr[mt] + bo) ^ kx);
            ldsm4(b_[0][0], b_[0][1], b_[1][0], b_[1][1], (bAddr[0] + bo) ^ kx);
            ldsm4(b_[2][0], b_[2][1], b_[3][0], b_[3][1], (bAddr[1] + bo) ^ kx);
            #pragma unroll
            for (int mt = 0; mt < 4; ++mt)
                #pragma unroll
                for (int nt = 0; nt < 4; ++nt) {
                    asm volatile(
                        "mma.sync.aligned.m16n8k8.row.col.f32.tf32.tf32.f32 "
                        "{%0,%1,%2,%3}, {%4,%5,%6,%7}, {%8,%9}, {%0,%1,%2,%3};\n"
                        : "+f"(acc[mt][nt][0]), "+f"(acc[mt][nt][1]),
                          "+f"(acc[mt][nt][2]), "+f"(acc[mt][nt][3])
                        : "r"(a_[mt][0]), "r"(a_[mt][1]), "r"(a_[mt][2]), "r"(a_[mt][3]),
                          "r"(b_[nt][0]), "r"(b_[nt][1]));
                }
        }
    };

    const int nsteps = K >> 4;   // >= 8 for all our shapes
    issue(0, 0); cp_commit();
    issue(1, 1); cp_commit();
    issue(2, 2); cp_commit();
    cp_wait<2>();
    __syncthreads();
    for (int s = 0; s < nsteps; ++s) {
        compute(s & 3);
        if (s + 3 < nsteps) issue(s + 3, (s + 3) & 3);
        cp_commit();
        cp_wait<2>();
        __syncthreads();
    }

    // epilogue
    #pragma unroll
    for (int mt = 0; mt < 4; ++mt) {
        int row0 = bm + wm + mt * 16 + g;
        #pragma unroll
        for (int rr = 0; rr < 2; ++rr) {
            int row = row0 + rr * 8;
            #pragma unroll
            for (int nt = 0; nt < 4; ++nt) {
                #pragma unroll
                for (int cc = 0; cc < 2; ++cc) {
                    int col = bn + wn + nt * 8 + 2 * tig + cc;
                    float v = acc[mt][nt][rr * 2 + cc] + bias[col];
                    if (EPI == 0) {
                        Cout[(size_t)row * 256 + col] = v;
                    } else if (EPI == 4) {
                        int bb = row / HW_;
                        int pp = row - bb * HW_;
                        float* tgt = (col < 256) ? Cout : Cout2;
                        tgt[(size_t)(bb * 256 + (col & 255)) * HW_ + pp] = v;
                    } else if (EPI == 5) {
                        if (col < 128) Cout[(size_t)row * 128 + col] = v;
                        else           Cout2[(size_t)row * 128 + (col - 128)] = v;
                    } else if (EPI == 6) {
                        float vv = to_tf32(v * aux[(size_t)row * 128 + col]);
                        int r2 = row, co = 128;
                        if (r2 >= M_) { r2 -= M_; co = 256; }
                        Cout[(size_t)r2 * 384 + co + col] = vv;
                    } else if (EPI == 7) {
                        if (col < 256) {
                            float gl = 0.5f * v * (1.f + erff(v * 0.70710678f));
                            Cout[(size_t)row * 256 + col] = to_tf32(gl);
                        } else if (col < 384) {
                            Cout2[(size_t)row * 128 + (col - 256)] = v;
                        } else {
                            Cout3[(size_t)row * 128 + (col - 384)] = v;
                        }
                    }
                }
            }
        }
    }
}

// ---------------------------------------------------------------------------
// 2b) Small FFMA SGEMM (288-row pooled GEMM only; W is [K][N] original)
// ---------------------------------------------------------------------------
__global__ __launch_bounds__(256)
void sgemm_small(const float* __restrict__ A, const float* __restrict__ Wm,
                 const float* __restrict__ bias, float* __restrict__ Cout,
                 int M, int N, int K)
{
    __shared__ float As[16][132];
    __shared__ float Ws[16][64];
    int tid = threadIdx.x;
    int bm = blockIdx.y * 128;
    int bn = blockIdx.x * 64;
    int tx = tid & 15, ty = tid >> 4;
    float acc[8][4];
    #pragma unroll
    for (int i = 0; i < 8; ++i)
        #pragma unroll
        for (int j = 0; j < 4; ++j) acc[i][j] = 0.f;
    int aRow = tid >> 2;
    int aK   = (tid & 3) << 2;
    int wRow = tid >> 4;
    int wCol = (tid & 15) << 2;
    for (int k0 = 0; k0 < K; k0 += 16) {
        #pragma unroll
        for (int r = 0; r < 2; ++r) {
            int row = bm + aRow + r * 64;
            float4 v = make_float4(0.f, 0.f, 0.f, 0.f);
            if (row < M)
                v = *reinterpret_cast<const float4*>(A + (size_t)row * K + k0 + aK);
            As[aK + 0][aRow + r * 64] = v.x;
            As[aK + 1][aRow + r * 64] = v.y;
            As[aK + 2][aRow + r * 64] = v.z;
            As[aK + 3][aRow + r * 64] = v.w;
        }
        *reinterpret_cast<float4*>(&Ws[wRow][wCol]) =
            *reinterpret_cast<const float4*>(Wm + (size_t)(k0 + wRow) * N + bn + wCol);
        __syncthreads();
        #pragma unroll
        for (int kk = 0; kk < 16; ++kk) {
            float a[8], bf[4];
            #pragma unroll
            for (int i = 0; i < 8; ++i) a[i] = As[kk][ty * 8 + i];
            #pragma unroll
            for (int j = 0; j < 4; ++j) bf[j] = Ws[kk][tx * 4 + j];
            #pragma unroll
            for (int i = 0; i < 8; ++i)
                #pragma unroll
                for (int j = 0; j < 4; ++j)
                    acc[i][j] = fmaf(a[i], bf[j], acc[i][j]);
        }
        __syncthreads();
    }
    #pragma unroll
    for (int i = 0; i < 8; ++i) {
        int row = bm + ty * 8 + i;
        if (row >= M) continue;
        #pragma unroll
        for (int j = 0; j < 4; ++j) {
            int col = bn + tx * 4 + j;
            Cout[(size_t)row * N + col] = acc[i][j] + bias[col];
        }
    }
}

// ---------------------------------------------------------------------------
// 4) Attention (online softmax, split over keys) + combine.
//    K/V smem rows at stride KSTR_=20 floats (16B aligned) -> float4 loads.
// ---------------------------------------------------------------------------
__global__ __launch_bounds__(288)
void attn_partial(const float* __restrict__ kv, const float* __restrict__ mq_all,
                  float* __restrict__ pmax, float* __restrict__ psum,
                  float* __restrict__ pacc)
{
    __shared__ float ks[CHUNK_ * KSTR_];
    __shared__ float vs[CHUNK_ * KSTR_];
    int b = blockIdx.z, head = blockIdx.y, sp = blockIdx.x;
    int tid = threadIdx.x;
    int q = tid >> 3, j = tid & 7;
    float mq[16];
    #pragma unroll
    for (int d = 0; d < 16; ++d)
        mq[d] = mq_all[(size_t)(b * 36 + q) * 128 + head * 16 + d] * 0.25f;
    float mx = -INFINITY, sm = 0.f;
    float acc[16];
    #pragma unroll
    for (int d = 0; d < 16; ++d) acc[d] = 0.f;
    int kb = sp * KPS_;
    for (int c0 = 0; c0 < NCHUNK_; ++c0) {
        int pos0 = kb + c0 * CHUNK_;
        if (tid < CHUNK_ * 4) {
            int key = tid >> 2, d4 = tid & 3;
            size_t gb = ((size_t)b * HW_ + pos0 + key) * 256 + head * 16 + d4 * 4;
            *reinterpret_cast<float4*>(&ks[key * KSTR_ + d4 * 4]) =
                *reinterpret_cast<const float4*>(kv + gb);
            *reinterpret_cast<float4*>(&vs[key * KSTR_ + d4 * 4]) =
                *reinterpret_cast<const float4*>(kv + gb + 128);
        }
        __syncthreads();
        for (int key = j; key < CHUNK_; key += 8) {
            const float4* k4 = reinterpret_cast<const float4*>(&ks[key * KSTR_]);
            float4 ka = k4[0], kb2 = k4[1], kc = k4[2], kd = k4[3];
            float s = mq[0] * ka.x;
            s = fmaf(mq[1],  ka.y,  s); s = fmaf(mq[2],  ka.z,  s);
            s = fmaf(mq[3],  ka.w,  s); s = fmaf(mq[4],  kb2.x, s);
            s = fmaf(mq[5],  kb2.y, s); s = fmaf(mq[6],  kb2.z, s);
            s = fmaf(mq[7],  kb2.w, s); s = fmaf(mq[8],  kc.x,  s);
            s = fmaf(mq[9],  kc.y,  s); s = fmaf(mq[10], kc.z,  s);
            s = fmaf(mq[11], kc.w,  s); s = fmaf(mq[12], kd.x,  s);
            s = fmaf(mq[13], kd.y,  s); s = fmaf(mq[14], kd.z,  s);
            s = fmaf(mq[15], kd.w,  s);
            const float4* v4 = reinterpret_cast<const float4*>(&vs[key * KSTR_]);
            float4 va = v4[0], vb = v4[1], vc = v4[2], vd = v4[3];
            if (s <= mx) {
                float p = __expf(s - mx);
                sm += p;
                acc[0]  = fmaf(p, va.x, acc[0]);  acc[1]  = fmaf(p, va.y, acc[1]);
                acc[2]  = fmaf(p, va.z, acc[2]);  acc[3]  = fmaf(p, va.w, acc[3]);
                acc[4]  = fmaf(p, vb.x, acc[4]);  acc[5]  = fmaf(p, vb.y, acc[5]);
                acc[6]  = fmaf(p, vb.z, acc[6]);  acc[7]  = fmaf(p, vb.w, acc[7]);
                acc[8]  = fmaf(p, vc.x, acc[8]);  acc[9]  = fmaf(p, vc.y, acc[9]);
                acc[10] = fmaf(p, vc.z, acc[10]); acc[11] = fmaf(p, vc.w, acc[11]);
                acc[12] = fmaf(p, vd.x, acc[12]); acc[13] = fmaf(p, vd.y, acc[13]);
                acc[14] = fmaf(p, vd.z, acc[14]); acc[15] = fmaf(p, vd.w, acc[15]);
            } else {
                float cr = __expf(mx - s);
                sm = fmaf(sm, cr, 1.f);
                acc[0]  = fmaf(acc[0],  cr, va.x); acc[1]  = fmaf(acc[1],  cr, va.y);
                acc[2]  = fmaf(acc[2],  cr, va.z); acc[3]  = fmaf(acc[3],  cr, va.w);
                acc[4]  = fmaf(acc[4],  cr, vb.x); acc[5]  = fmaf(acc[5],  cr, vb.y);
                acc[6]  = fmaf(acc[6],  cr, vb.z); acc[7]  = fmaf(acc[7],  cr, vb.w);
                acc[8]  = fmaf(acc[8],  cr, vc.x); acc[9]  = fmaf(acc[9],  cr, vc.y);
                acc[10] = fmaf(acc[10], cr, vc.z); acc[11] = fmaf(acc[11], cr, vc.w);
                acc[12] = fmaf(acc[12], cr, vd.x); acc[13] = fmaf(acc[13], cr, vd.y);
                acc[14] = fmaf(acc[14], cr, vd.z); acc[15] = fmaf(acc[15], cr, vd.w);
                mx = s;
            }
        }
        __syncthreads();
    }
    #pragma unroll
    for (int o = 4; o > 0; o >>= 1) {
        float omx = __shfl_xor_sync(0xffffffffu, mx, o);
        float osm = __shfl_xor_sync(0xffffffffu, sm, o);
        float nm = fmaxf(mx, omx);
        float c1 = __expf(mx - nm), c2 = __expf(omx - nm);
        sm = sm * c1 + osm * c2;
        #pragma unroll
        for (int d = 0; d < 16; ++d) {
            float oa = __shfl_xor_sync(0xffffffffu, acc[d], o);
            acc[d] = acc[d] * c1 + oa * c2;
        }
        mx = nm;
    }
    int pi = (b * NH_ + head) * 36 + q;
    if (j == 0) {
        pmax[pi * SPLIT_ + sp] = mx;
        psum[pi * SPLIT_ + sp] = sm;
        #pragma unroll
        for (int d = 0; d < 16; ++d)
            pacc[((size_t)pi * SPLIT_ + sp) * 16 + d] = acc[d];
    }
}

__global__ void attn_combine(const float* __restrict__ pmax, const float* __restrict__ psum,
                             const float* __restrict__ pacc, float* __restrict__ sm_out)
{
    int idx = blockIdx.x * blockDim.x + threadIdx.x;
    if (idx >= B_ * NH_ * 36 * 16) return;
    int d  = idx & 15;
    int q  = (idx >> 4) % 36;
    int bh = idx / (16 * 36);
    int pi = bh * 36 + q;
    float gm = -INFINITY;
    #pragma unroll
    for (int s = 0; s < SPLIT_; ++s) gm = fmaxf(gm, pmax[pi * SPLIT_ + s]);
    float ts = 0.f, tv = 0.f;
    #pragma unroll
    for (int s = 0; s < SPLIT_; ++s) {
        float c = __expf(pmax[pi * SPLIT_ + s] - gm);
        ts += c * psum[pi * SPLIT_ + s];
        tv += c * pacc[((size_t)pi * SPLIT_ + s) * 16 + d];
    }
    int b = bh >> 3, head = bh & 7;
    sm_out[(size_t)(b * 128 + head * 16 + d) * 36 + q] = tv / ts;
}

// ---------------------------------------------------------------------------
// 5) Bilinear upsample (B,128,6,6) -> cat[:, 0:128], tf32-rounded
// ---------------------------------------------------------------------------
__global__ void upsample_kernel(const float* __restrict__ sm_in, float* __restrict__ cat)
{
    __shared__ float s[36][128];
    int b = blockIdx.y;
    for (int idx = threadIdx.x; idx < 36 * 128; idx += 128) {
        int q = idx >> 7, ch = idx & 127;
        s[q][ch] = sm_in[(size_t)(b * 128 + ch) * 36 + q];
    }
    __syncthreads();
    int ch = threadIdx.x;
    int p0 = blockIdx.x * 64;
    for (int k = 0; k < 64; ++k) {
        int p = p0 + k;
        if (p >= HW_) return;
        int h = p / 132, w = p - h * 132;
        float sy = (h + 0.5f) * (1.f / 22.f) - 0.5f;
        float sx = (w + 0.5f) * (1.f / 22.f) - 0.5f;
        float fy0 = floorf(sy), fx0 = floorf(sx);
        float fy = sy - fy0, fx = sx - fx0;
        int y0 = (int)fy0, x0 = (int)fx0;
        int y1 = min(y0 + 1, 5), x1 = min(x0 + 1, 5);
        y0 = max(y0, 0); x0 = max(x0, 0);
        float v00 = s[y0 * 6 + x0][ch], v01 = s[y0 * 6 + x1][ch];
        float v10 = s[y1 * 6 + x0][ch], v11 = s[y1 * 6 + x1][ch];
        float v = (1.f - fy) * ((1.f - fx) * v00 + fx * v01)
                + fy * ((1.f - fx) * v10 + fx * v11);
        cat[((size_t)b * HW_ + p) * 384 + ch] = to_tf32(v);
    }
}

// ---------------------------------------------------------------------------
// 6) Depthwise 7x7 conv, NHWC channels-inner, batched over 2B images;
//    output tf32-rounded
// ---------------------------------------------------------------------------
__global__ __launch_bounds__(256)
void dwconv_kernel(const float* __restrict__ in, const float* __restrict__ wgt,
                   const float* __restrict__ cbias, float* __restrict__ out)
{
    __shared__ float s[10][22][32];
    __shared__ float wsm[32][49];
    int wt = blockIdx.x, ht = blockIdx.y;
    int bz = blockIdx.z;
    int b = bz >> 2, cg = bz & 3;    // b in [0, 2*B_)
    int h0 = ht * 4, w0 = wt * 16;
    int tid = threadIdx.x;
    for (int idx = tid; idx < 32 * 49; idx += 256) {
        int ch = idx / 49, t = idx - ch * 49;
        wsm[ch][t] = wgt[(cg * 32 + ch) * 49 + t];
    }
    const float* inb = in + (size_t)b * HW_ * 128;
    for (int idx = tid; idx < 10 * 22 * 32; idx += 256) {
        int ch = idx & 31;
        int r  = idx >> 5;
        int lw = r % 22, lh = r / 22;
        int gh = h0 - 3 + lh, gw = w0 - 3 + lw;
        float v = 0.f;
        if (gh >= 0 && gh < 132 && gw >= 0 && gw < 132)
            v = inb[(size_t)(gh * 132 + gw) * 128 + cg * 32 + ch];
        s[lh][lw][ch] = v;
    }
    __syncthreads();
    int ch = tid & 31;
    int pg = tid >> 5;
    float acc[8];
    #pragma unroll
    for (int i = 0; i < 8; ++i) acc[i] = 0.f;
    #pragma unroll
    for (int dy = 0; dy < 7; ++dy)
        #pragma unroll
        for (int dx = 0; dx < 7; ++dx) {
            float wv = wsm[ch][dy * 7 + dx];
            #pragma unroll
            for (int pi = 0; pi < 8; ++pi) {
                int posid = pg + pi * 8;
                int lh = posid >> 4, lw = posid & 15;
                acc[pi] = fmaf(wv, s[lh + dy][lw + dx][ch], acc[pi]);
            }
        }
    float bv = cbias[cg * 32 + ch];
    #pragma unroll
    for (int pi = 0; pi < 8; ++pi) {
        int posid = pg + pi * 8;
        int lh = posid >> 4, lw = posid & 15;
        int gw = w0 + lw;
        if (gw < 132)
            out[((size_t)b * HW_ + (h0 + lh) * 132 + gw) * 128 + cg * 32 + ch]
                = to_tf32(acc[pi] + bv);
    }
}

// ---------------------------------------------------------------------------
// Launcher
// ---------------------------------------------------------------------------
extern "C" void kernel_launch(void* const* d_in, const int* in_sizes, int n_in,
                              void* d_out, int out_size)
{
    (void)in_sizes; (void)n_in; (void)out_size;
    const float* x       = (const float*)d_in[0];
    const float* x_e     = (const float*)d_in[1];
    const float* norm_w  = (const float*)d_in[2];
    const float* norm_b  = (const float*)d_in[3];
    const float* norme_w = (const float*)d_in[4];
    const float* norme_b = (const float*)d_in[5];
    const float* l_w     = (const float*)d_in[6];
    const float* l_b     = (const float*)d_in[7];
    const float* kv_w    = (const float*)d_in[8];
    const float* kv_b    = (const float*)d_in[9];
    const float* xe_w    = (const float*)d_in[10];
    const float* xe_b    = (const float*)d_in[11];
    const float* q_w     = (const float*)d_in[12];
    const float* q_b     = (const float*)d_in[13];
    const float* ef_w    = (const float*)d_in[14];
    const float* ef_b    = (const float*)d_in[15];
    const float* ec_w    = (const float*)d_in[16];
    const float* ec_b    = (const float*)d_in[17];
    const float* eb_w    = (const float*)d_in[18];
    const float* eb_b    = (const float*)d_in[19];
    const float* proj_w  = (const float*)d_in[20];
    const float* proj_b  = (const float*)d_in[21];
    const float* proje_w = (const float*)d_in[22];
    const float* proje_b = (const float*)d_in[23];

    float* base = nullptr;
    cudaGetSymbolAddress((void**)&base, g_scratch);
    float* xc    = base + OFF_XC;
    float* xec   = base + OFF_XEC;
    float* xg    = base + OFF_XG;
    float* kvb   = base + OFF_KV;
    float* cat   = base + OFF_CAT;
    float* tq    = base + OFF_TQ;    // [q_xc ; q_xec]
    float* tef   = base + OFF_TEF;   // [ef_xec ; ef_xc]
    float* tcv   = base + OFF_TCV;   // conv outputs, same row order as tef
    float* pool  = base + OFF_POOL;
    float* mbuf  = base + OFF_MM;
    float* smalb = base + OFF_SMALL;
    float* pmax  = base + OFF_PMAX;
    float* psum  = base + OFF_PSUM;
    float* pacc  = base + OFF_PACC;
    float* wbig  = base + OFF_WBIG;
    float* wkv_t = base + OFF_WKV;
    float* web_t = base + OFF_WEB;
    float* wproj_t = base + OFF_WPROJ;
    float* bbig  = base + OFF_BBIG;
    float* bqef  = base + OFF_BQEF;
    float* bproj = base + OFF_BPROJ;
    float* wqef_t = wbig + 256 * 256;   // rows 256..511 of wbig == q|ef fused

    float* outp = (float*)d_out;
    float* oute = outp + SZ_BIG;

    dim3 lnG((HW_ + 31) / 32, B_);

    // zero the pooled accumulator (graph-capturable async memset)
    cudaMemsetAsync(pool, 0, (size_t)B_ * 36 * 512 * sizeof(float));

    // weight/bias prep
    tr_round3<<<(256 * 512 + 255) / 256, 256>>>(l_w, q_w, ef_w, wbig);
    tr_round <<<(256 * 256 + 255) / 256, 256>>>(kv_w, wkv_t, 256, 256);
    prep_bias<<<2, 256>>>(l_b, q_b, ef_b, proj_b, proje_b, bbig, bqef, bproj);
    tr_round <<<(128 * 128 + 255) / 256, 256>>>(eb_w, web_t, 128, 128);
    tr_round2<<<(384 * 512 + 255) / 256, 256>>>(proj_w, proje_w, wproj_t, 384, 256);

    // LayerNorms with fused pooling accumulation
    ln_kernel<<<lnG, 256>>>(x,   norm_w,  norm_b,  xc,  pool, 0);
    ln_kernel<<<lnG, 256>>>(x_e, norme_w, norme_b, xec, pool, 256);

    // fused xc GEMM (N=512): gelu->xg | q_xc->tq[0:M] | ef_xc->tef[M:2M]
    tgemm<7><<<dim3(4, 1089), 256>>>(xc, wbig, bbig, nullptr,
                                     xg, tq, tef + SZ_HALF, M_, 512, 256);
    // kv GEMM
    tgemm<0><<<dim3(2, 1089), 256>>>(xg, wkv_t, kv_b, nullptr,
                                     kvb, nullptr, nullptr, M_, 256, 256);
    // xec q|ef GEMM: q_xec->tq[M:2M] | ef_xec->tef[0:M]
    tgemm<5><<<dim3(2, 1089), 256>>>(xec, wqef_t, bqef, nullptr,
                                     tq + SZ_HALF, tef, nullptr, M_, 256, 256);

    // GFA small path (pooled sums ready after LNs)
    sgemm_small<<<dim3(2, 3), 256>>>(pool, xe_w, xe_b, mbuf, B_ * 36, 128, 512);
    attn_partial<<<dim3(SPLIT_, NH_, B_), 288>>>(kvb, mbuf, pmax, psum, pacc);
    attn_combine<<<(B_ * NH_ * 36 * 16 + 255) / 256, 256>>>(pmax, psum, pacc, smalb);
    upsample_kernel<<<dim3((HW_ + 63) / 64, B_), 128>>>(smalb, cat);  // cat[:,0:128]

    // batched depthwise conv over both LFA inputs
    dwconv_kernel<<<dim3(9, 33, 2 * B_ * 4), 256>>>(tef, ec_w, ec_b, tcv);
    // merged eb GEMM (M=2M_), *q epilogue, row-split into cat cols 128/256
    tgemm<6><<<dim3(1, 2178), 256>>>(tcv, web_t, eb_b, tq,
                                     cat, nullptr, nullptr, 2 * M_, 128, 128);
    // fused projections, NCHW outputs split at col 256
    tgemm<4><<<dim3(4, 1089), 256>>>(cat, wproj_t, bproj, nullptr,
                                     outp, oute, nullptr, M_, 512, 384);
}